// round 1
// baseline (speedup 1.0000x reference)
#include <cuda_runtime.h>
#include <cuda_bf16.h>
#include <math.h>
#include <stdint.h>

// Problem constants
#define BS 128
#define NN 2000
#define DD 256
#define HH 8
#define HDIM 32
#define CCTX 64
#define CNODE 8
#define TANH_CLIP 10.0f

#define INV_SQRT_HD 0.17677669529663687f   // 1/sqrt(32)
#define INV_SQRT_D  0.0625f                // 1/sqrt(256)

// ---------------- scratch (no cudaMalloc allowed) ----------------
__device__ float g_sum[BS * DD];          // sum over n of enc
__device__ float g_qk[BS * HH * DD];      // per-head query projected into enc space (scale folded)
__device__ float g_qn[BS * HH * CNODE];   // per-head query projected into node-feat space (scale folded)
__device__ float g_aw[BS * HH * DD];      // attention-weighted enc (normalized)
__device__ float g_anf[BS * HH * CNODE];  // attention-weighted node_feat (normalized)
__device__ float g_g2[BS * DD];           // glimpse @ Wk2 (with 1/sqrt(D))
__device__ float g_gn[BS * CNODE];        // Wn_l^T glimpse (with 1/sqrt(D))
__device__ int   g_flags;                 // mask dtype detection flags

// ---------------- helpers ----------------
__device__ __forceinline__ void cp_async16(void* sdst, const void* gsrc) {
    unsigned s = (unsigned)__cvta_generic_to_shared(sdst);
    asm volatile("cp.async.cg.shared.global [%0], [%1], 16;\n" :: "r"(s), "l"(gsrc) : "memory");
}
#define CP_COMMIT asm volatile("cp.async.commit_group;\n" ::: "memory")
#define CP_WAIT1  asm volatile("cp.async.wait_group 1;\n" ::: "memory")
#define CP_WAIT0  asm volatile("cp.async.wait_group 0;\n" ::: "memory")

__device__ __forceinline__ bool read_mask(const void* mp, int flags, size_t i) {
    if (flags == 0) return false;                       // all-false mask: never read (dtype unknown)
    if (flags & 2) {
        if (flags & 1) return ((const unsigned char*)mp)[i] != 0;  // bool / uint8
        return ((const float*)mp)[i] != 0.0f;                      // float32
    }
    return ((const int*)mp)[i] != 0;                               // int32
}

// ---------------- K00: zero scratch accumulators ----------------
__global__ void k00_zero() {
    int t = blockIdx.x * blockDim.x + threadIdx.x;
    if (t < BS * DD) g_sum[t] = 0.0f;
    if (t == 0) g_flags = 0;
}

// ---------------- K1: partial sums of enc over n  +  mask dtype scan ----------------
// grid: (BS, 8), block: 256
__global__ __launch_bounds__(256) void k1_sum(const float* __restrict__ enc,
                                              const void* __restrict__ maskp) {
    int b = blockIdx.x, s = blockIdx.y;
    int tid = threadIdx.x;
    const int RPB = NN / 8;  // 250 rows per block
    const float* base = enc + ((size_t)b * NN + (size_t)s * RPB) * DD + tid;
    float acc = 0.0f;
#pragma unroll 5
    for (int r = 0; r < RPB; r++) acc += base[(size_t)r * DD];
    atomicAdd(&g_sum[b * DD + tid], acc);

    // mask dtype detection: scan first BS*NN bytes (valid for every candidate dtype)
    size_t idx = (size_t)(b * 8 + s) * 256 + tid;
    bool nz0 = false, nz1 = false;
    if (idx < (size_t)BS * NN) {
        unsigned char v = ((const unsigned char*)maskp)[idx];
        if (v) { if ((idx & 3) == 0) nz0 = true; else nz1 = true; }
    }
    unsigned b0 = __ballot_sync(0xffffffffu, nz0);
    unsigned b1 = __ballot_sync(0xffffffffu, nz1);
    if ((tid & 31) == 0) {
        int f = (b0 ? 1 : 0) | (b1 ? 2 : 0);
        if (f) atomicOr(&g_flags, f);
    }
}

// ---------------- K2: per-batch setup: graph_embed, Q, qk, qn ----------------
// grid: BS, block: 256
__global__ __launch_bounds__(256) void k2_setup(const float* __restrict__ shelf,
                                                const float* __restrict__ ctx,
                                                const float* __restrict__ Wk,
                                                const float* __restrict__ Wq,
                                                const float* __restrict__ Wc,
                                                const float* __restrict__ Wg,
                                                const float* __restrict__ Wn,
                                                const int* __restrict__ cur_node) {
    __shared__ float Xs[2 * DD];
    __shared__ float Qs[DD];
    __shared__ float ms[DD];
    int b = blockIdx.x, t = threadIdx.x;

    int cn = cur_node[b];
    Xs[t] = shelf[((size_t)b * NN + cn) * DD + t];
    float a = 0.0f;
#pragma unroll 8
    for (int c = 0; c < CCTX; c++) a += ctx[b * CCTX + c] * Wc[t * CCTX + c];
    Xs[DD + t] = a;
    ms[t] = g_sum[b * DD + t] * (1.0f / NN);
    __syncthreads();

    float q = 0.0f;
#pragma unroll 8
    for (int d2 = 0; d2 < DD; d2++) q += ms[d2] * Wg[t * DD + d2];
#pragma unroll 8
    for (int k = 0; k < 2 * DD; k++) q += Xs[k] * Wq[t * 2 * DD + k];
    Qs[t] = q;
    __syncthreads();

#pragma unroll
    for (int h = 0; h < HH; h++) {
        float a2 = 0.0f;
#pragma unroll 8
        for (int e = 0; e < HDIM; e++) a2 += Qs[h * HDIM + e] * Wk[(h * HDIM + e) * DD + t];
        g_qk[(b * HH + h) * DD + t] = a2 * INV_SQRT_HD;
    }
    if (t < HH * CNODE) {
        int h = t >> 3, c = t & 7;
        float a3 = 0.0f;
#pragma unroll 8
        for (int e = 0; e < HDIM; e++) a3 += Qs[h * HDIM + e] * Wn[(h * HDIM + e) * CNODE + c];
        g_qn[(b * HH + h) * CNODE + c] = a3 * INV_SQRT_HD;
    }
}

// ---------------- K3: flash glimpse: compat + online softmax + weighted enc/nf ----------------
// grid: BS, block: 256 (warp h owns head h). cp.async double-buffered 16-row tiles.
#define TR 16
#define NTILES (NN / TR)  // 125, exact
__global__ __launch_bounds__(256) void k3_attn(const float* __restrict__ enc,
                                               const float* __restrict__ nf) {
    __shared__ float encS[2][TR * DD];
    __shared__ float nfS[2][TR * CNODE];
    int b = blockIdx.x;
    int tid = threadIdx.x, wid = tid >> 5, lane = tid & 31;

    // per-lane slice of qk (8 contiguous d's)
    const float* qkp = g_qk + (b * HH + wid) * DD + lane * 8;
    float q0 = qkp[0], q1 = qkp[1], q2 = qkp[2], q3 = qkp[3];
    float q4 = qkp[4], q5 = qkp[5], q6 = qkp[6], q7 = qkp[7];
    float qnl = (lane < CNODE) ? g_qn[(b * HH + wid) * CNODE + lane] : 0.0f;

    float aw[8];
#pragma unroll
    for (int j = 0; j < 8; j++) aw[j] = 0.0f;
    float anf = 0.0f, m = -1e30f, l = 0.0f;

    // prologue load of tile 0
    {
        const float* src = enc + ((size_t)b * NN) * DD;
        float* dst = encS[0];
#pragma unroll
        for (int i = 0; i < 4; i++) { int off = tid * 4 + i * 1024; cp_async16(dst + off, src + off); }
        if (tid < 32) {
            const float* ns = nf + ((size_t)b * NN) * CNODE;
            cp_async16(nfS[0] + tid * 4, ns + tid * 4);
        }
        CP_COMMIT;
    }

    for (int t = 0; t < NTILES; t++) {
        int buf = t & 1;
        if (t + 1 < NTILES) {
            const float* src = enc + ((size_t)b * NN + (size_t)(t + 1) * TR) * DD;
            float* dst = encS[buf ^ 1];
#pragma unroll
            for (int i = 0; i < 4; i++) { int off = tid * 4 + i * 1024; cp_async16(dst + off, src + off); }
            if (tid < 32) {
                const float* ns = nf + ((size_t)b * NN + (size_t)(t + 1) * TR) * CNODE;
                cp_async16(nfS[buf ^ 1] + tid * 4, ns + tid * 4);
            }
            CP_COMMIT;
            CP_WAIT1;
        } else {
            CP_WAIT0;
        }
        __syncthreads();

#pragma unroll 4
        for (int r = 0; r < TR; r++) {
            const float* e = &encS[buf][r * DD + lane * 8];
            float4 ea = *(const float4*)(e);
            float4 eb = *(const float4*)(e + 4);
            float p = ea.x * q0 + ea.y * q1 + ea.z * q2 + ea.w * q3
                    + eb.x * q4 + eb.y * q5 + eb.z * q6 + eb.w * q7;
            float nfv = (lane < CNODE) ? nfS[buf][r * CNODE + lane] : 0.0f;
            p += nfv * qnl;
#pragma unroll
            for (int o = 16; o > 0; o >>= 1) p += __shfl_xor_sync(0xffffffffu, p, o);

            float w;
            if (p > m) {
                float c = __expf(m - p);
                m = p;
                l *= c;
#pragma unroll
                for (int j = 0; j < 8; j++) aw[j] *= c;
                anf *= c;
                w = 1.0f;
            } else {
                w = __expf(p - m);
            }
            l += w;
            aw[0] += w * ea.x; aw[1] += w * ea.y; aw[2] += w * ea.z; aw[3] += w * ea.w;
            aw[4] += w * eb.x; aw[5] += w * eb.y; aw[6] += w * eb.z; aw[7] += w * eb.w;
            anf += w * nfv;
        }
        __syncthreads();
    }

    float invl = 1.0f / l;
    float* ao = g_aw + (b * HH + wid) * DD + lane * 8;
#pragma unroll
    for (int j = 0; j < 8; j++) ao[j] = aw[j] * invl;
    if (lane < CNODE) g_anf[(b * HH + wid) * CNODE + lane] = anf * invl;
}

// ---------------- K4: glimpse = heads @ Wout^T ; g2 = glimpse@Wk2 ; gn = Wn_l^T glimpse ----------
// grid: BS, block: 256
__global__ __launch_bounds__(256) void k4_glimpse(const float* __restrict__ Wv,
                                                  const float* __restrict__ Wout,
                                                  const float* __restrict__ Wk2,
                                                  const float* __restrict__ Wn) {
    __shared__ float hs[DD];
    __shared__ float gl[DD];
    int b = blockIdx.x, t = threadIdx.x;
    int h = t >> 5, e = t & 31;

    const float* awp = g_aw + (b * HH + h) * DD;
    const float* wvp = Wv + (h * HDIM + e) * DD;
    float a = 0.0f;
#pragma unroll 8
    for (int d = 0; d < DD; d++) a += awp[d] * wvp[d];
#pragma unroll
    for (int c = 0; c < CNODE; c++)
        a += g_anf[(b * HH + h) * CNODE + c] * Wn[(DD + h * HDIM + e) * CNODE + c];
    hs[t] = a;
    __syncthreads();

    float g = 0.0f;
#pragma unroll 8
    for (int k = 0; k < DD; k++) g += hs[k] * Wout[t * DD + k];
    gl[t] = g;
    __syncthreads();

    float a2 = 0.0f;
#pragma unroll 8
    for (int d = 0; d < DD; d++) a2 += gl[d] * Wk2[d * DD + t];
    g_g2[b * DD + t] = a2 * INV_SQRT_D;
    if (t < CNODE) {
        float a3 = 0.0f;
#pragma unroll 8
        for (int d = 0; d < DD; d++) a3 += gl[d] * Wn[(2 * DD + d) * CNODE + t];
        g_gn[b * CNODE + t] = a3 * INV_SQRT_D;
    }
}

// ---------------- K5: logits over nodes + tanh clip + mask + softmax ----------------
// grid: BS, block: 256 (warp per row)
__global__ __launch_bounds__(256) void k5_logits(const float* __restrict__ enc,
                                                 const float* __restrict__ nf,
                                                 const void* __restrict__ maskp,
                                                 float* __restrict__ out) {
    __shared__ float g2s[DD];
    __shared__ float gns[CNODE];
    __shared__ float tl[NN];
    __shared__ float red[256];
    int b = blockIdx.x;
    int tid = threadIdx.x, wid = tid >> 5, lane = tid & 31;

    g2s[tid] = g_g2[b * DD + tid];
    if (tid < CNODE) gns[tid] = g_gn[b * CNODE + tid];
    int flags = g_flags;
    __syncthreads();

    float ca0 = g2s[lane * 4 + 0], ca1 = g2s[lane * 4 + 1];
    float ca2 = g2s[lane * 4 + 2], ca3 = g2s[lane * 4 + 3];
    float cb0 = g2s[128 + lane * 4 + 0], cb1 = g2s[128 + lane * 4 + 1];
    float cb2 = g2s[128 + lane * 4 + 2], cb3 = g2s[128 + lane * 4 + 3];
    float gnl = (lane < CNODE) ? gns[lane] : 0.0f;

    for (int n = wid; n < NN; n += 8) {
        const float* e = enc + ((size_t)b * NN + n) * DD;
        float4 ea = *(const float4*)(e + lane * 4);
        float4 eb = *(const float4*)(e + 128 + lane * 4);
        float p = ea.x * ca0 + ea.y * ca1 + ea.z * ca2 + ea.w * ca3
                + eb.x * cb0 + eb.y * cb1 + eb.z * cb2 + eb.w * cb3;
        if (lane < CNODE) p += nf[((size_t)b * NN + n) * CNODE + lane] * gnl;
#pragma unroll
        for (int o = 16; o > 0; o >>= 1) p += __shfl_xor_sync(0xffffffffu, p, o);
        if (lane == 0) {
            bool msk = read_mask(maskp, flags, (size_t)b * NN + n);
            tl[n] = msk ? -INFINITY : TANH_CLIP * tanhf(p);
        }
    }
    __syncthreads();

    // block max
    float mx = -INFINITY;
    for (int n = tid; n < NN; n += 256) mx = fmaxf(mx, tl[n]);
    red[tid] = mx;
    __syncthreads();
    for (int s = 128; s > 0; s >>= 1) {
        if (tid < s) red[tid] = fmaxf(red[tid], red[tid + s]);
        __syncthreads();
    }
    mx = red[0];
    __syncthreads();

    // block sum of exp
    float sm = 0.0f;
    for (int n = tid; n < NN; n += 256) sm += __expf(tl[n] - mx);
    red[tid] = sm;
    __syncthreads();
    for (int s = 128; s > 0; s >>= 1) {
        if (tid < s) red[tid] += red[tid + s];
        __syncthreads();
    }
    float inv = 1.0f / red[0];

    for (int n = tid; n < NN; n += 256)
        out[(size_t)b * NN + n] = __expf(tl[n] - mx) * inv;
}

// ---------------- launch ----------------
extern "C" void kernel_launch(void* const* d_in, const int* in_sizes, int n_in,
                              void* d_out, int out_size) {
    const float* shelf = (const float*)d_in[0];
    const float* enc   = (const float*)d_in[1];
    const float* ctx   = (const float*)d_in[2];
    const float* nf    = (const float*)d_in[3];
    const float* Wk    = (const float*)d_in[4];
    const float* Wv    = (const float*)d_in[5];
    const float* Wk2   = (const float*)d_in[6];
    const float* Wq    = (const float*)d_in[7];
    const float* Wout  = (const float*)d_in[8];
    const float* Wc    = (const float*)d_in[9];
    const float* Wg    = (const float*)d_in[10];
    const float* Wn    = (const float*)d_in[11];
    const int*   cur   = (const int*)d_in[12];
    const void*  maskp = (const void*)d_in[13];
    float* out = (float*)d_out;

    k00_zero<<<(BS * DD + 255) / 256, 256>>>();
    {
        dim3 g(BS, 8);
        k1_sum<<<g, 256>>>(enc, maskp);
    }
    k2_setup<<<BS, 256>>>(shelf, ctx, Wk, Wq, Wc, Wg, Wn, cur);
    k3_attn<<<BS, 256>>>(enc, nf);
    k4_glimpse<<<BS, 256>>>(Wv, Wout, Wk2, Wn);
    k5_logits<<<BS, 256>>>(enc, nf, maskp, out);
}

// round 2
// speedup vs baseline: 2.0679x; 2.0679x over previous
#include <cuda_runtime.h>
#include <cuda_bf16.h>
#include <math.h>
#include <stdint.h>

// Problem constants
#define BS 128
#define NN 2000
#define DD 256
#define HH 8
#define HDIM 32
#define CCTX 64
#define CNODE 8
#define TANH_CLIP 10.0f

#define SPLIT 10          // n-dimension splits for streaming kernels
#define RS (NN / SPLIT)   // 200 rows per split
#define TR 20             // tile rows in k3 (RS/TR = 10 tiles exactly)

#define INV_SQRT_HD 0.17677669529663687f   // 1/sqrt(32)
#define INV_SQRT_D  0.0625f                // 1/sqrt(256)

// ---------------- scratch (no cudaMalloc allowed) ----------------
__device__ float g_sum[BS * DD];                       // sum over n of enc
__device__ float g_qk[BS * HH * DD];                   // per-head query in enc space (scale folded)
__device__ float g_qn[BS * HH * CNODE];                // per-head query in node-feat space
__device__ float g_pm[BS * SPLIT * HH];                // partial max
__device__ float g_pl[BS * SPLIT * HH];                // partial sum-of-exp
__device__ float g_paw[BS * SPLIT * HH * DD];          // partial weighted enc (raw)
__device__ float g_panf[BS * SPLIT * HH * CNODE];      // partial weighted node_feat (raw)
__device__ float g_g2[BS * DD];                        // glimpse @ Wk2 (with 1/sqrt(D))
__device__ float g_gn[BS * CNODE];                     // Wn_l^T glimpse (with 1/sqrt(D))
__device__ float g_tl[BS * NN];                        // clipped masked logits
__device__ float g_pmax[BS * SPLIT];                   // partial max of logits
__device__ int   g_flags;                              // mask dtype detection flags

// ---------------- helpers ----------------
__device__ __forceinline__ void cp_async16(void* sdst, const void* gsrc) {
    unsigned s = (unsigned)__cvta_generic_to_shared(sdst);
    asm volatile("cp.async.cg.shared.global [%0], [%1], 16;\n" :: "r"(s), "l"(gsrc) : "memory");
}
#define CP_COMMIT asm volatile("cp.async.commit_group;\n" ::: "memory")
#define CP_WAIT1  asm volatile("cp.async.wait_group 1;\n" ::: "memory")
#define CP_WAIT0  asm volatile("cp.async.wait_group 0;\n" ::: "memory")

__device__ __forceinline__ bool read_mask(const void* mp, int flags, size_t i) {
    if (flags == 0) return false;
    if (flags & 2) {
        if (flags & 1) return ((const unsigned char*)mp)[i] != 0;  // bool / uint8
        return ((const float*)mp)[i] != 0.0f;                      // float32
    }
    return ((const int*)mp)[i] != 0;                               // int32
}

// ---------------- K00: zero scratch accumulators ----------------
__global__ void k00_zero() {
    int t = blockIdx.x * blockDim.x + threadIdx.x;
    if (t < BS * DD) g_sum[t] = 0.0f;
    if (t == 0) g_flags = 0;
}

// ---------------- K1: partial sums of enc over n (float4, 4 row streams) + mask scan ----
// grid: (BS, 8), block: 256
__global__ __launch_bounds__(256) void k1_sum(const float* __restrict__ enc,
                                              const void* __restrict__ maskp) {
    __shared__ float4 sred[256];
    int b = blockIdx.x, s = blockIdx.y;
    int tid = threadIdx.x;
    const int RPB = NN / 8;  // 250 rows per block
    int c4 = tid & 63;       // column group (4 floats)
    int rg = tid >> 6;       // row stream 0..3

    const float4* base = (const float4*)(enc + ((size_t)b * NN + (size_t)s * RPB) * DD) + c4;
    float4 acc = make_float4(0.f, 0.f, 0.f, 0.f);
#pragma unroll 4
    for (int r = rg; r < RPB; r += 4) {
        float4 v = base[(size_t)r * 64];
        acc.x += v.x; acc.y += v.y; acc.z += v.z; acc.w += v.w;
    }
    sred[tid] = acc;
    __syncthreads();
    if (tid < 64) {
        float4 a = sred[tid], b1 = sred[tid + 64], c = sred[tid + 128], d = sred[tid + 192];
        float* dst = &g_sum[b * DD + c4 * 4];
        atomicAdd(dst + 0, a.x + b1.x + c.x + d.x);
        atomicAdd(dst + 1, a.y + b1.y + c.y + d.y);
        atomicAdd(dst + 2, a.z + b1.z + c.z + d.z);
        atomicAdd(dst + 3, a.w + b1.w + c.w + d.w);
    }

    // mask dtype detection over first BS*NN bytes (safe for all candidate dtypes)
    size_t idx = (size_t)(b * 8 + s) * 256 + tid;
    bool nz0 = false, nz1 = false;
    if (idx < (size_t)BS * NN) {
        unsigned char v = ((const unsigned char*)maskp)[idx];
        if (v) { if ((idx & 3) == 0) nz0 = true; else nz1 = true; }
    }
    unsigned b0 = __ballot_sync(0xffffffffu, nz0);
    unsigned b1 = __ballot_sync(0xffffffffu, nz1);
    if ((tid & 31) == 0) {
        int f = (b0 ? 1 : 0) | (b1 ? 2 : 0);
        if (f) atomicOr(&g_flags, f);
    }
}

// ---------------- K2: per-batch setup: graph_embed, Q, qk, qn ----------------
// grid: BS, block: 256
__global__ __launch_bounds__(256) void k2_setup(const float* __restrict__ shelf,
                                                const float* __restrict__ ctx,
                                                const float* __restrict__ Wk,
                                                const float* __restrict__ Wq,
                                                const float* __restrict__ Wc,
                                                const float* __restrict__ Wg,
                                                const float* __restrict__ Wn,
                                                const int* __restrict__ cur_node) {
    __shared__ float Xs[2 * DD];
    __shared__ float Qs[DD];
    __shared__ float ms[DD];
    int b = blockIdx.x, t = threadIdx.x;

    int cn = cur_node[b];
    Xs[t] = shelf[((size_t)b * NN + cn) * DD + t];
    float a = 0.0f;
#pragma unroll 8
    for (int c = 0; c < CCTX; c++) a += ctx[b * CCTX + c] * Wc[t * CCTX + c];
    Xs[DD + t] = a;
    ms[t] = g_sum[b * DD + t] * (1.0f / NN);
    __syncthreads();

    float q = 0.0f;
#pragma unroll 8
    for (int d2 = 0; d2 < DD; d2++) q += ms[d2] * Wg[t * DD + d2];
#pragma unroll 8
    for (int k = 0; k < 2 * DD; k++) q += Xs[k] * Wq[t * 2 * DD + k];
    Qs[t] = q;
    __syncthreads();

#pragma unroll
    for (int h = 0; h < HH; h++) {
        float a2 = 0.0f;
#pragma unroll 8
        for (int e = 0; e < HDIM; e++) a2 += Qs[h * HDIM + e] * Wk[(h * HDIM + e) * DD + t];
        g_qk[(b * HH + h) * DD + t] = a2 * INV_SQRT_HD;
    }
    if (t < HH * CNODE) {
        int h = t >> 3, c = t & 7;
        float a3 = 0.0f;
#pragma unroll 8
        for (int e = 0; e < HDIM; e++) a3 += Qs[h * HDIM + e] * Wn[(h * HDIM + e) * CNODE + c];
        g_qn[(b * HH + h) * CNODE + c] = a3 * INV_SQRT_HD;
    }
}

// ---------------- K3: split flash glimpse ----------------
// grid: (BS, SPLIT), block: 256 (warp h owns head h). cp.async double-buffered TR-row tiles.
#define NTILES (RS / TR)  // 10, exact
__global__ __launch_bounds__(256) void k3_attn(const float* __restrict__ enc,
                                               const float* __restrict__ nf) {
    __shared__ float encS[2][TR * DD];
    __shared__ float nfS[2][TR * CNODE];
    int b = blockIdx.x, s = blockIdx.y;
    int tid = threadIdx.x, wid = tid >> 5, lane = tid & 31;
    size_t row0 = (size_t)b * NN + (size_t)s * RS;

    const float* qkp = g_qk + (b * HH + wid) * DD + lane * 8;
    float q0 = qkp[0], q1 = qkp[1], q2 = qkp[2], q3 = qkp[3];
    float q4 = qkp[4], q5 = qkp[5], q6 = qkp[6], q7 = qkp[7];
    float qnl = (lane < CNODE) ? g_qn[(b * HH + wid) * CNODE + lane] : 0.0f;

    float aw[8];
#pragma unroll
    for (int j = 0; j < 8; j++) aw[j] = 0.0f;
    float anf = 0.0f, m = -1e30f, l = 0.0f;

    // prologue: load tile 0
    {
        const float* src = enc + row0 * DD;
        float* dst = encS[0];
#pragma unroll
        for (int i = 0; i < 5; i++) { int off = (tid + i * 256) * 4; cp_async16(dst + off, src + off); }
        if (tid < TR * CNODE / 4) {
            const float* ns = nf + row0 * CNODE;
            cp_async16(nfS[0] + tid * 4, ns + tid * 4);
        }
        CP_COMMIT;
    }

    for (int t = 0; t < NTILES; t++) {
        int buf = t & 1;
        if (t + 1 < NTILES) {
            const float* src = enc + (row0 + (size_t)(t + 1) * TR) * DD;
            float* dst = encS[buf ^ 1];
#pragma unroll
            for (int i = 0; i < 5; i++) { int off = (tid + i * 256) * 4; cp_async16(dst + off, src + off); }
            if (tid < TR * CNODE / 4) {
                const float* ns = nf + (row0 + (size_t)(t + 1) * TR) * CNODE;
                cp_async16(nfS[buf ^ 1] + tid * 4, ns + tid * 4);
            }
            CP_COMMIT;
            CP_WAIT1;
        } else {
            CP_WAIT0;
        }
        __syncthreads();

#pragma unroll 4
        for (int r = 0; r < TR; r++) {
            const float* e = &encS[buf][r * DD + lane * 8];
            float4 ea = *(const float4*)(e);
            float4 eb = *(const float4*)(e + 4);
            float p = ea.x * q0 + ea.y * q1 + ea.z * q2 + ea.w * q3
                    + eb.x * q4 + eb.y * q5 + eb.z * q6 + eb.w * q7;
            float nfv = (lane < CNODE) ? nfS[buf][r * CNODE + lane] : 0.0f;
            p += nfv * qnl;
#pragma unroll
            for (int o = 16; o > 0; o >>= 1) p += __shfl_xor_sync(0xffffffffu, p, o);

            // branchless online softmax
            float mn = fmaxf(m, p);
            float c = __expf(m - mn);
            float w = __expf(p - mn);
            m = mn;
            l = l * c + w;
            aw[0] = aw[0] * c + w * ea.x; aw[1] = aw[1] * c + w * ea.y;
            aw[2] = aw[2] * c + w * ea.z; aw[3] = aw[3] * c + w * ea.w;
            aw[4] = aw[4] * c + w * eb.x; aw[5] = aw[5] * c + w * eb.y;
            aw[6] = aw[6] * c + w * eb.z; aw[7] = aw[7] * c + w * eb.w;
            anf = anf * c + w * nfv;
        }
        __syncthreads();
    }

    int pidx = (b * SPLIT + s) * HH + wid;
    if (lane == 0) { g_pm[pidx] = m; g_pl[pidx] = l; }
    float* ao = g_paw + (size_t)pidx * DD + lane * 8;
#pragma unroll
    for (int j = 0; j < 8; j++) ao[j] = aw[j];
    if (lane < CNODE) g_panf[pidx * CNODE + lane] = anf;
}

// ---------------- K4: combine splits + glimpse + g2/gn ----------------
// grid: BS, block: 256
__global__ __launch_bounds__(256) void k4_glimpse(const float* __restrict__ Wv,
                                                  const float* __restrict__ Wout,
                                                  const float* __restrict__ Wk2,
                                                  const float* __restrict__ Wn) {
    __shared__ float sAW[HH * DD];
    __shared__ float sANF[HH * CNODE];
    __shared__ float hs[DD];
    __shared__ float gl[DD];
    int b = blockIdx.x, t = threadIdx.x;
    int h = t >> 5, lane = t & 31;

    // combine partials for head h (each lane of the head's warp computes M,L redundantly)
    float M = -1e30f;
    float es[SPLIT];
#pragma unroll
    for (int s = 0; s < SPLIT; s++) M = fmaxf(M, g_pm[(b * SPLIT + s) * HH + h]);
    float L = 0.0f;
#pragma unroll
    for (int s = 0; s < SPLIT; s++) {
        float e = __expf(g_pm[(b * SPLIT + s) * HH + h] - M);
        es[s] = e;
        L += g_pl[(b * SPLIT + s) * HH + h] * e;
    }
    float invL = 1.0f / L;

#pragma unroll
    for (int j = 0; j < 8; j++) {
        float acc = 0.0f;
#pragma unroll
        for (int s = 0; s < SPLIT; s++)
            acc += es[s] * g_paw[(size_t)((b * SPLIT + s) * HH + h) * DD + lane * 8 + j];
        sAW[h * DD + lane * 8 + j] = acc * invL;
    }
    if (lane < CNODE) {
        float acc = 0.0f;
#pragma unroll
        for (int s = 0; s < SPLIT; s++)
            acc += es[s] * g_panf[((b * SPLIT + s) * HH + h) * CNODE + lane];
        sANF[h * CNODE + lane] = acc * invL;
    }
    __syncthreads();

    // heads: hs[h*32+e] = aw[h]·Wv_row + anf[h]·Wn_v_row
    {
        int e = t & 31;
        const float* awp = &sAW[h * DD];
        const float* wvp = Wv + (h * HDIM + e) * DD;
        float a = 0.0f;
#pragma unroll 8
        for (int d = 0; d < DD; d++) a += awp[d] * wvp[d];
#pragma unroll
        for (int c = 0; c < CNODE; c++)
            a += sANF[h * CNODE + c] * Wn[(DD + h * HDIM + e) * CNODE + c];
        hs[t] = a;
    }
    __syncthreads();

    float g = 0.0f;
#pragma unroll 8
    for (int k = 0; k < DD; k++) g += hs[k] * Wout[t * DD + k];
    gl[t] = g;
    __syncthreads();

    float a2 = 0.0f;
#pragma unroll 8
    for (int d = 0; d < DD; d++) a2 += gl[d] * Wk2[d * DD + t];
    g_g2[b * DD + t] = a2 * INV_SQRT_D;
    if (t < CNODE) {
        float a3 = 0.0f;
#pragma unroll 8
        for (int d = 0; d < DD; d++) a3 += gl[d] * Wn[(2 * DD + d) * CNODE + t];
        g_gn[b * CNODE + t] = a3 * INV_SQRT_D;
    }
}

// ---------------- K5A: split logits: dot + tanh clip + mask + partial max ----------------
// grid: (BS, SPLIT), block: 256 (warp per row)
__global__ __launch_bounds__(256) void k5a_logits(const float* __restrict__ enc,
                                                  const float* __restrict__ nf,
                                                  const void* __restrict__ maskp) {
    __shared__ float g2s[DD];
    __shared__ float gns[CNODE];
    __shared__ float red[8];
    int b = blockIdx.x, s = blockIdx.y;
    int tid = threadIdx.x, wid = tid >> 5, lane = tid & 31;

    g2s[tid] = g_g2[b * DD + tid];
    if (tid < CNODE) gns[tid] = g_gn[b * CNODE + tid];
    int flags = g_flags;
    __syncthreads();

    float ca0 = g2s[lane * 4 + 0], ca1 = g2s[lane * 4 + 1];
    float ca2 = g2s[lane * 4 + 2], ca3 = g2s[lane * 4 + 3];
    float cb0 = g2s[128 + lane * 4 + 0], cb1 = g2s[128 + lane * 4 + 1];
    float cb2 = g2s[128 + lane * 4 + 2], cb3 = g2s[128 + lane * 4 + 3];
    float gnl = (lane < CNODE) ? gns[lane] : 0.0f;

    float wmax = -INFINITY;
    int n0 = s * RS;
#pragma unroll 4
    for (int i = 0; i < RS / 8; i++) {
        int n = n0 + wid + i * 8;
        const float* e = enc + ((size_t)b * NN + n) * DD;
        float4 ea = *(const float4*)(e + lane * 4);
        float4 eb = *(const float4*)(e + 128 + lane * 4);
        float p = ea.x * ca0 + ea.y * ca1 + ea.z * ca2 + ea.w * ca3
                + eb.x * cb0 + eb.y * cb1 + eb.z * cb2 + eb.w * cb3;
        if (lane < CNODE) p += nf[((size_t)b * NN + n) * CNODE + lane] * gnl;
#pragma unroll
        for (int o = 16; o > 0; o >>= 1) p += __shfl_xor_sync(0xffffffffu, p, o);
        if (lane == 0) {
            bool msk = read_mask(maskp, flags, (size_t)b * NN + n);
            float v = msk ? -INFINITY : TANH_CLIP * tanhf(p);
            g_tl[(size_t)b * NN + n] = v;
            wmax = fmaxf(wmax, v);
        }
    }
    if (lane == 0) red[wid] = wmax;
    __syncthreads();
    if (tid == 0) {
        float m = red[0];
#pragma unroll
        for (int w = 1; w < 8; w++) m = fmaxf(m, red[w]);
        g_pmax[b * SPLIT + s] = m;
    }
}

// ---------------- K5B: batch softmax over nodes ----------------
// grid: BS, block: 256
__global__ __launch_bounds__(256) void k5b_softmax(float* __restrict__ out) {
    __shared__ float red[256];
    int b = blockIdx.x, tid = threadIdx.x;

    float mx = -INFINITY;
    if (tid < SPLIT) mx = g_pmax[b * SPLIT + tid];
#pragma unroll
    for (int o = 16; o > 0; o >>= 1) mx = fmaxf(mx, __shfl_xor_sync(0xffffffffu, mx, o));
    mx = __shfl_sync(0xffffffffu, mx, 0);
    if (tid == 0) red[0] = mx;
    __syncthreads();
    mx = red[0];
    __syncthreads();

    float sm = 0.0f;
    for (int n = tid; n < NN; n += 256) sm += __expf(g_tl[(size_t)b * NN + n] - mx);
    red[tid] = sm;
    __syncthreads();
    for (int st = 128; st > 0; st >>= 1) {
        if (tid < st) red[tid] += red[tid + st];
        __syncthreads();
    }
    float inv = 1.0f / red[0];

    for (int n = tid; n < NN; n += 256)
        out[(size_t)b * NN + n] = __expf(g_tl[(size_t)b * NN + n] - mx) * inv;
}

// ---------------- launch ----------------
extern "C" void kernel_launch(void* const* d_in, const int* in_sizes, int n_in,
                              void* d_out, int out_size) {
    const float* shelf = (const float*)d_in[0];
    const float* enc   = (const float*)d_in[1];
    const float* ctx   = (const float*)d_in[2];
    const float* nf    = (const float*)d_in[3];
    const float* Wk    = (const float*)d_in[4];
    const float* Wv    = (const float*)d_in[5];
    const float* Wk2   = (const float*)d_in[6];
    const float* Wq    = (const float*)d_in[7];
    const float* Wout  = (const float*)d_in[8];
    const float* Wc    = (const float*)d_in[9];
    const float* Wg    = (const float*)d_in[10];
    const float* Wn    = (const float*)d_in[11];
    const int*   cur   = (const int*)d_in[12];
    const void*  maskp = (const void*)d_in[13];
    float* out = (float*)d_out;

    k00_zero<<<(BS * DD + 255) / 256, 256>>>();
    {
        dim3 g(BS, 8);
        k1_sum<<<g, 256>>>(enc, maskp);
    }
    k2_setup<<<BS, 256>>>(shelf, ctx, Wk, Wq, Wc, Wg, Wn, cur);
    {
        dim3 g(BS, SPLIT);
        k3_attn<<<g, 256>>>(enc, nf);
    }
    k4_glimpse<<<BS, 256>>>(Wv, Wout, Wk2, Wn);
    {
        dim3 g(BS, SPLIT);
        k5a_logits<<<g, 256>>>(enc, nf, maskp);
    }
    k5b_softmax<<<BS, 256>>>(out);
}

// round 3
// speedup vs baseline: 2.4607x; 1.1900x over previous
#include <cuda_runtime.h>
#include <cuda_bf16.h>
#include <math.h>
#include <stdint.h>

// Problem constants
#define BS 128
#define NN 2000
#define DD 256
#define HH 8
#define HDIM 32
#define CCTX 64
#define CNODE 8
#define TANH_CLIP 10.0f

#define SPLIT 10          // n-splits for k3
#define RS (NN / SPLIT)   // 200 rows per k3 block
#define TR 20             // tile rows in k3
#define NTILES (RS / TR)  // 10

#define SPLITL 20         // n-splits for k5
#define RSL (NN / SPLITL) // 100 rows per k5a block

#define INV_SQRT_HD 0.17677669529663687f   // 1/sqrt(32)
#define INV_SQRT_D  0.0625f                // 1/sqrt(256)

// ---------------- scratch ----------------
__device__ float g_sump[BS * 8 * DD];                  // per-split enc sums
__device__ float g_qk[BS * HH * DD];                   // per-head query in enc space
__device__ float g_qn[BS * HH * CNODE];                // per-head query in nf space
__device__ float g_pm[BS * SPLIT * HH];                // partial max (k3)
__device__ float g_pl[BS * SPLIT * HH];                // partial sum-of-exp (k3)
__device__ float g_paw[BS * SPLIT * HH * DD];          // partial weighted enc (raw)
__device__ float g_panf[BS * SPLIT * HH * CNODE];      // partial weighted nf (raw)
__device__ float g_aw[BS * HH * DD];                   // combined normalized weighted enc
__device__ float g_anfc[BS * HH * CNODE];              // combined normalized weighted nf
__device__ float g_g2[BS * DD];                        // glimpse @ Wk2 (scaled)
__device__ float g_gn[BS * CNODE];                     // Wn_l^T glimpse (scaled)
__device__ float g_tl[BS * NN];                        // clipped masked logits
__device__ float g_pmax[BS * SPLITL];                  // per-split logit max
__device__ float g_psum[BS * SPLITL];                  // per-split expsum (rel. split max)
__device__ float g_M[BS];                              // global logit max
__device__ float g_inv[BS];                            // 1/global expsum
__device__ int   g_flags;                              // mask dtype flags

// ---------------- helpers ----------------
__device__ __forceinline__ void cp_async16(void* sdst, const void* gsrc) {
    unsigned s = (unsigned)__cvta_generic_to_shared(sdst);
    asm volatile("cp.async.cg.shared.global [%0], [%1], 16;\n" :: "r"(s), "l"(gsrc) : "memory");
}
#define CP_COMMIT asm volatile("cp.async.commit_group;\n" ::: "memory")
#define CP_WAIT1  asm volatile("cp.async.wait_group 1;\n" ::: "memory")
#define CP_WAIT0  asm volatile("cp.async.wait_group 0;\n" ::: "memory")
#define FULLM 0xffffffffu

__device__ __forceinline__ bool read_mask(const void* mp, int flags, size_t i) {
    if (flags == 0) return false;
    if (flags & 2) {
        if (flags & 1) return ((const unsigned char*)mp)[i] != 0;  // bool
        return ((const float*)mp)[i] != 0.0f;                      // float32
    }
    return ((const int*)mp)[i] != 0;                               // int32
}

// ---------------- K00: zero flags ----------------
__global__ void k00_zero() { if (threadIdx.x == 0) g_flags = 0; }

// ---------------- K1: per-split partial sums of enc + mask scan ----------------
// grid (BS,8), block 256
__global__ __launch_bounds__(256) void k1_sum(const float* __restrict__ enc,
                                              const void* __restrict__ maskp) {
    __shared__ float4 sred[256];
    int b = blockIdx.x, s = blockIdx.y;
    int tid = threadIdx.x;
    const int RPB = NN / 8;  // 250
    int c4 = tid & 63;
    int rg = tid >> 6;

    const float4* base = (const float4*)(enc + ((size_t)b * NN + (size_t)s * RPB) * DD) + c4;
    float4 acc = make_float4(0.f, 0.f, 0.f, 0.f);
#pragma unroll 4
    for (int r = rg; r < RPB; r += 4) {
        float4 v = base[(size_t)r * 64];
        acc.x += v.x; acc.y += v.y; acc.z += v.z; acc.w += v.w;
    }
    sred[tid] = acc;
    __syncthreads();
    if (tid < 64) {
        float4 a = sred[tid], b1 = sred[tid + 64], c = sred[tid + 128], d = sred[tid + 192];
        float* dst = &g_sump[(b * 8 + s) * DD + c4 * 4];
        dst[0] = a.x + b1.x + c.x + d.x;
        dst[1] = a.y + b1.y + c.y + d.y;
        dst[2] = a.z + b1.z + c.z + d.z;
        dst[3] = a.w + b1.w + c.w + d.w;
    }

    size_t idx = (size_t)(b * 8 + s) * 256 + tid;
    bool nz0 = false, nz1 = false;
    if (idx < (size_t)BS * NN) {
        unsigned char v = ((const unsigned char*)maskp)[idx];
        if (v) { if ((idx & 3) == 0) nz0 = true; else nz1 = true; }
    }
    unsigned b0 = __ballot_sync(FULLM, nz0);
    unsigned b1 = __ballot_sync(FULLM, nz1);
    if ((tid & 31) == 0) {
        int f = (b0 ? 1 : 0) | (b1 ? 2 : 0);
        if (f) atomicOr(&g_flags, f);
    }
}

// ---------------- K2: per-batch setup ----------------
// grid BS, block 256
__global__ __launch_bounds__(256) void k2_setup(const float* __restrict__ shelf,
                                                const float* __restrict__ ctx,
                                                const float* __restrict__ Wk,
                                                const float* __restrict__ Wq,
                                                const float* __restrict__ Wc,
                                                const float* __restrict__ Wg,
                                                const float* __restrict__ Wn,
                                                const int* __restrict__ cur_node) {
    __shared__ float Xs[2 * DD];
    __shared__ float Qs[DD];
    __shared__ float ms[DD];
    int b = blockIdx.x, t = threadIdx.x;

    int cn = cur_node[b];
    Xs[t] = shelf[((size_t)b * NN + cn) * DD + t];
    float a = 0.0f;
#pragma unroll 8
    for (int c = 0; c < CCTX; c++) a += ctx[b * CCTX + c] * Wc[t * CCTX + c];
    Xs[DD + t] = a;
    float sm = 0.0f;
#pragma unroll
    for (int s = 0; s < 8; s++) sm += g_sump[(b * 8 + s) * DD + t];
    ms[t] = sm * (1.0f / NN);
    __syncthreads();

    float q = 0.0f;
#pragma unroll 8
    for (int d2 = 0; d2 < DD; d2++) q += ms[d2] * Wg[t * DD + d2];
#pragma unroll 8
    for (int k = 0; k < 2 * DD; k++) q += Xs[k] * Wq[t * 2 * DD + k];
    Qs[t] = q;
    __syncthreads();

#pragma unroll
    for (int h = 0; h < HH; h++) {
        float a2 = 0.0f;
#pragma unroll 8
        for (int e = 0; e < HDIM; e++) a2 += Qs[h * HDIM + e] * Wk[(h * HDIM + e) * DD + t];
        g_qk[(b * HH + h) * DD + t] = a2 * INV_SQRT_HD;
    }
    if (t < HH * CNODE) {
        int h = t >> 3, c = t & 7;
        float a3 = 0.0f;
#pragma unroll 8
        for (int e = 0; e < HDIM; e++) a3 += Qs[h * HDIM + e] * Wn[(h * HDIM + e) * CNODE + c];
        g_qn[(b * HH + h) * CNODE + c] = a3 * INV_SQRT_HD;
    }
}

// ---------------- K3: split flash glimpse, warps-own-rows, 4 heads/warp ----------------
// grid (BS, SPLIT), block 256
// warp w: head-group g=w>>2 (heads 4g..4g+3), row-lane rl=w&3 (rows r%4==rl within tile)
__global__ __launch_bounds__(256, 2) void k3_attn(const float* __restrict__ enc,
                                                  const float* __restrict__ nf) {
    __shared__ float encS[2][TR * DD];        // 40 KB, aliased for combine at the end
    __shared__ float nfS[2][TR * CNODE];
    __shared__ float cM[8][4], cL[8][4];
    __shared__ float cANF[8][4][CNODE];

    int b = blockIdx.x, s = blockIdx.y;
    int tid = threadIdx.x, w = tid >> 5, lane = tid & 31;
    int g = w >> 2, rl = w & 3;
    size_t row0 = (size_t)b * NN + (size_t)s * RS;

    // queries for this warp's 4 heads, at this lane's 8 dims
    float qr[4][8];
#pragma unroll
    for (int hl = 0; hl < 4; hl++) {
        const float* qp = g_qk + ((size_t)(b * HH + g * 4 + hl)) * DD + lane * 8;
#pragma unroll
        for (int j = 0; j < 8; j++) qr[hl][j] = qp[j];
    }
    float qnr[4];
#pragma unroll
    for (int hl = 0; hl < 4; hl++)
        qnr[hl] = (lane < CNODE) ? g_qn[(b * HH + g * 4 + hl) * CNODE + lane] : 0.0f;

    float aw[4][8];
#pragma unroll
    for (int hl = 0; hl < 4; hl++)
#pragma unroll
        for (int j = 0; j < 8; j++) aw[hl][j] = 0.0f;
    float anf[4] = {0.f, 0.f, 0.f, 0.f};
    float m = -INFINITY, l = 0.0f;   // state for head (lane&3)

    // prologue: tile 0
    {
        const float* src = enc + row0 * DD;
#pragma unroll
        for (int i = 0; i < 5; i++) { int off = (tid + i * 256) * 4; cp_async16(&encS[0][off], src + off); }
        if (tid < TR * CNODE / 4) cp_async16(&nfS[0][tid * 4], nf + row0 * CNODE + tid * 4);
        CP_COMMIT;
    }

    for (int t = 0; t < NTILES; t++) {
        int buf = t & 1;
        if (t + 1 < NTILES) {
            const float* src = enc + (row0 + (size_t)(t + 1) * TR) * DD;
#pragma unroll
            for (int i = 0; i < 5; i++) { int off = (tid + i * 256) * 4; cp_async16(&encS[buf ^ 1][off], src + off); }
            if (tid < TR * CNODE / 4)
                cp_async16(&nfS[buf ^ 1][tid * 4], nf + (row0 + (size_t)(t + 1) * TR) * CNODE + tid * 4);
            CP_COMMIT;
            CP_WAIT1;
        } else {
            CP_WAIT0;
        }
        __syncthreads();

#pragma unroll
        for (int k = 0; k < TR / 4; k++) {
            int r = rl + 4 * k;
            const float* e = &encS[buf][r * DD + lane * 8];
            float4 ea = *(const float4*)(e);
            float4 eb = *(const float4*)(e + 4);
            float nfv = (lane < CNODE) ? nfS[buf][r * CNODE + lane] : 0.0f;

            float sacc[4];
#pragma unroll
            for (int hl = 0; hl < 4; hl++) {
                sacc[hl] = ea.x * qr[hl][0] + ea.y * qr[hl][1] + ea.z * qr[hl][2] + ea.w * qr[hl][3]
                         + eb.x * qr[hl][4] + eb.y * qr[hl][5] + eb.z * qr[hl][6] + eb.w * qr[hl][7]
                         + nfv * qnr[hl];
            }
            // fold-reduce 4 head sums across 32 lanes -> p for head (lane&3)
            float v01 = (lane & 1) ? sacc[1] : sacc[0];
            float o01 = (lane & 1) ? sacc[0] : sacc[1];
            v01 += __shfl_xor_sync(FULLM, o01, 1);
            float v23 = (lane & 1) ? sacc[3] : sacc[2];
            float o23 = (lane & 1) ? sacc[2] : sacc[3];
            v23 += __shfl_xor_sync(FULLM, o23, 1);
            float vv = (lane & 2) ? v23 : v01;
            float oo = (lane & 2) ? v01 : v23;
            vv += __shfl_xor_sync(FULLM, oo, 2);
            vv += __shfl_xor_sync(FULLM, vv, 4);
            vv += __shfl_xor_sync(FULLM, vv, 8);
            vv += __shfl_xor_sync(FULLM, vv, 16);
            float p = vv;

            float mn = fmaxf(m, p);
            unsigned upd = __ballot_sync(FULLM, mn != m);
            float wv = __expf(p - mn);
            if (upd) {
                float c = __expf(m - mn);
                l *= c;
                float c0 = __shfl_sync(FULLM, c, 0);
                float c1 = __shfl_sync(FULLM, c, 1);
                float c2 = __shfl_sync(FULLM, c, 2);
                float c3 = __shfl_sync(FULLM, c, 3);
#pragma unroll
                for (int j = 0; j < 8; j++) {
                    aw[0][j] *= c0; aw[1][j] *= c1; aw[2][j] *= c2; aw[3][j] *= c3;
                }
                anf[0] *= c0; anf[1] *= c1; anf[2] *= c2; anf[3] *= c3;
            }
            m = mn;
            l += wv;
            float w0 = __shfl_sync(FULLM, wv, 0);
            float w1 = __shfl_sync(FULLM, wv, 1);
            float w2 = __shfl_sync(FULLM, wv, 2);
            float w3 = __shfl_sync(FULLM, wv, 3);
            aw[0][0] += w0 * ea.x; aw[0][1] += w0 * ea.y; aw[0][2] += w0 * ea.z; aw[0][3] += w0 * ea.w;
            aw[0][4] += w0 * eb.x; aw[0][5] += w0 * eb.y; aw[0][6] += w0 * eb.z; aw[0][7] += w0 * eb.w;
            aw[1][0] += w1 * ea.x; aw[1][1] += w1 * ea.y; aw[1][2] += w1 * ea.z; aw[1][3] += w1 * ea.w;
            aw[1][4] += w1 * eb.x; aw[1][5] += w1 * eb.y; aw[1][6] += w1 * eb.z; aw[1][7] += w1 * eb.w;
            aw[2][0] += w2 * ea.x; aw[2][1] += w2 * ea.y; aw[2][2] += w2 * ea.z; aw[2][3] += w2 * ea.w;
            aw[2][4] += w2 * eb.x; aw[2][5] += w2 * eb.y; aw[2][6] += w2 * eb.z; aw[2][7] += w2 * eb.w;
            aw[3][0] += w3 * ea.x; aw[3][1] += w3 * ea.y; aw[3][2] += w3 * ea.z; aw[3][3] += w3 * ea.w;
            aw[3][4] += w3 * eb.x; aw[3][5] += w3 * eb.y; aw[3][6] += w3 * eb.z; aw[3][7] += w3 * eb.w;
            anf[0] += w0 * nfv; anf[1] += w1 * nfv; anf[2] += w2 * nfv; anf[3] += w3 * nfv;
        }
        __syncthreads();
    }

    // ---- block combine: 4 row-warps per head-group -> split partials ----
    float* cAW = (float*)encS;   // 8 warps * 4 heads * 256 dims = 32 KB (enc tiles are dead)
    if (lane < 4) { cM[w][lane] = m; cL[w][lane] = l; }
#pragma unroll
    for (int hl = 0; hl < 4; hl++) {
#pragma unroll
        for (int j = 0; j < 8; j++) cAW[(w * 4 + hl) * DD + lane * 8 + j] = aw[hl][j];
    }
    if (lane < CNODE) {
#pragma unroll
        for (int hl = 0; hl < 4; hl++) cANF[w][hl][lane] = anf[hl];
    }
    __syncthreads();

    // warp w combines global head h = w
    {
        int h = w, g2 = h >> 2, hl2 = h & 3;
        float M = -INFINITY;
#pragma unroll
        for (int rw = 0; rw < 4; rw++) M = fmaxf(M, cM[g2 * 4 + rw][hl2]);
        float es[4], L = 0.0f;
#pragma unroll
        for (int rw = 0; rw < 4; rw++) {
            es[rw] = __expf(cM[g2 * 4 + rw][hl2] - M);
            L += cL[g2 * 4 + rw][hl2] * es[rw];
        }
        int pidx = (b * SPLIT + s) * HH + h;
        float* dst = g_paw + (size_t)pidx * DD + lane * 8;
#pragma unroll
        for (int j = 0; j < 8; j++) {
            float acc = 0.0f;
#pragma unroll
            for (int rw = 0; rw < 4; rw++)
                acc += es[rw] * cAW[((g2 * 4 + rw) * 4 + hl2) * DD + lane * 8 + j];
            dst[j] = acc;
        }
        if (lane == 0) { g_pm[pidx] = M; g_pl[pidx] = L; }
        if (lane < CNODE) {
            float acc = 0.0f;
#pragma unroll
            for (int rw = 0; rw < 4; rw++) acc += es[rw] * cANF[g2 * 4 + rw][hl2][lane];
            g_panf[pidx * CNODE + lane] = acc;
        }
    }
}

// ---------------- K4a: combine split partials -> normalized aw/anf ----------------
// grid (BS, HH), block 256 (thread = dim)
__global__ __launch_bounds__(256) void k4a_combine() {
    int b = blockIdx.x, h = blockIdx.y, t = threadIdx.x;
    float M = -INFINITY;
#pragma unroll
    for (int s = 0; s < SPLIT; s++) M = fmaxf(M, g_pm[(b * SPLIT + s) * HH + h]);
    float es[SPLIT], L = 0.0f;
#pragma unroll
    for (int s = 0; s < SPLIT; s++) {
        es[s] = __expf(g_pm[(b * SPLIT + s) * HH + h] - M);
        L += g_pl[(b * SPLIT + s) * HH + h] * es[s];
    }
    float invL = 1.0f / L;
    float acc = 0.0f;
#pragma unroll
    for (int s = 0; s < SPLIT; s++)
        acc += es[s] * g_paw[(size_t)((b * SPLIT + s) * HH + h) * DD + t];
    g_aw[(b * HH + h) * DD + t] = acc * invL;
    if (t < CNODE) {
        float a2 = 0.0f;
#pragma unroll
        for (int s = 0; s < SPLIT; s++)
            a2 += es[s] * g_panf[((b * SPLIT + s) * HH + h) * CNODE + t];
        g_anfc[(b * HH + h) * CNODE + t] = a2 * invL;
    }
}

// ---------------- K4b: glimpse + g2/gn ----------------
// grid BS, block 256
__global__ __launch_bounds__(256) void k4b_glimpse(const float* __restrict__ Wv,
                                                   const float* __restrict__ Wout,
                                                   const float* __restrict__ Wk2,
                                                   const float* __restrict__ Wn) {
    __shared__ float hs[DD];
    __shared__ float gl[DD];
    int b = blockIdx.x, t = threadIdx.x;
    int h = t >> 5, e = t & 31;

    const float* awp = g_aw + (b * HH + h) * DD;
    const float* wvp = Wv + (h * HDIM + e) * DD;
    float a = 0.0f;
#pragma unroll 8
    for (int d = 0; d < DD; d++) a += awp[d] * wvp[d];
#pragma unroll
    for (int c = 0; c < CNODE; c++)
        a += g_anfc[(b * HH + h) * CNODE + c] * Wn[(DD + h * HDIM + e) * CNODE + c];
    hs[t] = a;
    __syncthreads();

    float g = 0.0f;
#pragma unroll 8
    for (int k = 0; k < DD; k++) g += hs[k] * Wout[t * DD + k];
    gl[t] = g;
    __syncthreads();

    float a2 = 0.0f;
#pragma unroll 8
    for (int d = 0; d < DD; d++) a2 += gl[d] * Wk2[d * DD + t];
    g_g2[b * DD + t] = a2 * INV_SQRT_D;
    if (t < CNODE) {
        float a3 = 0.0f;
#pragma unroll 8
        for (int d = 0; d < DD; d++) a3 += gl[d] * Wn[(2 * DD + d) * CNODE + t];
        g_gn[b * CNODE + t] = a3 * INV_SQRT_D;
    }
}

// ---------------- K5a: split logits + per-split max & expsum ----------------
// grid (BS, SPLITL), block 256 (warp per row)
__global__ __launch_bounds__(256) void k5a_logits(const float* __restrict__ enc,
                                                  const float* __restrict__ nf,
                                                  const void* __restrict__ maskp) {
    __shared__ float g2s[DD];
    __shared__ float gns[CNODE];
    __shared__ float tls[RSL];
    __shared__ float red[256];
    int b = blockIdx.x, s = blockIdx.y;
    int tid = threadIdx.x, wid = tid >> 5, lane = tid & 31;

    g2s[tid] = g_g2[b * DD + tid];
    if (tid < CNODE) gns[tid] = g_gn[b * CNODE + tid];
    int flags = g_flags;
    __syncthreads();

    float ca0 = g2s[lane * 4 + 0], ca1 = g2s[lane * 4 + 1];
    float ca2 = g2s[lane * 4 + 2], ca3 = g2s[lane * 4 + 3];
    float cb0 = g2s[128 + lane * 4 + 0], cb1 = g2s[128 + lane * 4 + 1];
    float cb2 = g2s[128 + lane * 4 + 2], cb3 = g2s[128 + lane * 4 + 3];
    float gnl = (lane < CNODE) ? gns[lane] : 0.0f;

    int n0 = s * RSL;
#pragma unroll
    for (int i = 0; i < (RSL + 7) / 8; i++) {
        int rr = wid + i * 8;
        if (rr >= RSL) break;
        int n = n0 + rr;
        const float* e = enc + ((size_t)b * NN + n) * DD;
        float4 ea = *(const float4*)(e + lane * 4);
        float4 eb = *(const float4*)(e + 128 + lane * 4);
        float p = ea.x * ca0 + ea.y * ca1 + ea.z * ca2 + ea.w * ca3
                + eb.x * cb0 + eb.y * cb1 + eb.z * cb2 + eb.w * cb3;
        if (lane < CNODE) p += nf[((size_t)b * NN + n) * CNODE + lane] * gnl;
#pragma unroll
        for (int o = 16; o > 0; o >>= 1) p += __shfl_xor_sync(FULLM, p, o);
        if (lane == 0) {
            bool msk = read_mask(maskp, flags, (size_t)b * NN + n);
            float v = msk ? -INFINITY : TANH_CLIP * tanhf(p);
            g_tl[(size_t)b * NN + n] = v;
            tls[rr] = v;
        }
    }
    __syncthreads();

    // block max over RSL logits
    float mx = -INFINITY;
    for (int r = tid; r < RSL; r += 256) mx = fmaxf(mx, tls[r]);
    red[tid] = mx;
    __syncthreads();
    for (int st = 128; st > 0; st >>= 1) {
        if (tid < st) red[tid] = fmaxf(red[tid], red[tid + st]);
        __syncthreads();
    }
    mx = red[0];
    __syncthreads();

    float sm = 0.0f;
    if (mx > -INFINITY) {
        for (int r = tid; r < RSL; r += 256) sm += __expf(tls[r] - mx);
    }
    red[tid] = sm;
    __syncthreads();
    for (int st = 128; st > 0; st >>= 1) {
        if (tid < st) red[tid] += red[tid + st];
        __syncthreads();
    }
    if (tid == 0) {
        g_pmax[b * SPLITL + s] = mx;
        g_psum[b * SPLITL + s] = (mx > -INFINITY) ? red[0] : 0.0f;
    }
}

// ---------------- K5b: tiny combine ----------------
// grid BS, block 32
__global__ void k5b_combine() {
    int b = blockIdx.x, t = threadIdx.x;
    float mx = (t < SPLITL) ? g_pmax[b * SPLITL + t] : -INFINITY;
#pragma unroll
    for (int o = 16; o > 0; o >>= 1) mx = fmaxf(mx, __shfl_xor_sync(FULLM, mx, o));
    float sm = 0.0f;
    if (t < SPLITL) {
        float pm = g_pmax[b * SPLITL + t];
        sm = (pm > -INFINITY) ? g_psum[b * SPLITL + t] * __expf(pm - mx) : 0.0f;
    }
#pragma unroll
    for (int o = 16; o > 0; o >>= 1) sm += __shfl_xor_sync(FULLM, sm, o);
    if (t == 0) { g_M[b] = mx; g_inv[b] = 1.0f / sm; }
}

// ---------------- K5c: normalize ----------------
// grid (BS, SPLITL), block 128
__global__ __launch_bounds__(128) void k5c_norm(float* __restrict__ out) {
    int b = blockIdx.x, s = blockIdx.y, t = threadIdx.x;
    float M = g_M[b], inv = g_inv[b];
    int n0 = s * RSL;
    for (int r = t; r < RSL; r += 128) {
        size_t i = (size_t)b * NN + n0 + r;
        out[i] = __expf(g_tl[i] - M) * inv;
    }
}

// ---------------- launch ----------------
extern "C" void kernel_launch(void* const* d_in, const int* in_sizes, int n_in,
                              void* d_out, int out_size) {
    const float* shelf = (const float*)d_in[0];
    const float* enc   = (const float*)d_in[1];
    const float* ctx   = (const float*)d_in[2];
    const float* nf    = (const float*)d_in[3];
    const float* Wk    = (const float*)d_in[4];
    const float* Wv    = (const float*)d_in[5];
    const float* Wk2   = (const float*)d_in[6];
    const float* Wq    = (const float*)d_in[7];
    const float* Wout  = (const float*)d_in[8];
    const float* Wc    = (const float*)d_in[9];
    const float* Wg    = (const float*)d_in[10];
    const float* Wn    = (const float*)d_in[11];
    const int*   cur   = (const int*)d_in[12];
    const void*  maskp = (const void*)d_in[13];
    float* out = (float*)d_out;

    k00_zero<<<1, 32>>>();
    { dim3 g(BS, 8);  k1_sum<<<g, 256>>>(enc, maskp); }
    k2_setup<<<BS, 256>>>(shelf, ctx, Wk, Wq, Wc, Wg, Wn, cur);
    { dim3 g(BS, SPLIT); k3_attn<<<g, 256>>>(enc, nf); }
    { dim3 g(BS, HH);    k4a_combine<<<g, 256>>>(); }
    k4b_glimpse<<<BS, 256>>>(Wv, Wout, Wk2, Wn);
    { dim3 g(BS, SPLITL); k5a_logits<<<g, 256>>>(enc, nf, maskp); }
    k5b_combine<<<BS, 32>>>();
    { dim3 g(BS, SPLITL); k5c_norm<<<g, 128>>>(out); }
}

// round 6
// speedup vs baseline: 2.8557x; 1.1605x over previous
#include <cuda_runtime.h>
#include <cuda_bf16.h>
#include <math.h>
#include <stdint.h>

// Problem constants
#define BS 128
#define NN 2000
#define DD 256
#define HH 8
#define HDIM 32
#define CCTX 64
#define CNODE 8
#define TANH_CLIP 10.0f

#define SPLIT 10          // n-splits for k3
#define RS (NN / SPLIT)   // 200 rows per k3 block
#define TR 20             // tile rows in k3
#define NTILES (RS / TR)  // 10

#define SPLITL 20         // n-splits for k5
#define RSL (NN / SPLITL) // 100 rows per k5a block

#define INV_SQRT_HD 0.17677669529663687f   // 1/sqrt(32)
#define INV_SQRT_D  0.0625f                // 1/sqrt(256)

typedef unsigned long long u64;

// ---------------- scratch (16B aligned: packed u64/float4 access) ----------------
__device__ __align__(16) float g_sump[BS * 8 * DD];
__device__ __align__(16) float g_qk[BS * HH * DD];
__device__ __align__(16) float g_qn[BS * HH * CNODE];
__device__ __align__(16) float g_pm[BS * SPLIT * HH];
__device__ __align__(16) float g_pl[BS * SPLIT * HH];
__device__ __align__(16) float g_paw[BS * SPLIT * HH * DD];
__device__ __align__(16) float g_panf[BS * SPLIT * HH * CNODE];
__device__ __align__(16) float g_aw[BS * HH * DD];
__device__ __align__(16) float g_anfc[BS * HH * CNODE];
__device__ __align__(16) float g_g2[BS * DD];
__device__ __align__(16) float g_gn[BS * CNODE];
__device__ __align__(16) float g_tl[BS * NN];
__device__ __align__(16) float g_pmax[BS * SPLITL];
__device__ __align__(16) float g_psum[BS * SPLITL];
__device__ float g_M[BS];
__device__ float g_inv[BS];
__device__ int   g_flags;

// ---------------- helpers ----------------
__device__ __forceinline__ void cp_async16(void* sdst, const void* gsrc) {
    unsigned s = (unsigned)__cvta_generic_to_shared(sdst);
    asm volatile("cp.async.cg.shared.global [%0], [%1], 16;\n" :: "r"(s), "l"(gsrc) : "memory");
}
#define CP_COMMIT asm volatile("cp.async.commit_group;\n" ::: "memory")
#define CP_WAIT1  asm volatile("cp.async.wait_group 1;\n" ::: "memory")
#define CP_WAIT0  asm volatile("cp.async.wait_group 0;\n" ::: "memory")
#define FULLM 0xffffffffu

// packed fp32x2 (Blackwell FFMA2 — PTX-only path)
__device__ __forceinline__ u64 fma2(u64 a, u64 b, u64 c) {
    u64 d; asm("fma.rn.f32x2 %0, %1, %2, %3;" : "=l"(d) : "l"(a), "l"(b), "l"(c)); return d;
}
__device__ __forceinline__ u64 mul2(u64 a, u64 b) {
    u64 d; asm("mul.rn.f32x2 %0, %1, %2;" : "=l"(d) : "l"(a), "l"(b)); return d;
}
__device__ __forceinline__ u64 pk2(float lo, float hi) {
    u64 r; asm("mov.b64 %0, {%1, %2};" : "=l"(r) : "f"(lo), "f"(hi)); return r;
}
__device__ __forceinline__ float hsum2(u64 v) {
    float lo, hi; asm("mov.b64 {%0, %1}, %2;" : "=f"(lo), "=f"(hi) : "l"(v)); return lo + hi;
}

__device__ __forceinline__ bool read_mask(const void* mp, int flags, size_t i) {
    if (flags == 0) return false;
    if (flags & 2) {
        if (flags & 1) return ((const unsigned char*)mp)[i] != 0;  // bool
        return ((const float*)mp)[i] != 0.0f;                      // float32
    }
    return ((const int*)mp)[i] != 0;                               // int32
}

// ---------------- K00 ----------------
__global__ void k00_zero() { if (threadIdx.x == 0) g_flags = 0; }

// ---------------- K1: per-split partial sums of enc + mask scan ----------------
// grid (BS,8), block 256
__global__ __launch_bounds__(256) void k1_sum(const float* __restrict__ enc,
                                              const void* __restrict__ maskp) {
    __shared__ __align__(16) float4 sred[256];
    int b = blockIdx.x, s = blockIdx.y;
    int tid = threadIdx.x;
    const int RPB = NN / 8;  // 250
    int c4 = tid & 63;
    int rg = tid >> 6;

    const float4* base = (const float4*)(enc + ((size_t)b * NN + (size_t)s * RPB) * DD) + c4;
    float4 acc = make_float4(0.f, 0.f, 0.f, 0.f);
#pragma unroll 8
    for (int r = rg; r < RPB; r += 4) {
        float4 v = base[(size_t)r * 64];
        acc.x += v.x; acc.y += v.y; acc.z += v.z; acc.w += v.w;
    }
    sred[tid] = acc;
    __syncthreads();
    if (tid < 64) {
        float4 a = sred[tid], b1 = sred[tid + 64], c = sred[tid + 128], d = sred[tid + 192];
        float* dst = &g_sump[(b * 8 + s) * DD + c4 * 4];
        dst[0] = a.x + b1.x + c.x + d.x;
        dst[1] = a.y + b1.y + c.y + d.y;
        dst[2] = a.z + b1.z + c.z + d.z;
        dst[3] = a.w + b1.w + c.w + d.w;
    }

    size_t idx = (size_t)(b * 8 + s) * 256 + tid;
    bool nz0 = false, nz1 = false;
    if (idx < (size_t)BS * NN) {
        unsigned char v = ((const unsigned char*)maskp)[idx];
        if (v) { if ((idx & 3) == 0) nz0 = true; else nz1 = true; }
    }
    unsigned b0 = __ballot_sync(FULLM, nz0);
    unsigned b1 = __ballot_sync(FULLM, nz1);
    if ((tid & 31) == 0) {
        int f = (b0 ? 1 : 0) | (b1 ? 2 : 0);
        if (f) atomicOr(&g_flags, f);
    }
}

// ---------------- K2: per-batch setup (coalesced warp-GEMV) ----------------
// grid BS, block 256
__global__ __launch_bounds__(256) void k2_setup(const float* __restrict__ shelf,
                                                const float* __restrict__ ctx,
                                                const float* __restrict__ Wk,
                                                const float* __restrict__ Wq,
                                                const float* __restrict__ Wc,
                                                const float* __restrict__ Wg,
                                                const float* __restrict__ Wn,
                                                const int* __restrict__ cur_node) {
    __shared__ __align__(16) float Xs[2 * DD];
    __shared__ __align__(16) float Qs[DD];
    __shared__ __align__(16) float ms[DD];
    int b = blockIdx.x, t = threadIdx.x;
    int w = t >> 5, lane = t & 31;

    int cn = cur_node[b];
    Xs[t] = shelf[((size_t)b * NN + cn) * DD + t];
    float a = 0.0f;
#pragma unroll 8
    for (int c = 0; c < CCTX; c++) a += ctx[b * CCTX + c] * Wc[t * CCTX + c];
    Xs[DD + t] = a;
    float smv = 0.0f;
#pragma unroll
    for (int s = 0; s < 8; s++) smv += g_sump[(b * 8 + s) * DD + t];
    ms[t] = smv * (1.0f / NN);
    __syncthreads();

    // warp-GEMV: warp w computes Qs[w*32 .. w*32+31], lanes split k (coalesced)
    {
        float msr[8];
        const float4* msp = (const float4*)ms + lane * 2;
        { float4 v0 = msp[0], v1 = msp[1];
          msr[0]=v0.x; msr[1]=v0.y; msr[2]=v0.z; msr[3]=v0.w;
          msr[4]=v1.x; msr[5]=v1.y; msr[6]=v1.z; msr[7]=v1.w; }
        float xr[16];
        const float4* xp = (const float4*)Xs + lane * 4;
#pragma unroll
        for (int j = 0; j < 4; j++) {
            float4 v = xp[j];
            xr[j*4+0]=v.x; xr[j*4+1]=v.y; xr[j*4+2]=v.z; xr[j*4+3]=v.w;
        }
#pragma unroll 4
        for (int o = 0; o < 32; o++) {
            int tt = w * 32 + o;
            const float4* wg4 = (const float4*)(Wg + (size_t)tt * DD) + lane * 2;
            const float4* wq4 = (const float4*)(Wq + (size_t)tt * 2 * DD) + lane * 4;
            float acc = 0.0f;
            float4 g0 = wg4[0], g1 = wg4[1];
            acc += msr[0]*g0.x + msr[1]*g0.y + msr[2]*g0.z + msr[3]*g0.w;
            acc += msr[4]*g1.x + msr[5]*g1.y + msr[6]*g1.z + msr[7]*g1.w;
#pragma unroll
            for (int j = 0; j < 4; j++) {
                float4 q4 = wq4[j];
                acc += xr[j*4+0]*q4.x + xr[j*4+1]*q4.y + xr[j*4+2]*q4.z + xr[j*4+3]*q4.w;
            }
#pragma unroll
            for (int o2 = 16; o2 > 0; o2 >>= 1) acc += __shfl_xor_sync(FULLM, acc, o2);
            if (lane == 0) Qs[tt] = acc;
        }
    }
    __syncthreads();

#pragma unroll
    for (int h = 0; h < HH; h++) {
        float a2 = 0.0f;
#pragma unroll 8
        for (int e = 0; e < HDIM; e++) a2 += Qs[h * HDIM + e] * Wk[(h * HDIM + e) * DD + t];
        g_qk[(b * HH + h) * DD + t] = a2 * INV_SQRT_HD;
    }
    if (t < HH * CNODE) {
        int h = t >> 3, c = t & 7;
        float a3 = 0.0f;
#pragma unroll 8
        for (int e = 0; e < HDIM; e++) a3 += Qs[h * HDIM + e] * Wn[(h * HDIM + e) * CNODE + c];
        g_qn[(b * HH + h) * CNODE + c] = a3 * INV_SQRT_HD;
    }
}

// ---------------- K3: split flash glimpse, warps-own-rows, 4 heads/warp, f32x2 ----------------
// grid (BS, SPLIT), block 256
__global__ __launch_bounds__(256, 2) void k3_attn(const float* __restrict__ enc,
                                                  const float* __restrict__ nf) {
    __shared__ __align__(16) float encS[2][TR * DD];   // 40 KB, aliased for combine
    __shared__ __align__(16) float nfS[2][TR * CNODE];
    __shared__ float cM[8][4], cL[8][4];
    __shared__ float cANF[8][4][CNODE];

    int b = blockIdx.x, s = blockIdx.y;
    int tid = threadIdx.x, w = tid >> 5, lane = tid & 31;
    int g = w >> 2, rl = w & 3;
    size_t row0 = (size_t)b * NN + (size_t)s * RS;

    // packed queries: 4 heads x 4 pairs (8 dims at lane*8)
    u64 qp[4][4];
#pragma unroll
    for (int hl = 0; hl < 4; hl++) {
        const ulonglong2* qq = (const ulonglong2*)(g_qk + ((size_t)(b * HH + g * 4 + hl)) * DD + lane * 8);
        ulonglong2 qa = qq[0], qb = qq[1];
        qp[hl][0] = qa.x; qp[hl][1] = qa.y; qp[hl][2] = qb.x; qp[hl][3] = qb.y;
    }
    float qnr[4];
#pragma unroll
    for (int hl = 0; hl < 4; hl++)
        qnr[hl] = (lane < CNODE) ? g_qn[(b * HH + g * 4 + hl) * CNODE + lane] : 0.0f;

    u64 aw[4][4];
    const u64 z2 = 0ull;
#pragma unroll
    for (int hl = 0; hl < 4; hl++)
#pragma unroll
        for (int j = 0; j < 4; j++) aw[hl][j] = z2;
    float anf[4] = {0.f, 0.f, 0.f, 0.f};
    float m = -INFINITY, l = 0.0f;   // state for head (lane&3)

    // prologue: tile 0
    {
        const float* src = enc + row0 * DD;
#pragma unroll
        for (int i = 0; i < 5; i++) { int off = (tid + i * 256) * 4; cp_async16(&encS[0][off], src + off); }
        if (tid < TR * CNODE / 4) cp_async16(&nfS[0][tid * 4], nf + row0 * CNODE + tid * 4);
        CP_COMMIT;
    }

    for (int t = 0; t < NTILES; t++) {
        int buf = t & 1;
        if (t + 1 < NTILES) {
            const float* src = enc + (row0 + (size_t)(t + 1) * TR) * DD;
#pragma unroll
            for (int i = 0; i < 5; i++) { int off = (tid + i * 256) * 4; cp_async16(&encS[buf ^ 1][off], src + off); }
            if (tid < TR * CNODE / 4)
                cp_async16(&nfS[buf ^ 1][tid * 4], nf + (row0 + (size_t)(t + 1) * TR) * CNODE + tid * 4);
            CP_COMMIT;
            CP_WAIT1;
        } else {
            CP_WAIT0;
        }
        __syncthreads();

#pragma unroll
        for (int k = 0; k < TR / 4; k++) {
            int r = rl + 4 * k;
            const ulonglong2* e2 = (const ulonglong2*)(&encS[buf][r * DD + lane * 8]);
            ulonglong2 eA = e2[0], eB = e2[1];  // (d0d1,d2d3),(d4d5,d6d7)
            float nfv = (lane < CNODE) ? nfS[buf][r * CNODE + lane] : 0.0f;

            float sacc[4];
#pragma unroll
            for (int hl = 0; hl < 4; hl++) {
                u64 acc2 = mul2(eA.x, qp[hl][0]);
                acc2 = fma2(eA.y, qp[hl][1], acc2);
                acc2 = fma2(eB.x, qp[hl][2], acc2);
                acc2 = fma2(eB.y, qp[hl][3], acc2);
                sacc[hl] = hsum2(acc2) + nfv * qnr[hl];
            }
            // fold-reduce 4 head sums across 32 lanes -> p for head (lane&3)
            float v01 = (lane & 1) ? sacc[1] : sacc[0];
            float o01 = (lane & 1) ? sacc[0] : sacc[1];
            v01 += __shfl_xor_sync(FULLM, o01, 1);
            float v23 = (lane & 1) ? sacc[3] : sacc[2];
            float o23 = (lane & 1) ? sacc[2] : sacc[3];
            v23 += __shfl_xor_sync(FULLM, o23, 1);
            float vv = (lane & 2) ? v23 : v01;
            float oo = (lane & 2) ? v01 : v23;
            vv += __shfl_xor_sync(FULLM, oo, 2);
            vv += __shfl_xor_sync(FULLM, vv, 4);
            vv += __shfl_xor_sync(FULLM, vv, 8);
            vv += __shfl_xor_sync(FULLM, vv, 16);
            float p = vv;

            float mn = fmaxf(m, p);
            unsigned upd = __ballot_sync(FULLM, mn != m);
            float wv = __expf(p - mn);
            if (upd) {
                float c = __expf(m - mn);
                l *= c;
                u64 c0 = pk2(1.f, 1.f);
                float cc0 = __shfl_sync(FULLM, c, 0);
                float cc1 = __shfl_sync(FULLM, c, 1);
                float cc2 = __shfl_sync(FULLM, c, 2);
                float cc3 = __shfl_sync(FULLM, c, 3);
                u64 cp0 = pk2(cc0, cc0), cp1 = pk2(cc1, cc1);
                u64 cp2 = pk2(cc2, cc2), cp3 = pk2(cc3, cc3);
                (void)c0;
#pragma unroll
                for (int j = 0; j < 4; j++) {
                    aw[0][j] = mul2(aw[0][j], cp0);
                    aw[1][j] = mul2(aw[1][j], cp1);
                    aw[2][j] = mul2(aw[2][j], cp2);
                    aw[3][j] = mul2(aw[3][j], cp3);
                }
                anf[0] *= cc0; anf[1] *= cc1; anf[2] *= cc2; anf[3] *= cc3;
            }
            m = mn;
            l += wv;
            float w0 = __shfl_sync(FULLM, wv, 0);
            float w1 = __shfl_sync(FULLM, wv, 1);
            float w2 = __shfl_sync(FULLM, wv, 2);
            float w3 = __shfl_sync(FULLM, wv, 3);
            u64 wp0 = pk2(w0, w0), wp1 = pk2(w1, w1), wp2 = pk2(w2, w2), wp3 = pk2(w3, w3);
            aw[0][0] = fma2(eA.x, wp0, aw[0][0]); aw[0][1] = fma2(eA.y, wp0, aw[0][1]);
            aw[0][2] = fma2(eB.x, wp0, aw[0][2]); aw[0][3] = fma2(eB.y, wp0, aw[0][3]);
            aw[1][0] = fma2(eA.x, wp1, aw[1][0]); aw[1][1] = fma2(eA.y, wp1, aw[1][1]);
            aw[1][2] = fma2(eB.x, wp1, aw[1][2]); aw[1][3] = fma2(eB.y, wp1, aw[1][3]);
            aw[2][0] = fma2(eA.x, wp2, aw[2][0]); aw[2][1] = fma2(eA.y, wp2, aw[2][1]);
            aw[2][2] = fma2(eB.x, wp2, aw[2][2]); aw[2][3] = fma2(eB.y, wp2, aw[2][3]);
            aw[3][0] = fma2(eA.x, wp3, aw[3][0]); aw[3][1] = fma2(eA.y, wp3, aw[3][1]);
            aw[3][2] = fma2(eB.x, wp3, aw[3][2]); aw[3][3] = fma2(eB.y, wp3, aw[3][3]);
            anf[0] += w0 * nfv; anf[1] += w1 * nfv; anf[2] += w2 * nfv; anf[3] += w3 * nfv;
        }
        __syncthreads();
    }

    // ---- block combine: 4 row-warps per head-group -> split partials ----
    u64* cAW = (u64*)encS;   // 8 warps * 4 heads * 128 u64
    if (lane < 4) { cM[w][lane] = m; cL[w][lane] = l; }
#pragma unroll
    for (int hl = 0; hl < 4; hl++) {
#pragma unroll
        for (int j = 0; j < 4; j++) cAW[(w * 4 + hl) * (DD / 2) + lane * 4 + j] = aw[hl][j];
    }
    if (lane < CNODE) {
#pragma unroll
        for (int hl = 0; hl < 4; hl++) cANF[w][hl][lane] = anf[hl];
    }
    __syncthreads();

    // warp w combines global head h = w
    {
        int h = w, g2 = h >> 2, hl2 = h & 3;
        float M = -INFINITY;
#pragma unroll
        for (int rw = 0; rw < 4; rw++) M = fmaxf(M, cM[g2 * 4 + rw][hl2]);
        float es[4], L = 0.0f;
#pragma unroll
        for (int rw = 0; rw < 4; rw++) {
            es[rw] = __expf(cM[g2 * 4 + rw][hl2] - M);
            L += cL[g2 * 4 + rw][hl2] * es[rw];
        }
        int pidx = (b * SPLIT + s) * HH + h;
        u64* dst = (u64*)g_paw + (size_t)pidx * (DD / 2) + lane * 4;
        u64 ep[4];
#pragma unroll
        for (int rw = 0; rw < 4; rw++) ep[rw] = pk2(es[rw], es[rw]);
#pragma unroll
        for (int j = 0; j < 4; j++) {
            u64 acc = 0ull;
#pragma unroll
            for (int rw = 0; rw < 4; rw++)
                acc = fma2(cAW[((g2 * 4 + rw) * 4 + hl2) * (DD / 2) + lane * 4 + j], ep[rw], acc);
            dst[j] = acc;
        }
        if (lane == 0) { g_pm[pidx] = M; g_pl[pidx] = L; }
        if (lane < CNODE) {
            float acc = 0.0f;
#pragma unroll
            for (int rw = 0; rw < 4; rw++) acc += es[rw] * cANF[g2 * 4 + rw][hl2][lane];
            g_panf[pidx * CNODE + lane] = acc;
        }
    }
}

// ---------------- K4a: combine split partials -> normalized aw/anf ----------------
// grid (BS, HH), block 256
__global__ __launch_bounds__(256) void k4a_combine() {
    int b = blockIdx.x, h = blockIdx.y, t = threadIdx.x;
    float M = -INFINITY;
#pragma unroll
    for (int s = 0; s < SPLIT; s++) M = fmaxf(M, g_pm[(b * SPLIT + s) * HH + h]);
    float es[SPLIT], L = 0.0f;
#pragma unroll
    for (int s = 0; s < SPLIT; s++) {
        es[s] = __expf(g_pm[(b * SPLIT + s) * HH + h] - M);
        L += g_pl[(b * SPLIT + s) * HH + h] * es[s];
    }
    float invL = 1.0f / L;
    float acc = 0.0f;
#pragma unroll
    for (int s = 0; s < SPLIT; s++)
        acc += es[s] * g_paw[(size_t)((b * SPLIT + s) * HH + h) * DD + t];
    g_aw[(b * HH + h) * DD + t] = acc * invL;
    if (t < CNODE) {
        float a2 = 0.0f;
#pragma unroll
        for (int s = 0; s < SPLIT; s++)
            a2 += es[s] * g_panf[((b * SPLIT + s) * HH + h) * CNODE + t];
        g_anfc[(b * HH + h) * CNODE + t] = a2 * invL;
    }
}

// ---------------- K4b: glimpse + g2/gn ----------------
// grid BS, block 256
__global__ __launch_bounds__(256) void k4b_glimpse(const float* __restrict__ Wv,
                                                   const float* __restrict__ Wout,
                                                   const float* __restrict__ Wk2,
                                                   const float* __restrict__ Wn) {
    __shared__ __align__(16) float hs[DD];
    __shared__ __align__(16) float gl[DD];
    int b = blockIdx.x, t = threadIdx.x;
    int h = t >> 5, e = t & 31;

    const float* awp = g_aw + (b * HH + h) * DD;
    const float* wvp = Wv + (h * HDIM + e) * DD;
    float a = 0.0f;
#pragma unroll 8
    for (int d = 0; d < DD; d++) a += awp[d] * wvp[d];
#pragma unroll
    for (int c = 0; c < CNODE; c++)
        a += g_anfc[(b * HH + h) * CNODE + c] * Wn[(DD + h * HDIM + e) * CNODE + c];
    hs[t] = a;
    __syncthreads();

    float g = 0.0f;
#pragma unroll 8
    for (int k = 0; k < DD; k++) g += hs[k] * Wout[t * DD + k];
    gl[t] = g;
    __syncthreads();

    float a2 = 0.0f;
#pragma unroll 8
    for (int d = 0; d < DD; d++) a2 += gl[d] * Wk2[d * DD + t];
    g_g2[b * DD + t] = a2 * INV_SQRT_D;
    if (t < CNODE) {
        float a3 = 0.0f;
#pragma unroll 8
        for (int d = 0; d < DD; d++) a3 += gl[d] * Wn[(2 * DD + d) * CNODE + t];
        g_gn[b * CNODE + t] = a3 * INV_SQRT_D;
    }
}

// ---------------- K5a: split logits, 2 rows in flight per warp, packed dot ----------------
// grid (BS, SPLITL), block 256
__global__ __launch_bounds__(256) void k5a_logits(const float* __restrict__ enc,
                                                  const float* __restrict__ nf,
                                                  const void* __restrict__ maskp) {
    __shared__ __align__(16) float g2s[DD];
    __shared__ float gns[CNODE];
    __shared__ float tls[RSL];
    __shared__ float red[256];
    int b = blockIdx.x, s = blockIdx.y;
    int tid = threadIdx.x, wid = tid >> 5, lane = tid & 31;

    g2s[tid] = g_g2[b * DD + tid];
    if (tid < CNODE) gns[tid] = g_gn[b * CNODE + tid];
    int flags = g_flags;
    __syncthreads();

    // packed g2 coefficients for this lane's 8 dims (lane*4 and 128+lane*4)
    const ulonglong2* cpa = (const ulonglong2*)(g2s + lane * 4);
    const ulonglong2* cpb = (const ulonglong2*)(g2s + 128 + lane * 4);
    ulonglong2 cA = cpa[0], cB = cpb[0];
    float gnl = (lane < CNODE) ? gns[lane] : 0.0f;

    int n0 = s * RSL;
    size_t rowb = (size_t)b * NN;
    // rows rr = wid + 8*i, i = 0..12 (rr < 100); process 2 per iteration
#pragma unroll
    for (int i = 0; i < 13; i += 2) {
        int r1 = wid + 8 * i;
        int r2 = r1 + 8;
        bool v1 = r1 < RSL, v2 = r2 < RSL;
        float p1 = 0.f, p2v = 0.f;
        if (v1) {
            const ulonglong2* e1a = (const ulonglong2*)(enc + (rowb + n0 + r1) * DD + lane * 4);
            const ulonglong2* e1b = (const ulonglong2*)(enc + (rowb + n0 + r1) * DD + 128 + lane * 4);
            ulonglong2 ea = e1a[0], eb = e1b[0];
            u64 a2 = mul2(ea.x, cA.x); a2 = fma2(ea.y, cA.y, a2);
            a2 = fma2(eb.x, cB.x, a2); a2 = fma2(eb.y, cB.y, a2);
            p1 = hsum2(a2);
            if (lane < CNODE) p1 += nf[(rowb + n0 + r1) * CNODE + lane] * gnl;
        }
        if (v2) {
            const ulonglong2* e2a = (const ulonglong2*)(enc + (rowb + n0 + r2) * DD + lane * 4);
            const ulonglong2* e2b = (const ulonglong2*)(enc + (rowb + n0 + r2) * DD + 128 + lane * 4);
            ulonglong2 ea = e2a[0], eb = e2b[0];
            u64 a2 = mul2(ea.x, cA.x); a2 = fma2(ea.y, cA.y, a2);
            a2 = fma2(eb.x, cB.x, a2); a2 = fma2(eb.y, cB.y, a2);
            p2v = hsum2(a2);
            if (lane < CNODE) p2v += nf[(rowb + n0 + r2) * CNODE + lane] * gnl;
        }
#pragma unroll
        for (int o = 16; o > 0; o >>= 1) {
            p1 += __shfl_xor_sync(FULLM, p1, o);
            p2v += __shfl_xor_sync(FULLM, p2v, o);
        }
        if (lane == 0) {
            if (v1) {
                bool msk = read_mask(maskp, flags, rowb + n0 + r1);
                float v = msk ? -INFINITY : TANH_CLIP * tanhf(p1);
                g_tl[rowb + n0 + r1] = v;
                tls[r1] = v;
            }
            if (v2) {
                bool msk = read_mask(maskp, flags, rowb + n0 + r2);
                float v = msk ? -INFINITY : TANH_CLIP * tanhf(p2v);
                g_tl[rowb + n0 + r2] = v;
                tls[r2] = v;
            }
        }
    }
    __syncthreads();

    float mx = -INFINITY;
    for (int r = tid; r < RSL; r += 256) mx = fmaxf(mx, tls[r]);
    red[tid] = mx;
    __syncthreads();
    for (int st = 128; st > 0; st >>= 1) {
        if (tid < st) red[tid] = fmaxf(red[tid], red[tid + st]);
        __syncthreads();
    }
    mx = red[0];
    __syncthreads();

    float sm = 0.0f;
    if (mx > -INFINITY) {
        for (int r = tid; r < RSL; r += 256) sm += __expf(tls[r] - mx);
    }
    red[tid] = sm;
    __syncthreads();
    for (int st = 128; st > 0; st >>= 1) {
        if (tid < st) red[tid] += red[tid + st];
        __syncthreads();
    }
    if (tid == 0) {
        g_pmax[b * SPLITL + s] = mx;
        g_psum[b * SPLITL + s] = (mx > -INFINITY) ? red[0] : 0.0f;
    }
}

// ---------------- K5b: tiny combine ----------------
__global__ void k5b_combine() {
    int b = blockIdx.x, t = threadIdx.x;
    float mx = (t < SPLITL) ? g_pmax[b * SPLITL + t] : -INFINITY;
#pragma unroll
    for (int o = 16; o > 0; o >>= 1) mx = fmaxf(mx, __shfl_xor_sync(FULLM, mx, o));
    float sm = 0.0f;
    if (t < SPLITL) {
        float pm = g_pmax[b * SPLITL + t];
        sm = (pm > -INFINITY) ? g_psum[b * SPLITL + t] * __expf(pm - mx) : 0.0f;
    }
#pragma unroll
    for (int o = 16; o > 0; o >>= 1) sm += __shfl_xor_sync(FULLM, sm, o);
    if (t == 0) { g_M[b] = mx; g_inv[b] = 1.0f / sm; }
}

// ---------------- K5c: normalize ----------------
__global__ __launch_bounds__(128) void k5c_norm(float* __restrict__ out) {
    int b = blockIdx.x, s = blockIdx.y, t = threadIdx.x;
    float M = g_M[b], inv = g_inv[b];
    int n0 = s * RSL;
    for (int r = t; r < RSL; r += 128) {
        size_t i = (size_t)b * NN + n0 + r;
        out[i] = __expf(g_tl[i] - M) * inv;
    }
}

// ---------------- launch ----------------
extern "C" void kernel_launch(void* const* d_in, const int* in_sizes, int n_in,
                              void* d_out, int out_size) {
    const float* shelf = (const float*)d_in[0];
    const float* enc   = (const float*)d_in[1];
    const float* ctx   = (const float*)d_in[2];
    const float* nf    = (const float*)d_in[3];
    const float* Wk    = (const float*)d_in[4];
    const float* Wv    = (const float*)d_in[5];
    const float* Wk2   = (const float*)d_in[6];
    const float* Wq    = (const float*)d_in[7];
    const float* Wout  = (const float*)d_in[8];
    const float* Wc    = (const float*)d_in[9];
    const float* Wg    = (const float*)d_in[10];
    const float* Wn    = (const float*)d_in[11];
    const int*   cur   = (const int*)d_in[12];
    const void*  maskp = (const void*)d_in[13];
    float* out = (float*)d_out;

    k00_zero<<<1, 32>>>();
    { dim3 g(BS, 8);  k1_sum<<<g, 256>>>(enc, maskp); }
    k2_setup<<<BS, 256>>>(shelf, ctx, Wk, Wq, Wc, Wg, Wn, cur);
    { dim3 g(BS, SPLIT); k3_attn<<<g, 256>>>(enc, nf); }
    { dim3 g(BS, HH);    k4a_combine<<<g, 256>>>(); }
    k4b_glimpse<<<BS, 256>>>(Wv, Wout, Wk2, Wn);
    { dim3 g(BS, SPLITL); k5a_logits<<<g, 256>>>(enc, nf, maskp); }
    k5b_combine<<<BS, 32>>>();
    { dim3 g(BS, SPLITL); k5c_norm<<<g, 128>>>(out); }
}

// round 7
// speedup vs baseline: 3.1416x; 1.1001x over previous
#include <cuda_runtime.h>
#include <cuda_bf16.h>
#include <math.h>
#include <stdint.h>

// Problem constants
#define BS 128
#define NN 2000
#define DD 256
#define HH 8
#define HDIM 32
#define CCTX 64
#define CNODE 8
#define TANH_CLIP 10.0f

#define SPLIT 20          // n-splits for k3
#define RS (NN / SPLIT)   // 100 rows per k3 block
#define TR 20             // tile rows in k3
#define NTILES (RS / TR)  // 5
#define RPW (TR / 4)      // 5 rows per warp per tile

#define SPLIT1 16         // n-splits for k1
#define RPB1 (NN / SPLIT1) // 125

#define SPLITL 20         // n-splits for k5
#define RSL (NN / SPLITL) // 100 rows per k5a block

#define INV_SQRT_HD 0.17677669529663687f   // 1/sqrt(32)
#define INV_SQRT_D  0.0625f                // 1/sqrt(256)

typedef unsigned long long u64;

// ---------------- scratch (16B aligned: packed u64/float4 access) ----------------
__device__ __align__(16) float g_sump[BS * SPLIT1 * DD];
__device__ __align__(16) float g_qk[BS * HH * DD];
__device__ __align__(16) float g_qn[BS * HH * CNODE];
__device__ __align__(16) float g_pm[BS * SPLIT * HH];
__device__ __align__(16) float g_pl[BS * SPLIT * HH];
__device__ __align__(16) float g_paw[BS * SPLIT * HH * DD];
__device__ __align__(16) float g_panf[BS * SPLIT * HH * CNODE];
__device__ __align__(16) float g_aw[BS * HH * DD];
__device__ __align__(16) float g_anfc[BS * HH * CNODE];
__device__ __align__(16) float g_g2[BS * DD];
__device__ __align__(16) float g_gn[BS * CNODE];
__device__ __align__(16) float g_tl[BS * NN];
__device__ __align__(16) float g_pmax[BS * SPLITL];
__device__ __align__(16) float g_psum[BS * SPLITL];
__device__ float g_M[BS];
__device__ float g_inv[BS];
__device__ int   g_flags;

// ---------------- helpers ----------------
__device__ __forceinline__ void cp_async16(void* sdst, const void* gsrc) {
    unsigned s = (unsigned)__cvta_generic_to_shared(sdst);
    asm volatile("cp.async.cg.shared.global [%0], [%1], 16;\n" :: "r"(s), "l"(gsrc) : "memory");
}
#define CP_COMMIT asm volatile("cp.async.commit_group;\n" ::: "memory")
#define CP_WAIT1  asm volatile("cp.async.wait_group 1;\n" ::: "memory")
#define CP_WAIT0  asm volatile("cp.async.wait_group 0;\n" ::: "memory")
#define FULLM 0xffffffffu

// packed fp32x2 (Blackwell FFMA2 — PTX-only path)
__device__ __forceinline__ u64 fma2(u64 a, u64 b, u64 c) {
    u64 d; asm("fma.rn.f32x2 %0, %1, %2, %3;" : "=l"(d) : "l"(a), "l"(b), "l"(c)); return d;
}
__device__ __forceinline__ u64 mul2(u64 a, u64 b) {
    u64 d; asm("mul.rn.f32x2 %0, %1, %2;" : "=l"(d) : "l"(a), "l"(b)); return d;
}
__device__ __forceinline__ u64 pk2(float lo, float hi) {
    u64 r; asm("mov.b64 %0, {%1, %2};" : "=l"(r) : "f"(lo), "f"(hi)); return r;
}
__device__ __forceinline__ float hsum2(u64 v) {
    float lo, hi; asm("mov.b64 {%0, %1}, %2;" : "=f"(lo), "=f"(hi) : "l"(v)); return lo + hi;
}

__device__ __forceinline__ bool read_mask(const void* mp, int flags, size_t i) {
    if (flags == 0) return false;
    if (flags & 2) {
        if (flags & 1) return ((const unsigned char*)mp)[i] != 0;  // bool
        return ((const float*)mp)[i] != 0.0f;                      // float32
    }
    return ((const int*)mp)[i] != 0;                               // int32
}

// ---------------- K00 ----------------
__global__ void k00_zero() { if (threadIdx.x == 0) g_flags = 0; }

// ---------------- K1: per-split partial sums of enc + mask scan ----------------
// grid (BS, SPLIT1), block 256
__global__ __launch_bounds__(256) void k1_sum(const float* __restrict__ enc,
                                              const void* __restrict__ maskp) {
    __shared__ __align__(16) float4 sred[256];
    int b = blockIdx.x, s = blockIdx.y;
    int tid = threadIdx.x;
    int c4 = tid & 63;
    int rg = tid >> 6;

    const float4* base = (const float4*)(enc + ((size_t)b * NN + (size_t)s * RPB1) * DD) + c4;
    float4 acc = make_float4(0.f, 0.f, 0.f, 0.f);
#pragma unroll 8
    for (int r = rg; r < RPB1; r += 4) {
        float4 v = base[(size_t)r * 64];
        acc.x += v.x; acc.y += v.y; acc.z += v.z; acc.w += v.w;
    }
    sred[tid] = acc;
    __syncthreads();
    if (tid < 64) {
        float4 a = sred[tid], b1 = sred[tid + 64], c = sred[tid + 128], d = sred[tid + 192];
        float* dst = &g_sump[(b * SPLIT1 + s) * DD + c4 * 4];
        dst[0] = a.x + b1.x + c.x + d.x;
        dst[1] = a.y + b1.y + c.y + d.y;
        dst[2] = a.z + b1.z + c.z + d.z;
        dst[3] = a.w + b1.w + c.w + d.w;
    }

    size_t idx = (size_t)(b * SPLIT1 + s) * 256 + tid;
    bool nz0 = false, nz1 = false;
    if (idx < (size_t)BS * NN) {
        unsigned char v = ((const unsigned char*)maskp)[idx];
        if (v) { if ((idx & 3) == 0) nz0 = true; else nz1 = true; }
    }
    unsigned b0 = __ballot_sync(FULLM, nz0);
    unsigned b1 = __ballot_sync(FULLM, nz1);
    if ((tid & 31) == 0) {
        int f = (b0 ? 1 : 0) | (b1 ? 2 : 0);
        if (f) atomicOr(&g_flags, f);
    }
}

// ---------------- K2: per-batch setup (coalesced warp-GEMV) ----------------
// grid BS, block 256
__global__ __launch_bounds__(256) void k2_setup(const float* __restrict__ shelf,
                                                const float* __restrict__ ctx,
                                                const float* __restrict__ Wk,
                                                const float* __restrict__ Wq,
                                                const float* __restrict__ Wc,
                                                const float* __restrict__ Wg,
                                                const float* __restrict__ Wn,
                                                const int* __restrict__ cur_node) {
    __shared__ __align__(16) float Xs[2 * DD];
    __shared__ __align__(16) float Qs[DD];
    __shared__ __align__(16) float ms[DD];
    int b = blockIdx.x, t = threadIdx.x;
    int w = t >> 5, lane = t & 31;

    int cn = cur_node[b];
    Xs[t] = shelf[((size_t)b * NN + cn) * DD + t];
    float a = 0.0f;
#pragma unroll 8
    for (int c = 0; c < CCTX; c++) a += ctx[b * CCTX + c] * Wc[t * CCTX + c];
    Xs[DD + t] = a;
    float smv = 0.0f;
#pragma unroll
    for (int s = 0; s < SPLIT1; s++) smv += g_sump[(b * SPLIT1 + s) * DD + t];
    ms[t] = smv * (1.0f / NN);
    __syncthreads();

    // warp-GEMV: warp w computes Qs[w*32 .. w*32+31], lanes split k (coalesced)
    {
        float msr[8];
        const float4* msp = (const float4*)ms + lane * 2;
        { float4 v0 = msp[0], v1 = msp[1];
          msr[0]=v0.x; msr[1]=v0.y; msr[2]=v0.z; msr[3]=v0.w;
          msr[4]=v1.x; msr[5]=v1.y; msr[6]=v1.z; msr[7]=v1.w; }
        float xr[16];
        const float4* xp = (const float4*)Xs + lane * 4;
#pragma unroll
        for (int j = 0; j < 4; j++) {
            float4 v = xp[j];
            xr[j*4+0]=v.x; xr[j*4+1]=v.y; xr[j*4+2]=v.z; xr[j*4+3]=v.w;
        }
#pragma unroll 4
        for (int o = 0; o < 32; o++) {
            int tt = w * 32 + o;
            const float4* wg4 = (const float4*)(Wg + (size_t)tt * DD) + lane * 2;
            const float4* wq4 = (const float4*)(Wq + (size_t)tt * 2 * DD) + lane * 4;
            float acc = 0.0f;
            float4 g0 = wg4[0], g1 = wg4[1];
            acc += msr[0]*g0.x + msr[1]*g0.y + msr[2]*g0.z + msr[3]*g0.w;
            acc += msr[4]*g1.x + msr[5]*g1.y + msr[6]*g1.z + msr[7]*g1.w;
#pragma unroll
            for (int j = 0; j < 4; j++) {
                float4 q4 = wq4[j];
                acc += xr[j*4+0]*q4.x + xr[j*4+1]*q4.y + xr[j*4+2]*q4.z + xr[j*4+3]*q4.w;
            }
#pragma unroll
            for (int o2 = 16; o2 > 0; o2 >>= 1) acc += __shfl_xor_sync(FULLM, acc, o2);
            if (lane == 0) Qs[tt] = acc;
        }
    }
    __syncthreads();

#pragma unroll
    for (int h = 0; h < HH; h++) {
        float a2 = 0.0f;
#pragma unroll 8
        for (int e = 0; e < HDIM; e++) a2 += Qs[h * HDIM + e] * Wk[(h * HDIM + e) * DD + t];
        g_qk[(b * HH + h) * DD + t] = a2 * INV_SQRT_HD;
    }
    if (t < HH * CNODE) {
        int h = t >> 3, c = t & 7;
        float a3 = 0.0f;
#pragma unroll 8
        for (int e = 0; e < HDIM; e++) a3 += Qs[h * HDIM + e] * Wn[(h * HDIM + e) * CNODE + c];
        g_qn[(b * HH + h) * CNODE + c] = a3 * INV_SQRT_HD;
    }
}

// ---------------- K3: split flash glimpse, per-tile rescale, phased chains ----------------
// grid (BS, SPLIT), block 256
// warp w: head-group g=w>>2 (heads 4g..4g+3), row-lane rl=w&3 (rows r%4==rl within tile)
__global__ __launch_bounds__(256, 2) void k3_attn(const float* __restrict__ enc,
                                                  const float* __restrict__ nf) {
    __shared__ __align__(16) float encS[2][TR * DD];   // 40 KB, aliased for combine
    __shared__ __align__(16) float nfS[2][TR * CNODE];
    __shared__ float cM[8][4], cL[8][4];
    __shared__ float cANF[8][4][CNODE];

    int b = blockIdx.x, s = blockIdx.y;
    int tid = threadIdx.x, w = tid >> 5, lane = tid & 31;
    int g = w >> 2, rl = w & 3;
    size_t row0 = (size_t)b * NN + (size_t)s * RS;

    // packed queries: 4 heads x 4 pairs (8 dims at lane*8)
    u64 qp[4][4];
#pragma unroll
    for (int hl = 0; hl < 4; hl++) {
        const ulonglong2* qq = (const ulonglong2*)(g_qk + ((size_t)(b * HH + g * 4 + hl)) * DD + lane * 8);
        ulonglong2 qa = qq[0], qb = qq[1];
        qp[hl][0] = qa.x; qp[hl][1] = qa.y; qp[hl][2] = qb.x; qp[hl][3] = qb.y;
    }
    float qnr[4];
#pragma unroll
    for (int hl = 0; hl < 4; hl++)
        qnr[hl] = (lane < CNODE) ? g_qn[(b * HH + g * 4 + hl) * CNODE + lane] : 0.0f;

    u64 aw[4][4];
#pragma unroll
    for (int hl = 0; hl < 4; hl++)
#pragma unroll
        for (int j = 0; j < 4; j++) aw[hl][j] = 0ull;
    float anf[4] = {0.f, 0.f, 0.f, 0.f};
    float m = -INFINITY, l = 0.0f;   // per-lane state for head (lane&3)

    // prologue: tile 0
    {
        const float* src = enc + row0 * DD;
#pragma unroll
        for (int i = 0; i < 5; i++) { int off = (tid + i * 256) * 4; cp_async16(&encS[0][off], src + off); }
        if (tid < TR * CNODE / 4) cp_async16(&nfS[0][tid * 4], nf + row0 * CNODE + tid * 4);
        CP_COMMIT;
    }

    for (int t = 0; t < NTILES; t++) {
        int buf = t & 1;
        if (t + 1 < NTILES) {
            const float* src = enc + (row0 + (size_t)(t + 1) * TR) * DD;
#pragma unroll
            for (int i = 0; i < 5; i++) { int off = (tid + i * 256) * 4; cp_async16(&encS[buf ^ 1][off], src + off); }
            if (tid < TR * CNODE / 4)
                cp_async16(&nfS[buf ^ 1][tid * 4], nf + (row0 + (size_t)(t + 1) * TR) * CNODE + tid * 4);
            CP_COMMIT;
            CP_WAIT1;
        } else {
            CP_WAIT0;
        }
        __syncthreads();

        // ---- phase 1: dots for my RPW rows ----
        float sacc[RPW][4];
#pragma unroll
        for (int k = 0; k < RPW; k++) {
            int r = rl + 4 * k;
            const ulonglong2* e2 = (const ulonglong2*)(&encS[buf][r * DD + lane * 8]);
            ulonglong2 eA = e2[0], eB = e2[1];
            float nfv = (lane < CNODE) ? nfS[buf][r * CNODE + lane] : 0.0f;
#pragma unroll
            for (int hl = 0; hl < 4; hl++) {
                u64 acc2 = mul2(eA.x, qp[hl][0]);
                acc2 = fma2(eA.y, qp[hl][1], acc2);
                acc2 = fma2(eB.x, qp[hl][2], acc2);
                acc2 = fma2(eB.y, qp[hl][3], acc2);
                sacc[k][hl] = hsum2(acc2) + nfv * qnr[hl];
            }
        }

        // ---- interleaved fold-reduces (independent chains) ----
        float pk[RPW];
#pragma unroll
        for (int k = 0; k < RPW; k++) {
            float v01 = (lane & 1) ? sacc[k][1] : sacc[k][0];
            float o01 = (lane & 1) ? sacc[k][0] : sacc[k][1];
            v01 += __shfl_xor_sync(FULLM, o01, 1);
            float v23 = (lane & 1) ? sacc[k][3] : sacc[k][2];
            float o23 = (lane & 1) ? sacc[k][2] : sacc[k][3];
            v23 += __shfl_xor_sync(FULLM, o23, 1);
            float vv = (lane & 2) ? v23 : v01;
            float oo = (lane & 2) ? v01 : v23;
            vv += __shfl_xor_sync(FULLM, oo, 2);
            vv += __shfl_xor_sync(FULLM, vv, 4);
            vv += __shfl_xor_sync(FULLM, vv, 8);
            vv += __shfl_xor_sync(FULLM, vv, 16);
            pk[k] = vv;     // p for head (lane&3), row rl+4k
        }

        // ---- phase 2: one rescale per tile ----
        float tmax = pk[0];
#pragma unroll
        for (int k = 1; k < RPW; k++) tmax = fmaxf(tmax, pk[k]);
        float mn = fmaxf(m, tmax);
        float c = __expf(m - mn);   // 0 on first tile (m=-inf), often 1 later
        m = mn;
        l *= c;
        {
            float cc0 = __shfl_sync(FULLM, c, 0);
            float cc1 = __shfl_sync(FULLM, c, 1);
            float cc2 = __shfl_sync(FULLM, c, 2);
            float cc3 = __shfl_sync(FULLM, c, 3);
            u64 cp0 = pk2(cc0, cc0), cp1 = pk2(cc1, cc1);
            u64 cp2 = pk2(cc2, cc2), cp3 = pk2(cc3, cc3);
#pragma unroll
            for (int j = 0; j < 4; j++) {
                aw[0][j] = mul2(aw[0][j], cp0);
                aw[1][j] = mul2(aw[1][j], cp1);
                aw[2][j] = mul2(aw[2][j], cp2);
                aw[3][j] = mul2(aw[3][j], cp3);
            }
            anf[0] *= cc0; anf[1] *= cc1; anf[2] *= cc2; anf[3] *= cc3;
        }

        // ---- phase 3: accumulate rows (1-deep broadcast per row) ----
#pragma unroll
        for (int k = 0; k < RPW; k++) {
            int r = rl + 4 * k;
            float wv = __expf(pk[k] - m);
            l += wv;
            float w0 = __shfl_sync(FULLM, wv, 0);
            float w1 = __shfl_sync(FULLM, wv, 1);
            float w2 = __shfl_sync(FULLM, wv, 2);
            float w3 = __shfl_sync(FULLM, wv, 3);
            const ulonglong2* e2 = (const ulonglong2*)(&encS[buf][r * DD + lane * 8]);
            ulonglong2 eA = e2[0], eB = e2[1];
            float nfv = (lane < CNODE) ? nfS[buf][r * CNODE + lane] : 0.0f;
            u64 wp0 = pk2(w0, w0), wp1 = pk2(w1, w1), wp2 = pk2(w2, w2), wp3 = pk2(w3, w3);
            aw[0][0] = fma2(eA.x, wp0, aw[0][0]); aw[0][1] = fma2(eA.y, wp0, aw[0][1]);
            aw[0][2] = fma2(eB.x, wp0, aw[0][2]); aw[0][3] = fma2(eB.y, wp0, aw[0][3]);
            aw[1][0] = fma2(eA.x, wp1, aw[1][0]); aw[1][1] = fma2(eA.y, wp1, aw[1][1]);
            aw[1][2] = fma2(eB.x, wp1, aw[1][2]); aw[1][3] = fma2(eB.y, wp1, aw[1][3]);
            aw[2][0] = fma2(eA.x, wp2, aw[2][0]); aw[2][1] = fma2(eA.y, wp2, aw[2][1]);
            aw[2][2] = fma2(eB.x, wp2, aw[2][2]); aw[2][3] = fma2(eB.y, wp2, aw[2][3]);
            aw[3][0] = fma2(eA.x, wp3, aw[3][0]); aw[3][1] = fma2(eA.y, wp3, aw[3][1]);
            aw[3][2] = fma2(eB.x, wp3, aw[3][2]); aw[3][3] = fma2(eB.y, wp3, aw[3][3]);
            anf[0] += w0 * nfv; anf[1] += w1 * nfv; anf[2] += w2 * nfv; anf[3] += w3 * nfv;
        }
        __syncthreads();
    }

    // ---- block combine: 4 row-warps per head-group -> split partials ----
    u64* cAW = (u64*)encS;   // 8 warps * 4 heads * 128 u64 = 32 KB (enc tiles dead)
    if (lane < 4) { cM[w][lane] = m; cL[w][lane] = l; }
#pragma unroll
    for (int hl = 0; hl < 4; hl++) {
#pragma unroll
        for (int j = 0; j < 4; j++) cAW[(w * 4 + hl) * (DD / 2) + lane * 4 + j] = aw[hl][j];
    }
    if (lane < CNODE) {
#pragma unroll
        for (int hl = 0; hl < 4; hl++) cANF[w][hl][lane] = anf[hl];
    }
    __syncthreads();

    // warp w combines global head h = w
    {
        int h = w, g2 = h >> 2, hl2 = h & 3;
        float M = -INFINITY;
#pragma unroll
        for (int rw = 0; rw < 4; rw++) M = fmaxf(M, cM[g2 * 4 + rw][hl2]);
        float es[4], L = 0.0f;
#pragma unroll
        for (int rw = 0; rw < 4; rw++) {
            es[rw] = __expf(cM[g2 * 4 + rw][hl2] - M);
            L += cL[g2 * 4 + rw][hl2] * es[rw];
        }
        int pidx = (b * SPLIT + s) * HH + h;
        u64* dst = (u64*)g_paw + (size_t)pidx * (DD / 2) + lane * 4;
        u64 ep[4];
#pragma unroll
        for (int rw = 0; rw < 4; rw++) ep[rw] = pk2(es[rw], es[rw]);
#pragma unroll
        for (int j = 0; j < 4; j++) {
            u64 acc = 0ull;
#pragma unroll
            for (int rw = 0; rw < 4; rw++)
                acc = fma2(cAW[((g2 * 4 + rw) * 4 + hl2) * (DD / 2) + lane * 4 + j], ep[rw], acc);
            dst[j] = acc;
        }
        if (lane == 0) { g_pm[pidx] = M; g_pl[pidx] = L; }
        if (lane < CNODE) {
            float acc = 0.0f;
#pragma unroll
            for (int rw = 0; rw < 4; rw++) acc += es[rw] * cANF[g2 * 4 + rw][hl2][lane];
            g_panf[pidx * CNODE + lane] = acc;
        }
    }
}

// ---------------- K4a: combine split partials -> normalized aw/anf ----------------
// grid (BS, HH), block 256
__global__ __launch_bounds__(256) void k4a_combine() {
    int b = blockIdx.x, h = blockIdx.y, t = threadIdx.x;
    float M = -INFINITY;
#pragma unroll
    for (int s = 0; s < SPLIT; s++) M = fmaxf(M, g_pm[(b * SPLIT + s) * HH + h]);
    float es[SPLIT], L = 0.0f;
#pragma unroll
    for (int s = 0; s < SPLIT; s++) {
        es[s] = __expf(g_pm[(b * SPLIT + s) * HH + h] - M);
        L += g_pl[(b * SPLIT + s) * HH + h] * es[s];
    }
    float invL = 1.0f / L;
    float acc = 0.0f;
#pragma unroll
    for (int s = 0; s < SPLIT; s++)
        acc += es[s] * g_paw[(size_t)((b * SPLIT + s) * HH + h) * DD + t];
    g_aw[(b * HH + h) * DD + t] = acc * invL;
    if (t < CNODE) {
        float a2 = 0.0f;
#pragma unroll
        for (int s = 0; s < SPLIT; s++)
            a2 += es[s] * g_panf[((b * SPLIT + s) * HH + h) * CNODE + t];
        g_anfc[(b * HH + h) * CNODE + t] = a2 * invL;
    }
}

// ---------------- K4b: glimpse + g2/gn (warp-GEMV, coalesced) ----------------
// grid BS, block 256
__global__ __launch_bounds__(256) void k4b_glimpse(const float* __restrict__ Wv,
                                                   const float* __restrict__ Wout,
                                                   const float* __restrict__ Wk2,
                                                   const float* __restrict__ Wn) {
    __shared__ __align__(16) float hs[DD];
    __shared__ __align__(16) float gl[DD];
    int b = blockIdx.x, t = threadIdx.x;
    int w = t >> 5, lane = t & 31;

    // stage 1: hs[w*32+o] = aw[head w]·Wv_row(o) + anf·Wn_v_row(o)
    {
        float awr[8];
        const float4* ap = (const float4*)(g_aw + ((size_t)(b * HH + w)) * DD + lane * 8);
        float4 a0 = ap[0], a1 = ap[1];
        awr[0]=a0.x; awr[1]=a0.y; awr[2]=a0.z; awr[3]=a0.w;
        awr[4]=a1.x; awr[5]=a1.y; awr[6]=a1.z; awr[7]=a1.w;
        float anfr = (lane < CNODE) ? g_anfc[(b * HH + w) * CNODE + lane] : 0.0f;
#pragma unroll 4
        for (int o = 0; o < 32; o++) {
            int row = w * HDIM + o;
            const float4* wv4 = (const float4*)(Wv + (size_t)row * DD) + lane * 2;
            float4 v0 = wv4[0], v1 = wv4[1];
            float acc = awr[0]*v0.x + awr[1]*v0.y + awr[2]*v0.z + awr[3]*v0.w
                      + awr[4]*v1.x + awr[5]*v1.y + awr[6]*v1.z + awr[7]*v1.w;
            if (lane < CNODE) acc += anfr * Wn[(DD + row) * CNODE + lane];
#pragma unroll
            for (int o2 = 16; o2 > 0; o2 >>= 1) acc += __shfl_xor_sync(FULLM, acc, o2);
            if (lane == 0) hs[row] = acc;
        }
    }
    __syncthreads();

    // stage 2: gl[w*32+o] = hs · Wout_row(w*32+o)
    {
        float hr[8];
        const float4* hp = (const float4*)hs + lane * 2;
        float4 h0 = hp[0], h1 = hp[1];
        hr[0]=h0.x; hr[1]=h0.y; hr[2]=h0.z; hr[3]=h0.w;
        hr[4]=h1.x; hr[5]=h1.y; hr[6]=h1.z; hr[7]=h1.w;
#pragma unroll 4
        for (int o = 0; o < 32; o++) {
            int row = w * 32 + o;
            const float4* wo4 = (const float4*)(Wout + (size_t)row * DD) + lane * 2;
            float4 v0 = wo4[0], v1 = wo4[1];
            float acc = hr[0]*v0.x + hr[1]*v0.y + hr[2]*v0.z + hr[3]*v0.w
                      + hr[4]*v1.x + hr[5]*v1.y + hr[6]*v1.z + hr[7]*v1.w;
#pragma unroll
            for (int o2 = 16; o2 > 0; o2 >>= 1) acc += __shfl_xor_sync(FULLM, acc, o2);
            if (lane == 0) gl[row] = acc;
        }
    }
    __syncthreads();

    // stage 3: g2[t] = gl · Wk2_col(t) (coalesced over t), gn small
    float a2 = 0.0f;
#pragma unroll 8
    for (int d = 0; d < DD; d++) a2 += gl[d] * Wk2[d * DD + t];
    g_g2[b * DD + t] = a2 * INV_SQRT_D;
    if (t < CNODE) {
        float a3 = 0.0f;
#pragma unroll 8
        for (int d = 0; d < DD; d++) a3 += gl[d] * Wn[(2 * DD + d) * CNODE + t];
        g_gn[b * CNODE + t] = a3 * INV_SQRT_D;
    }
}

// ---------------- K5a: split logits, 4 rows in flight per warp, packed dot ----------------
// grid (BS, SPLITL), block 256
__global__ __launch_bounds__(256) void k5a_logits(const float* __restrict__ enc,
                                                  const float* __restrict__ nf,
                                                  const void* __restrict__ maskp) {
    __shared__ __align__(16) float g2s[DD];
    __shared__ float gns[CNODE];
    __shared__ float tls[RSL];
    __shared__ float red[256];
    int b = blockIdx.x, s = blockIdx.y;
    int tid = threadIdx.x, wid = tid >> 5, lane = tid & 31;

    g2s[tid] = g_g2[b * DD + tid];
    if (tid < CNODE) gns[tid] = g_gn[b * CNODE + tid];
    int flags = g_flags;
    __syncthreads();

    const ulonglong2* cpa = (const ulonglong2*)(g2s + lane * 4);
    const ulonglong2* cpb = (const ulonglong2*)(g2s + 128 + lane * 4);
    ulonglong2 cA = cpa[0], cB = cpb[0];
    float gnl = (lane < CNODE) ? gns[lane] : 0.0f;

    int n0 = s * RSL;
    size_t rowb = (size_t)b * NN;
    // rows rr = wid + 8*i, i = 0..12; 4 rows in flight
    for (int base = 0; base < 13; base += 4) {
        float pv[4] = {0.f, 0.f, 0.f, 0.f};
        bool val[4];
#pragma unroll
        for (int j = 0; j < 4; j++) {
            int i = base + j;
            int rr = wid + 8 * i;
            val[j] = (i < 13) && (rr < RSL);
            if (val[j]) {
                const ulonglong2* ea2 = (const ulonglong2*)(enc + (rowb + n0 + rr) * DD + lane * 4);
                const ulonglong2* eb2 = (const ulonglong2*)(enc + (rowb + n0 + rr) * DD + 128 + lane * 4);
                ulonglong2 ea = ea2[0], eb = eb2[0];
                u64 a2 = mul2(ea.x, cA.x); a2 = fma2(ea.y, cA.y, a2);
                a2 = fma2(eb.x, cB.x, a2); a2 = fma2(eb.y, cB.y, a2);
                pv[j] = hsum2(a2);
                if (lane < CNODE) pv[j] += nf[(rowb + n0 + rr) * CNODE + lane] * gnl;
            }
        }
#pragma unroll
        for (int o = 16; o > 0; o >>= 1) {
            pv[0] += __shfl_xor_sync(FULLM, pv[0], o);
            pv[1] += __shfl_xor_sync(FULLM, pv[1], o);
            pv[2] += __shfl_xor_sync(FULLM, pv[2], o);
            pv[3] += __shfl_xor_sync(FULLM, pv[3], o);
        }
        if (lane == 0) {
#pragma unroll
            for (int j = 0; j < 4; j++) {
                if (val[j]) {
                    int rr = wid + 8 * (base + j);
                    bool msk = read_mask(maskp, flags, rowb + n0 + rr);
                    float v = msk ? -INFINITY : TANH_CLIP * tanhf(pv[j]);
                    g_tl[rowb + n0 + rr] = v;
                    tls[rr] = v;
                }
            }
        }
    }
    __syncthreads();

    float mx = -INFINITY;
    for (int r = tid; r < RSL; r += 256) mx = fmaxf(mx, tls[r]);
    red[tid] = mx;
    __syncthreads();
    for (int st = 128; st > 0; st >>= 1) {
        if (tid < st) red[tid] = fmaxf(red[tid], red[tid + st]);
        __syncthreads();
    }
    mx = red[0];
    __syncthreads();

    float sm = 0.0f;
    if (mx > -INFINITY) {
        for (int r = tid; r < RSL; r += 256) sm += __expf(tls[r] - mx);
    }
    red[tid] = sm;
    __syncthreads();
    for (int st = 128; st > 0; st >>= 1) {
        if (tid < st) red[tid] += red[tid + st];
        __syncthreads();
    }
    if (tid == 0) {
        g_pmax[b * SPLITL + s] = mx;
        g_psum[b * SPLITL + s] = (mx > -INFINITY) ? red[0] : 0.0f;
    }
}

// ---------------- K5b: tiny combine ----------------
__global__ void k5b_combine() {
    int b = blockIdx.x, t = threadIdx.x;
    float mx = (t < SPLITL) ? g_pmax[b * SPLITL + t] : -INFINITY;
#pragma unroll
    for (int o = 16; o > 0; o >>= 1) mx = fmaxf(mx, __shfl_xor_sync(FULLM, mx, o));
    float sm = 0.0f;
    if (t < SPLITL) {
        float pm = g_pmax[b * SPLITL + t];
        sm = (pm > -INFINITY) ? g_psum[b * SPLITL + t] * __expf(pm - mx) : 0.0f;
    }
#pragma unroll
    for (int o = 16; o > 0; o >>= 1) sm += __shfl_xor_sync(FULLM, sm, o);
    if (t == 0) { g_M[b] = mx; g_inv[b] = 1.0f / sm; }
}

// ---------------- K5c: normalize ----------------
__global__ __launch_bounds__(128) void k5c_norm(float* __restrict__ out) {
    int b = blockIdx.x, s = blockIdx.y, t = threadIdx.x;
    float M = g_M[b], inv = g_inv[b];
    int n0 = s * RSL;
    for (int r = t; r < RSL; r += 128) {
        size_t i = (size_t)b * NN + n0 + r;
        out[i] = __expf(g_tl[i] - M) * inv;
    }
}

// ---------------- launch ----------------
extern "C" void kernel_launch(void* const* d_in, const int* in_sizes, int n_in,
                              void* d_out, int out_size) {
    const float* shelf = (const float*)d_in[0];
    const float* enc   = (const float*)d_in[1];
    const float* ctx   = (const float*)d_in[2];
    const float* nf    = (const float*)d_in[3];
    const float* Wk    = (const float*)d_in[4];
    const float* Wv    = (const float*)d_in[5];
    const float* Wk2   = (const float*)d_in[6];
    const float* Wq    = (const float*)d_in[7];
    const float* Wout  = (const float*)d_in[8];
    const float* Wc    = (const float*)d_in[9];
    const float* Wg    = (const float*)d_in[10];
    const float* Wn    = (const float*)d_in[11];
    const int*   cur   = (const int*)d_in[12];
    const void*  maskp = (const void*)d_in[13];
    float* out = (float*)d_out;

    k00_zero<<<1, 32>>>();
    { dim3 g(BS, SPLIT1); k1_sum<<<g, 256>>>(enc, maskp); }
    k2_setup<<<BS, 256>>>(shelf, ctx, Wk, Wq, Wc, Wg, Wn, cur);
    { dim3 g(BS, SPLIT);  k3_attn<<<g, 256>>>(enc, nf); }
    { dim3 g(BS, HH);     k4a_combine<<<g, 256>>>(); }
    k4b_glimpse<<<BS, 256>>>(Wv, Wout, Wk2, Wn);
    { dim3 g(BS, SPLITL); k5a_logits<<<g, 256>>>(enc, nf, maskp); }
    k5b_combine<<<BS, 32>>>();
    { dim3 g(BS, SPLITL); k5c_norm<<<g, 128>>>(out); }
}

// round 8
// speedup vs baseline: 3.2079x; 1.0211x over previous
#include <cuda_runtime.h>
#include <cuda_bf16.h>
#include <math.h>
#include <stdint.h>

// Problem constants
#define BS 128
#define NN 2000
#define DD 256
#define HH 8
#define HDIM 32
#define CCTX 64
#define CNODE 8
#define TANH_CLIP 10.0f

#define SPLIT 20          // n-splits for k3
#define RS (NN / SPLIT)   // 100 rows per k3 block
#define TR 20             // tile rows in k3
#define NTILES (RS / TR)  // 5
#define RPW (TR / 4)      // 5 rows per warp per tile

#define SPLIT1 25          // n-splits for k1
#define RPB1 (NN / SPLIT1) // 80

#define SPLITL 20         // n-splits for k5
#define RSL (NN / SPLITL) // 100 rows per k5a block

#define INV_SQRT_HD 0.17677669529663687f   // 1/sqrt(32)
#define INV_SQRT_D  0.0625f                // 1/sqrt(256)

typedef unsigned long long u64;

// ---------------- scratch (16B aligned) ----------------
__device__ __align__(16) float g_sump[BS * SPLIT1 * DD];
__device__ __align__(16) float g_qk[BS * HH * DD];
__device__ __align__(16) float g_qn[BS * HH * CNODE];
__device__ __align__(16) float g_pm[BS * SPLIT * HH];
__device__ __align__(16) float g_pl[BS * SPLIT * HH];
__device__ __align__(16) float g_paw[BS * SPLIT * HH * DD];
__device__ __align__(16) float g_panf[BS * SPLIT * HH * CNODE];
__device__ __align__(16) float g_g2[BS * DD];
__device__ __align__(16) float g_gn[BS * CNODE];
__device__ __align__(16) float g_tl[BS * NN];
__device__ __align__(16) float g_pmax[BS * SPLITL];
__device__ __align__(16) float g_psum[BS * SPLITL];
__device__ int g_flags;   // zero-initialized at load; atomicOr idempotent across replays

// ---------------- helpers ----------------
__device__ __forceinline__ void cp_async16(void* sdst, const void* gsrc) {
    unsigned s = (unsigned)__cvta_generic_to_shared(sdst);
    asm volatile("cp.async.cg.shared.global [%0], [%1], 16;\n" :: "r"(s), "l"(gsrc) : "memory");
}
#define CP_COMMIT asm volatile("cp.async.commit_group;\n" ::: "memory")
#define CP_WAIT1  asm volatile("cp.async.wait_group 1;\n" ::: "memory")
#define CP_WAIT0  asm volatile("cp.async.wait_group 0;\n" ::: "memory")
#define FULLM 0xffffffffu

// packed fp32x2 (Blackwell FFMA2 — PTX-only path)
__device__ __forceinline__ u64 fma2(u64 a, u64 b, u64 c) {
    u64 d; asm("fma.rn.f32x2 %0, %1, %2, %3;" : "=l"(d) : "l"(a), "l"(b), "l"(c)); return d;
}
__device__ __forceinline__ u64 mul2(u64 a, u64 b) {
    u64 d; asm("mul.rn.f32x2 %0, %1, %2;" : "=l"(d) : "l"(a), "l"(b)); return d;
}
__device__ __forceinline__ u64 pk2(float lo, float hi) {
    u64 r; asm("mov.b64 %0, {%1, %2};" : "=l"(r) : "f"(lo), "f"(hi)); return r;
}
__device__ __forceinline__ float hsum2(u64 v) {
    float lo, hi; asm("mov.b64 {%0, %1}, %2;" : "=f"(lo), "=f"(hi) : "l"(v)); return lo + hi;
}

__device__ __forceinline__ bool read_mask(const void* mp, int flags, size_t i) {
    if (flags == 0) return false;
    if (flags & 2) {
        if (flags & 1) return ((const unsigned char*)mp)[i] != 0;  // bool
        return ((const float*)mp)[i] != 0.0f;                      // float32
    }
    return ((const int*)mp)[i] != 0;                               // int32
}

// ---------------- K1: per-split partial sums of enc + mask scan ----------------
// grid (BS, SPLIT1), block 256
__global__ __launch_bounds__(256) void k1_sum(const float* __restrict__ enc,
                                              const void* __restrict__ maskp) {
    __shared__ __align__(16) float4 sred[256];
    int b = blockIdx.x, s = blockIdx.y;
    int tid = threadIdx.x;
    int c4 = tid & 63;
    int rg = tid >> 6;

    const float4* base = (const float4*)(enc + ((size_t)b * NN + (size_t)s * RPB1) * DD) + c4;
    float4 acc = make_float4(0.f, 0.f, 0.f, 0.f);
#pragma unroll 5
    for (int r = rg; r < RPB1; r += 4) {
        float4 v = base[(size_t)r * 64];
        acc.x += v.x; acc.y += v.y; acc.z += v.z; acc.w += v.w;
    }
    sred[tid] = acc;
    __syncthreads();
    if (tid < 64) {
        float4 a = sred[tid], b1 = sred[tid + 64], c = sred[tid + 128], d = sred[tid + 192];
        float* dst = &g_sump[(b * SPLIT1 + s) * DD + c4 * 4];
        dst[0] = a.x + b1.x + c.x + d.x;
        dst[1] = a.y + b1.y + c.y + d.y;
        dst[2] = a.z + b1.z + c.z + d.z;
        dst[3] = a.w + b1.w + c.w + d.w;
    }

    // mask dtype detection (covers first BS*NN bytes, safe for all candidate dtypes)
    size_t idx = (size_t)(b * SPLIT1 + s) * 256 + tid;
    bool nz0 = false, nz1 = false;
    if (idx < (size_t)BS * NN) {
        unsigned char v = ((const unsigned char*)maskp)[idx];
        if (v) { if ((idx & 3) == 0) nz0 = true; else nz1 = true; }
    }
    unsigned b0 = __ballot_sync(FULLM, nz0);
    unsigned b1 = __ballot_sync(FULLM, nz1);
    if ((tid & 31) == 0) {
        int f = (b0 ? 1 : 0) | (b1 ? 2 : 0);
        if (f) atomicOr(&g_flags, f);
    }
}

// ---------------- K2: per-batch setup (coalesced warp-GEMV) ----------------
// grid BS, block 256
__global__ __launch_bounds__(256) void k2_setup(const float* __restrict__ shelf,
                                                const float* __restrict__ ctx,
                                                const float* __restrict__ Wk,
                                                const float* __restrict__ Wq,
                                                const float* __restrict__ Wc,
                                                const float* __restrict__ Wg,
                                                const float* __restrict__ Wn,
                                                const int* __restrict__ cur_node) {
    __shared__ __align__(16) float Xs[2 * DD];
    __shared__ __align__(16) float Qs[DD];
    __shared__ __align__(16) float ms[DD];
    int b = blockIdx.x, t = threadIdx.x;
    int w = t >> 5, lane = t & 31;

    int cn = cur_node[b];
    Xs[t] = shelf[((size_t)b * NN + cn) * DD + t];
    float a = 0.0f;
#pragma unroll 8
    for (int c = 0; c < CCTX; c++) a += ctx[b * CCTX + c] * Wc[t * CCTX + c];
    Xs[DD + t] = a;
    float smv = 0.0f;
#pragma unroll
    for (int s = 0; s < SPLIT1; s++) smv += g_sump[(b * SPLIT1 + s) * DD + t];
    ms[t] = smv * (1.0f / NN);
    __syncthreads();

    // warp-GEMV: warp w computes Qs[w*32 .. w*32+31], lanes split k (coalesced)
    {
        float msr[8];
        const float4* msp = (const float4*)ms + lane * 2;
        { float4 v0 = msp[0], v1 = msp[1];
          msr[0]=v0.x; msr[1]=v0.y; msr[2]=v0.z; msr[3]=v0.w;
          msr[4]=v1.x; msr[5]=v1.y; msr[6]=v1.z; msr[7]=v1.w; }
        float xr[16];
        const float4* xp = (const float4*)Xs + lane * 4;
#pragma unroll
        for (int j = 0; j < 4; j++) {
            float4 v = xp[j];
            xr[j*4+0]=v.x; xr[j*4+1]=v.y; xr[j*4+2]=v.z; xr[j*4+3]=v.w;
        }
#pragma unroll 4
        for (int o = 0; o < 32; o++) {
            int tt = w * 32 + o;
            const float4* wg4 = (const float4*)(Wg + (size_t)tt * DD) + lane * 2;
            const float4* wq4 = (const float4*)(Wq + (size_t)tt * 2 * DD) + lane * 4;
            float acc = 0.0f;
            float4 g0 = wg4[0], g1 = wg4[1];
            acc += msr[0]*g0.x + msr[1]*g0.y + msr[2]*g0.z + msr[3]*g0.w;
            acc += msr[4]*g1.x + msr[5]*g1.y + msr[6]*g1.z + msr[7]*g1.w;
#pragma unroll
            for (int j = 0; j < 4; j++) {
                float4 q4 = wq4[j];
                acc += xr[j*4+0]*q4.x + xr[j*4+1]*q4.y + xr[j*4+2]*q4.z + xr[j*4+3]*q4.w;
            }
#pragma unroll
            for (int o2 = 16; o2 > 0; o2 >>= 1) acc += __shfl_xor_sync(FULLM, acc, o2);
            if (lane == 0) Qs[tt] = acc;
        }
    }
    __syncthreads();

#pragma unroll
    for (int h = 0; h < HH; h++) {
        float a2 = 0.0f;
#pragma unroll 8
        for (int e = 0; e < HDIM; e++) a2 += Qs[h * HDIM + e] * Wk[(h * HDIM + e) * DD + t];
        g_qk[(b * HH + h) * DD + t] = a2 * INV_SQRT_HD;
    }
    if (t < HH * CNODE) {
        int h = t >> 3, c = t & 7;
        float a3 = 0.0f;
#pragma unroll 8
        for (int e = 0; e < HDIM; e++) a3 += Qs[h * HDIM + e] * Wn[(h * HDIM + e) * CNODE + c];
        g_qn[(b * HH + h) * CNODE + c] = a3 * INV_SQRT_HD;
    }
}

// ---------------- K3: split flash glimpse, per-tile rescale ----------------
// grid (BS, SPLIT), block 256
__global__ __launch_bounds__(256, 2) void k3_attn(const float* __restrict__ enc,
                                                  const float* __restrict__ nf) {
    __shared__ __align__(16) float encS[2][TR * DD];   // 40 KB, aliased for combine
    __shared__ __align__(16) float nfS[2][TR * CNODE];
    __shared__ float cM[8][4], cL[8][4];
    __shared__ float cANF[8][4][CNODE];

    int b = blockIdx.x, s = blockIdx.y;
    int tid = threadIdx.x, w = tid >> 5, lane = tid & 31;
    int g = w >> 2, rl = w & 3;
    size_t row0 = (size_t)b * NN + (size_t)s * RS;

    u64 qp[4][4];
#pragma unroll
    for (int hl = 0; hl < 4; hl++) {
        const ulonglong2* qq = (const ulonglong2*)(g_qk + ((size_t)(b * HH + g * 4 + hl)) * DD + lane * 8);
        ulonglong2 qa = qq[0], qb = qq[1];
        qp[hl][0] = qa.x; qp[hl][1] = qa.y; qp[hl][2] = qb.x; qp[hl][3] = qb.y;
    }
    float qnr[4];
#pragma unroll
    for (int hl = 0; hl < 4; hl++)
        qnr[hl] = (lane < CNODE) ? g_qn[(b * HH + g * 4 + hl) * CNODE + lane] : 0.0f;

    u64 aw[4][4];
#pragma unroll
    for (int hl = 0; hl < 4; hl++)
#pragma unroll
        for (int j = 0; j < 4; j++) aw[hl][j] = 0ull;
    float anf[4] = {0.f, 0.f, 0.f, 0.f};
    float m = -INFINITY, l = 0.0f;   // per-lane state for head (lane&3)

    // prologue: tile 0
    {
        const float* src = enc + row0 * DD;
#pragma unroll
        for (int i = 0; i < 5; i++) { int off = (tid + i * 256) * 4; cp_async16(&encS[0][off], src + off); }
        if (tid < TR * CNODE / 4) cp_async16(&nfS[0][tid * 4], nf + row0 * CNODE + tid * 4);
        CP_COMMIT;
    }

    for (int t = 0; t < NTILES; t++) {
        int buf = t & 1;
        if (t + 1 < NTILES) {
            const float* src = enc + (row0 + (size_t)(t + 1) * TR) * DD;
#pragma unroll
            for (int i = 0; i < 5; i++) { int off = (tid + i * 256) * 4; cp_async16(&encS[buf ^ 1][off], src + off); }
            if (tid < TR * CNODE / 4)
                cp_async16(&nfS[buf ^ 1][tid * 4], nf + (row0 + (size_t)(t + 1) * TR) * CNODE + tid * 4);
            CP_COMMIT;
            CP_WAIT1;
        } else {
            CP_WAIT0;
        }
        __syncthreads();

        // ---- phase 1: per-row dot + fold -> pk[] ----
        float pk[RPW];
#pragma unroll
        for (int k = 0; k < RPW; k++) {
            int r = rl + 4 * k;
            const ulonglong2* e2 = (const ulonglong2*)(&encS[buf][r * DD + lane * 8]);
            ulonglong2 eA = e2[0], eB = e2[1];
            float nfv = (lane < CNODE) ? nfS[buf][r * CNODE + lane] : 0.0f;
            float sacc[4];
#pragma unroll
            for (int hl = 0; hl < 4; hl++) {
                u64 acc2 = mul2(eA.x, qp[hl][0]);
                acc2 = fma2(eA.y, qp[hl][1], acc2);
                acc2 = fma2(eB.x, qp[hl][2], acc2);
                acc2 = fma2(eB.y, qp[hl][3], acc2);
                sacc[hl] = hsum2(acc2) + nfv * qnr[hl];
            }
            float v01 = (lane & 1) ? sacc[1] : sacc[0];
            float o01 = (lane & 1) ? sacc[0] : sacc[1];
            v01 += __shfl_xor_sync(FULLM, o01, 1);
            float v23 = (lane & 1) ? sacc[3] : sacc[2];
            float o23 = (lane & 1) ? sacc[2] : sacc[3];
            v23 += __shfl_xor_sync(FULLM, o23, 1);
            float vv = (lane & 2) ? v23 : v01;
            float oo = (lane & 2) ? v01 : v23;
            vv += __shfl_xor_sync(FULLM, oo, 2);
            vv += __shfl_xor_sync(FULLM, vv, 4);
            vv += __shfl_xor_sync(FULLM, vv, 8);
            vv += __shfl_xor_sync(FULLM, vv, 16);
            pk[k] = vv;     // p for head (lane&3), row rl+4k
        }

        // ---- phase 2: one rescale per tile ----
        float tmax = pk[0];
#pragma unroll
        for (int k = 1; k < RPW; k++) tmax = fmaxf(tmax, pk[k]);
        float mn = fmaxf(m, tmax);
        float c = __expf(m - mn);
        m = mn;
        l *= c;
        {
            float cc0 = __shfl_sync(FULLM, c, 0);
            float cc1 = __shfl_sync(FULLM, c, 1);
            float cc2 = __shfl_sync(FULLM, c, 2);
            float cc3 = __shfl_sync(FULLM, c, 3);
            u64 cp0 = pk2(cc0, cc0), cp1 = pk2(cc1, cc1);
            u64 cp2 = pk2(cc2, cc2), cp3 = pk2(cc3, cc3);
#pragma unroll
            for (int j = 0; j < 4; j++) {
                aw[0][j] = mul2(aw[0][j], cp0);
                aw[1][j] = mul2(aw[1][j], cp1);
                aw[2][j] = mul2(aw[2][j], cp2);
                aw[3][j] = mul2(aw[3][j], cp3);
            }
            anf[0] *= cc0; anf[1] *= cc1; anf[2] *= cc2; anf[3] *= cc3;
        }

        // ---- phase 3: accumulate rows ----
#pragma unroll
        for (int k = 0; k < RPW; k++) {
            int r = rl + 4 * k;
            float wv = __expf(pk[k] - m);
            l += wv;
            float w0 = __shfl_sync(FULLM, wv, 0);
            float w1 = __shfl_sync(FULLM, wv, 1);
            float w2 = __shfl_sync(FULLM, wv, 2);
            float w3 = __shfl_sync(FULLM, wv, 3);
            const ulonglong2* e2 = (const ulonglong2*)(&encS[buf][r * DD + lane * 8]);
            ulonglong2 eA = e2[0], eB = e2[1];
            float nfv = (lane < CNODE) ? nfS[buf][r * CNODE + lane] : 0.0f;
            u64 wp0 = pk2(w0, w0), wp1 = pk2(w1, w1), wp2 = pk2(w2, w2), wp3 = pk2(w3, w3);
            aw[0][0] = fma2(eA.x, wp0, aw[0][0]); aw[0][1] = fma2(eA.y, wp0, aw[0][1]);
            aw[0][2] = fma2(eB.x, wp0, aw[0][2]); aw[0][3] = fma2(eB.y, wp0, aw[0][3]);
            aw[1][0] = fma2(eA.x, wp1, aw[1][0]); aw[1][1] = fma2(eA.y, wp1, aw[1][1]);
            aw[1][2] = fma2(eB.x, wp1, aw[1][2]); aw[1][3] = fma2(eB.y, wp1, aw[1][3]);
            aw[2][0] = fma2(eA.x, wp2, aw[2][0]); aw[2][1] = fma2(eA.y, wp2, aw[2][1]);
            aw[2][2] = fma2(eB.x, wp2, aw[2][2]); aw[2][3] = fma2(eB.y, wp2, aw[2][3]);
            aw[3][0] = fma2(eA.x, wp3, aw[3][0]); aw[3][1] = fma2(eA.y, wp3, aw[3][1]);
            aw[3][2] = fma2(eB.x, wp3, aw[3][2]); aw[3][3] = fma2(eB.y, wp3, aw[3][3]);
            anf[0] += w0 * nfv; anf[1] += w1 * nfv; anf[2] += w2 * nfv; anf[3] += w3 * nfv;
        }
        __syncthreads();
    }

    // ---- block combine: 4 row-warps per head-group -> split partials ----
    u64* cAW = (u64*)encS;
    if (lane < 4) { cM[w][lane] = m; cL[w][lane] = l; }
#pragma unroll
    for (int hl = 0; hl < 4; hl++) {
#pragma unroll
        for (int j = 0; j < 4; j++) cAW[(w * 4 + hl) * (DD / 2) + lane * 4 + j] = aw[hl][j];
    }
    if (lane < CNODE) {
#pragma unroll
        for (int hl = 0; hl < 4; hl++) cANF[w][hl][lane] = anf[hl];
    }
    __syncthreads();

    {
        int h = w, g2 = h >> 2, hl2 = h & 3;
        float M = -INFINITY;
#pragma unroll
        for (int rw = 0; rw < 4; rw++) M = fmaxf(M, cM[g2 * 4 + rw][hl2]);
        float es[4], L = 0.0f;
#pragma unroll
        for (int rw = 0; rw < 4; rw++) {
            es[rw] = __expf(cM[g2 * 4 + rw][hl2] - M);
            L += cL[g2 * 4 + rw][hl2] * es[rw];
        }
        int pidx = (b * SPLIT + s) * HH + h;
        u64* dst = (u64*)g_paw + (size_t)pidx * (DD / 2) + lane * 4;
        u64 ep[4];
#pragma unroll
        for (int rw = 0; rw < 4; rw++) ep[rw] = pk2(es[rw], es[rw]);
#pragma unroll
        for (int j = 0; j < 4; j++) {
            u64 acc = 0ull;
#pragma unroll
            for (int rw = 0; rw < 4; rw++)
                acc = fma2(cAW[((g2 * 4 + rw) * 4 + hl2) * (DD / 2) + lane * 4 + j], ep[rw], acc);
            dst[j] = acc;
        }
        if (lane == 0) { g_pm[pidx] = M; g_pl[pidx] = L; }
        if (lane < CNODE) {
            float acc = 0.0f;
#pragma unroll
            for (int rw = 0; rw < 4; rw++) acc += es[rw] * cANF[g2 * 4 + rw][hl2][lane];
            g_panf[pidx * CNODE + lane] = acc;
        }
    }
}

// ---------------- K4: fused split-combine + glimpse + g2/gn ----------------
// grid BS, block 256 (warp w owns head w for combine + stage 1)
__global__ __launch_bounds__(256) void k4_glimpse(const float* __restrict__ Wv,
                                                  const float* __restrict__ Wout,
                                                  const float* __restrict__ Wk2,
                                                  const float* __restrict__ Wn) {
    __shared__ __align__(16) float esS[HH][SPLIT];    // es * invL
    __shared__ __align__(16) u64 sAW[HH * DD / 2];    // combined normalized aw (8 KB)
    __shared__ __align__(16) float sANF[HH][CNODE];
    __shared__ __align__(16) float hs[DD];
    __shared__ __align__(16) float gl[DD];
    int b = blockIdx.x, t = threadIdx.x;
    int w = t >> 5, lane = t & 31;

    // stage 0: per-head softmax-stat combine (warp w = head w)
    {
        float pmv = (lane < SPLIT) ? g_pm[(b * SPLIT + lane) * HH + w] : -INFINITY;
        float plv = (lane < SPLIT) ? g_pl[(b * SPLIT + lane) * HH + w] : 0.0f;
        float M = pmv;
#pragma unroll
        for (int o = 16; o > 0; o >>= 1) M = fmaxf(M, __shfl_xor_sync(FULLM, M, o));
        float e = (lane < SPLIT) ? __expf(pmv - M) : 0.0f;
        float Lp = plv * e;
#pragma unroll
        for (int o = 16; o > 0; o >>= 1) Lp += __shfl_xor_sync(FULLM, Lp, o);
        float invL = 1.0f / Lp;
        if (lane < SPLIT) esS[w][lane] = e * invL;
    }
    __syncthreads();

    // stage 0b: combine aw (warp w = head w), packed
    {
        ulonglong2 acc0 = make_ulonglong2(0ull, 0ull);
        ulonglong2 acc1 = make_ulonglong2(0ull, 0ull);
#pragma unroll 4
        for (int s = 0; s < SPLIT; s++) {
            float es = esS[w][s];
            u64 ep = pk2(es, es);
            const ulonglong2* src = (const ulonglong2*)(g_paw + (size_t)((b * SPLIT + s) * HH + w) * DD + lane * 8);
            ulonglong2 v0 = src[0], v1 = src[1];
            acc0.x = fma2(v0.x, ep, acc0.x); acc0.y = fma2(v0.y, ep, acc0.y);
            acc1.x = fma2(v1.x, ep, acc1.x); acc1.y = fma2(v1.y, ep, acc1.y);
        }
        u64* dst = &sAW[w * (DD / 2) + lane * 4];
        dst[0] = acc0.x; dst[1] = acc0.y; dst[2] = acc1.x; dst[3] = acc1.y;
        if (lane < CNODE) {
            float acc = 0.0f;
#pragma unroll
            for (int s = 0; s < SPLIT; s++)
                acc += esS[w][s] * g_panf[((b * SPLIT + s) * HH + w) * CNODE + lane];
            sANF[w][lane] = acc;
        }
    }
    __syncthreads();

    // stage 1: hs[w*32+o] = aw[head w]·Wv_row(o) + anf·Wn_v_row(o)
    {
        float awr[8];
        const float4* ap = (const float4*)(&sAW[w * (DD / 2)]) + lane * 2;
        float4 a0 = ap[0], a1 = ap[1];
        awr[0]=a0.x; awr[1]=a0.y; awr[2]=a0.z; awr[3]=a0.w;
        awr[4]=a1.x; awr[5]=a1.y; awr[6]=a1.z; awr[7]=a1.w;
        float anfr = (lane < CNODE) ? sANF[w][lane] : 0.0f;
#pragma unroll 4
        for (int o = 0; o < 32; o++) {
            int row = w * HDIM + o;
            const float4* wv4 = (const float4*)(Wv + (size_t)row * DD) + lane * 2;
            float4 v0 = wv4[0], v1 = wv4[1];
            float acc = awr[0]*v0.x + awr[1]*v0.y + awr[2]*v0.z + awr[3]*v0.w
                      + awr[4]*v1.x + awr[5]*v1.y + awr[6]*v1.z + awr[7]*v1.w;
            if (lane < CNODE) acc += anfr * Wn[(DD + row) * CNODE + lane];
#pragma unroll
            for (int o2 = 16; o2 > 0; o2 >>= 1) acc += __shfl_xor_sync(FULLM, acc, o2);
            if (lane == 0) hs[row] = acc;
        }
    }
    __syncthreads();

    // stage 2: gl = hs @ Wout^T (warp-GEMV)
    {
        float hr[8];
        const float4* hp = (const float4*)hs + lane * 2;
        float4 h0 = hp[0], h1 = hp[1];
        hr[0]=h0.x; hr[1]=h0.y; hr[2]=h0.z; hr[3]=h0.w;
        hr[4]=h1.x; hr[5]=h1.y; hr[6]=h1.z; hr[7]=h1.w;
#pragma unroll 4
        for (int o = 0; o < 32; o++) {
            int row = w * 32 + o;
            const float4* wo4 = (const float4*)(Wout + (size_t)row * DD) + lane * 2;
            float4 v0 = wo4[0], v1 = wo4[1];
            float acc = hr[0]*v0.x + hr[1]*v0.y + hr[2]*v0.z + hr[3]*v0.w
                      + hr[4]*v1.x + hr[5]*v1.y + hr[6]*v1.z + hr[7]*v1.w;
#pragma unroll
            for (int o2 = 16; o2 > 0; o2 >>= 1) acc += __shfl_xor_sync(FULLM, acc, o2);
            if (lane == 0) gl[row] = acc;
        }
    }
    __syncthreads();

    // stage 3: g2[t] = gl · Wk2_col(t), gn small
    float a2 = 0.0f;
#pragma unroll 8
    for (int d = 0; d < DD; d++) a2 += gl[d] * Wk2[d * DD + t];
    g_g2[b * DD + t] = a2 * INV_SQRT_D;
    if (t < CNODE) {
        float a3 = 0.0f;
#pragma unroll 8
        for (int d = 0; d < DD; d++) a3 += gl[d] * Wn[(2 * DD + d) * CNODE + t];
        g_gn[b * CNODE + t] = a3 * INV_SQRT_D;
    }
}

// ---------------- K5a: split logits, 4 rows in flight per warp, packed dot ----------------
// grid (BS, SPLITL), block 256
__global__ __launch_bounds__(256) void k5a_logits(const float* __restrict__ enc,
                                                  const float* __restrict__ nf,
                                                  const void* __restrict__ maskp) {
    __shared__ __align__(16) float g2s[DD];
    __shared__ float gns[CNODE];
    __shared__ float tls[RSL];
    __shared__ float red[256];
    int b = blockIdx.x, s = blockIdx.y;
    int tid = threadIdx.x, wid = tid >> 5, lane = tid & 31;

    g2s[tid] = g_g2[b * DD + tid];
    if (tid < CNODE) gns[tid] = g_gn[b * CNODE + tid];
    int flags = g_flags;
    __syncthreads();

    const ulonglong2* cpa = (const ulonglong2*)(g2s + lane * 4);
    const ulonglong2* cpb = (const ulonglong2*)(g2s + 128 + lane * 4);
    ulonglong2 cA = cpa[0], cB = cpb[0];
    float gnl = (lane < CNODE) ? gns[lane] : 0.0f;

    int n0 = s * RSL;
    size_t rowb = (size_t)b * NN;
    for (int base = 0; base < 13; base += 4) {
        float pv[4] = {0.f, 0.f, 0.f, 0.f};
        bool val[4];
#pragma unroll
        for (int j = 0; j < 4; j++) {
            int i = base + j;
            int rr = wid + 8 * i;
            val[j] = (i < 13) && (rr < RSL);
            if (val[j]) {
                const ulonglong2* ea2 = (const ulonglong2*)(enc + (rowb + n0 + rr) * DD + lane * 4);
                const ulonglong2* eb2 = (const ulonglong2*)(enc + (rowb + n0 + rr) * DD + 128 + lane * 4);
                ulonglong2 ea = ea2[0], eb = eb2[0];
                u64 a2 = mul2(ea.x, cA.x); a2 = fma2(ea.y, cA.y, a2);
                a2 = fma2(eb.x, cB.x, a2); a2 = fma2(eb.y, cB.y, a2);
                pv[j] = hsum2(a2);
                if (lane < CNODE) pv[j] += nf[(rowb + n0 + rr) * CNODE + lane] * gnl;
            }
        }
#pragma unroll
        for (int o = 16; o > 0; o >>= 1) {
            pv[0] += __shfl_xor_sync(FULLM, pv[0], o);
            pv[1] += __shfl_xor_sync(FULLM, pv[1], o);
            pv[2] += __shfl_xor_sync(FULLM, pv[2], o);
            pv[3] += __shfl_xor_sync(FULLM, pv[3], o);
        }
        if (lane == 0) {
#pragma unroll
            for (int j = 0; j < 4; j++) {
                if (val[j]) {
                    int rr = wid + 8 * (base + j);
                    bool msk = read_mask(maskp, flags, rowb + n0 + rr);
                    float v = msk ? -INFINITY : TANH_CLIP * tanhf(pv[j]);
                    g_tl[rowb + n0 + rr] = v;
                    tls[rr] = v;
                }
            }
        }
    }
    __syncthreads();

    float mx = -INFINITY;
    for (int r = tid; r < RSL; r += 256) mx = fmaxf(mx, tls[r]);
    red[tid] = mx;
    __syncthreads();
    for (int st = 128; st > 0; st >>= 1) {
        if (tid < st) red[tid] = fmaxf(red[tid], red[tid + st]);
        __syncthreads();
    }
    mx = red[0];
    __syncthreads();

    float sm = 0.0f;
    if (mx > -INFINITY) {
        for (int r = tid; r < RSL; r += 256) sm += __expf(tls[r] - mx);
    }
    red[tid] = sm;
    __syncthreads();
    for (int st = 128; st > 0; st >>= 1) {
        if (tid < st) red[tid] += red[tid + st];
        __syncthreads();
    }
    if (tid == 0) {
        g_pmax[b * SPLITL + s] = mx;
        g_psum[b * SPLITL + s] = (mx > -INFINITY) ? red[0] : 0.0f;
    }
}

// ---------------- K5c: fused combine + normalize ----------------
// grid (BS, SPLITL), block 128
__global__ __launch_bounds__(128) void k5c_norm(float* __restrict__ out) {
    __shared__ float sM, sInv;
    int b = blockIdx.x, s = blockIdx.y, t = threadIdx.x;
    if (t < 32) {
        float mx = (t < SPLITL) ? g_pmax[b * SPLITL + t] : -INFINITY;
#pragma unroll
        for (int o = 16; o > 0; o >>= 1) mx = fmaxf(mx, __shfl_xor_sync(FULLM, mx, o));
        float sm = 0.0f;
        if (t < SPLITL) {
            float pm = g_pmax[b * SPLITL + t];
            sm = (pm > -INFINITY) ? g_psum[b * SPLITL + t] * __expf(pm - mx) : 0.0f;
        }
#pragma unroll
        for (int o = 16; o > 0; o >>= 1) sm += __shfl_xor_sync(FULLM, sm, o);
        if (t == 0) { sM = mx; sInv = 1.0f / sm; }
    }
    __syncthreads();
    float M = sM, inv = sInv;
    int n0 = s * RSL;
    for (int r = t; r < RSL; r += 128) {
        size_t i = (size_t)b * NN + n0 + r;
        out[i] = __expf(g_tl[i] - M) * inv;
    }
}

// ---------------- launch ----------------
extern "C" void kernel_launch(void* const* d_in, const int* in_sizes, int n_in,
                              void* d_out, int out_size) {
    const float* shelf = (const float*)d_in[0];
    const float* enc   = (const float*)d_in[1];
    const float* ctx   = (const float*)d_in[2];
    const float* nf    = (const float*)d_in[3];
    const float* Wk    = (const float*)d_in[4];
    const float* Wv    = (const float*)d_in[5];
    const float* Wk2   = (const float*)d_in[6];
    const float* Wq    = (const float*)d_in[7];
    const float* Wout  = (const float*)d_in[8];
    const float* Wc    = (const float*)d_in[9];
    const float* Wg    = (const float*)d_in[10];
    const float* Wn    = (const float*)d_in[11];
    const int*   cur   = (const int*)d_in[12];
    const void*  maskp = (const void*)d_in[13];
    float* out = (float*)d_out;

    { dim3 g(BS, SPLIT1); k1_sum<<<g, 256>>>(enc, maskp); }
    k2_setup<<<BS, 256>>>(shelf, ctx, Wk, Wq, Wc, Wg, Wn, cur);
    { dim3 g(BS, SPLIT);  k3_attn<<<g, 256>>>(enc, nf); }
    k4_glimpse<<<BS, 256>>>(Wv, Wout, Wk2, Wn);
    { dim3 g(BS, SPLITL); k5a_logits<<<g, 256>>>(enc, nf, maskp); }
    { dim3 g(BS, SPLITL); k5c_norm<<<g, 128>>>(out); }
}

// round 9
// speedup vs baseline: 3.2266x; 1.0058x over previous
#include <cuda_runtime.h>
#include <cuda_bf16.h>
#include <math.h>
#include <stdint.h>

// Problem constants
#define BS 128
#define NN 2000
#define DD 256
#define HH 8
#define HDIM 32
#define CCTX 64
#define CNODE 8
#define TANH_CLIP 10.0f

#define SPLIT 20          // n-splits for k3
#define RS (NN / SPLIT)   // 100 rows per k3 block
#define TR 20             // tile rows in k3
#define NTILES (RS / TR)  // 5
#define RPW (TR / 4)      // 5 rows per warp per tile

#define SPLIT1 25          // n-splits for k1
#define RPB1 (NN / SPLIT1) // 80

#define SPLITL 20         // n-splits for k5
#define RSL (NN / SPLITL) // 100 rows per k5a block

#define INV_SQRT_HD 0.17677669529663687f   // 1/sqrt(32)
#define INV_SQRT_D  0.0625f                // 1/sqrt(256)

typedef unsigned long long u64;

// ---------------- scratch (16B aligned) ----------------
__device__ __align__(16) float g_sump[BS * SPLIT1 * DD];
__device__ __align__(16) float g_qk[BS * HH * DD];
__device__ __align__(16) float g_qn[BS * HH * CNODE];
__device__ __align__(16) float g_pm[BS * SPLIT * HH];
__device__ __align__(16) float g_pl[BS * SPLIT * HH];
__device__ __align__(16) float g_paw[BS * SPLIT * HH * DD];
__device__ __align__(16) float g_panf[BS * SPLIT * HH * CNODE];
__device__ __align__(16) float g_aw[BS * HH * DD];
__device__ __align__(16) float g_anfc[BS * HH * CNODE];
__device__ __align__(16) float g_g2[BS * DD];
__device__ __align__(16) float g_gn[BS * CNODE];
__device__ __align__(16) float g_tl[BS * NN];
__device__ __align__(16) float g_pmax[BS * SPLITL];
__device__ __align__(16) float g_psum[BS * SPLITL];
__device__ int g_flags;   // zero-initialized at load; atomicOr idempotent across replays

// ---------------- helpers ----------------
__device__ __forceinline__ void cp_async16(void* sdst, const void* gsrc) {
    unsigned s = (unsigned)__cvta_generic_to_shared(sdst);
    asm volatile("cp.async.cg.shared.global [%0], [%1], 16;\n" :: "r"(s), "l"(gsrc) : "memory");
}
#define CP_COMMIT asm volatile("cp.async.commit_group;\n" ::: "memory")
#define CP_WAIT1  asm volatile("cp.async.wait_group 1;\n" ::: "memory")
#define CP_WAIT0  asm volatile("cp.async.wait_group 0;\n" ::: "memory")
#define FULLM 0xffffffffu

// packed fp32x2 (Blackwell FFMA2 — PTX-only path)
__device__ __forceinline__ u64 fma2(u64 a, u64 b, u64 c) {
    u64 d; asm("fma.rn.f32x2 %0, %1, %2, %3;" : "=l"(d) : "l"(a), "l"(b), "l"(c)); return d;
}
__device__ __forceinline__ u64 mul2(u64 a, u64 b) {
    u64 d; asm("mul.rn.f32x2 %0, %1, %2;" : "=l"(d) : "l"(a), "l"(b)); return d;
}
__device__ __forceinline__ u64 pk2(float lo, float hi) {
    u64 r; asm("mov.b64 %0, {%1, %2};" : "=l"(r) : "f"(lo), "f"(hi)); return r;
}
__device__ __forceinline__ float hsum2(u64 v) {
    float lo, hi; asm("mov.b64 {%0, %1}, %2;" : "=f"(lo), "=f"(hi) : "l"(v)); return lo + hi;
}

__device__ __forceinline__ bool read_mask(const void* mp, int flags, size_t i) {
    if (flags == 0) return false;
    if (flags & 2) {
        if (flags & 1) return ((const unsigned char*)mp)[i] != 0;  // bool
        return ((const float*)mp)[i] != 0.0f;                      // float32
    }
    return ((const int*)mp)[i] != 0;                               // int32
}

// ---------------- K1: per-split partial sums of enc + mask scan ----------------
// grid (BS, SPLIT1), block 256
__global__ __launch_bounds__(256) void k1_sum(const float* __restrict__ enc,
                                              const void* __restrict__ maskp) {
    __shared__ __align__(16) float4 sred[256];
    int b = blockIdx.x, s = blockIdx.y;
    int tid = threadIdx.x;
    int c4 = tid & 63;
    int rg = tid >> 6;

    const float4* base = (const float4*)(enc + ((size_t)b * NN + (size_t)s * RPB1) * DD) + c4;
    float4 acc = make_float4(0.f, 0.f, 0.f, 0.f);
#pragma unroll 5
    for (int r = rg; r < RPB1; r += 4) {
        float4 v = base[(size_t)r * 64];
        acc.x += v.x; acc.y += v.y; acc.z += v.z; acc.w += v.w;
    }
    sred[tid] = acc;
    __syncthreads();
    if (tid < 64) {
        float4 a = sred[tid], b1 = sred[tid + 64], c = sred[tid + 128], d = sred[tid + 192];
        float* dst = &g_sump[(b * SPLIT1 + s) * DD + c4 * 4];
        dst[0] = a.x + b1.x + c.x + d.x;
        dst[1] = a.y + b1.y + c.y + d.y;
        dst[2] = a.z + b1.z + c.z + d.z;
        dst[3] = a.w + b1.w + c.w + d.w;
    }

    // mask dtype detection
    size_t idx = (size_t)(b * SPLIT1 + s) * 256 + tid;
    bool nz0 = false, nz1 = false;
    if (idx < (size_t)BS * NN) {
        unsigned char v = ((const unsigned char*)maskp)[idx];
        if (v) { if ((idx & 3) == 0) nz0 = true; else nz1 = true; }
    }
    unsigned b0 = __ballot_sync(FULLM, nz0);
    unsigned b1 = __ballot_sync(FULLM, nz1);
    if ((tid & 31) == 0) {
        int f = (b0 ? 1 : 0) | (b1 ? 2 : 0);
        if (f) atomicOr(&g_flags, f);
    }
}

// ---------------- K2: per-batch setup (coalesced warp-GEMV) ----------------
// grid BS, block 256
__global__ __launch_bounds__(256) void k2_setup(const float* __restrict__ shelf,
                                                const float* __restrict__ ctx,
                                                const float* __restrict__ Wk,
                                                const float* __restrict__ Wq,
                                                const float* __restrict__ Wc,
                                                const float* __restrict__ Wg,
                                                const float* __restrict__ Wn,
                                                const int* __restrict__ cur_node) {
    __shared__ __align__(16) float Xs[2 * DD];
    __shared__ __align__(16) float Qs[DD];
    __shared__ __align__(16) float ms[DD];
    int b = blockIdx.x, t = threadIdx.x;
    int w = t >> 5, lane = t & 31;

    int cn = cur_node[b];
    Xs[t] = shelf[((size_t)b * NN + cn) * DD + t];
    float a = 0.0f;
#pragma unroll 8
    for (int c = 0; c < CCTX; c++) a += ctx[b * CCTX + c] * Wc[t * CCTX + c];
    Xs[DD + t] = a;
    float smv = 0.0f;
#pragma unroll
    for (int s = 0; s < SPLIT1; s++) smv += g_sump[(b * SPLIT1 + s) * DD + t];
    ms[t] = smv * (1.0f / NN);
    __syncthreads();

    {
        float msr[8];
        const float4* msp = (const float4*)ms + lane * 2;
        { float4 v0 = msp[0], v1 = msp[1];
          msr[0]=v0.x; msr[1]=v0.y; msr[2]=v0.z; msr[3]=v0.w;
          msr[4]=v1.x; msr[5]=v1.y; msr[6]=v1.z; msr[7]=v1.w; }
        float xr[16];
        const float4* xp = (const float4*)Xs + lane * 4;
#pragma unroll
        for (int j = 0; j < 4; j++) {
            float4 v = xp[j];
            xr[j*4+0]=v.x; xr[j*4+1]=v.y; xr[j*4+2]=v.z; xr[j*4+3]=v.w;
        }
#pragma unroll 4
        for (int o = 0; o < 32; o++) {
            int tt = w * 32 + o;
            const float4* wg4 = (const float4*)(Wg + (size_t)tt * DD) + lane * 2;
            const float4* wq4 = (const float4*)(Wq + (size_t)tt * 2 * DD) + lane * 4;
            float acc = 0.0f;
            float4 g0 = wg4[0], g1 = wg4[1];
            acc += msr[0]*g0.x + msr[1]*g0.y + msr[2]*g0.z + msr[3]*g0.w;
            acc += msr[4]*g1.x + msr[5]*g1.y + msr[6]*g1.z + msr[7]*g1.w;
#pragma unroll
            for (int j = 0; j < 4; j++) {
                float4 q4 = wq4[j];
                acc += xr[j*4+0]*q4.x + xr[j*4+1]*q4.y + xr[j*4+2]*q4.z + xr[j*4+3]*q4.w;
            }
#pragma unroll
            for (int o2 = 16; o2 > 0; o2 >>= 1) acc += __shfl_xor_sync(FULLM, acc, o2);
            if (lane == 0) Qs[tt] = acc;
        }
    }
    __syncthreads();

#pragma unroll
    for (int h = 0; h < HH; h++) {
        float a2 = 0.0f;
#pragma unroll 8
        for (int e = 0; e < HDIM; e++) a2 += Qs[h * HDIM + e] * Wk[(h * HDIM + e) * DD + t];
        g_qk[(b * HH + h) * DD + t] = a2 * INV_SQRT_HD;
    }
    if (t < HH * CNODE) {
        int h = t >> 3, c = t & 7;
        float a3 = 0.0f;
#pragma unroll 8
        for (int e = 0; e < HDIM; e++) a3 += Qs[h * HDIM + e] * Wn[(h * HDIM + e) * CNODE + c];
        g_qn[(b * HH + h) * CNODE + c] = a3 * INV_SQRT_HD;
    }
}

// ---------------- K3: split flash glimpse, per-tile rescale ----------------
// grid (BS, SPLIT), block 256
__global__ __launch_bounds__(256, 2) void k3_attn(const float* __restrict__ enc,
                                                  const float* __restrict__ nf) {
    __shared__ __align__(16) float encS[2][TR * DD];   // 40 KB, aliased for combine
    __shared__ __align__(16) float nfS[2][TR * CNODE];
    __shared__ float cM[8][4], cL[8][4];
    __shared__ float cANF[8][4][CNODE];

    int b = blockIdx.x, s = blockIdx.y;
    int tid = threadIdx.x, w = tid >> 5, lane = tid & 31;
    int g = w >> 2, rl = w & 3;
    size_t row0 = (size_t)b * NN + (size_t)s * RS;

    u64 qp[4][4];
#pragma unroll
    for (int hl = 0; hl < 4; hl++) {
        const ulonglong2* qq = (const ulonglong2*)(g_qk + ((size_t)(b * HH + g * 4 + hl)) * DD + lane * 8);
        ulonglong2 qa = qq[0], qb = qq[1];
        qp[hl][0] = qa.x; qp[hl][1] = qa.y; qp[hl][2] = qb.x; qp[hl][3] = qb.y;
    }
    float qnr[4];
#pragma unroll
    for (int hl = 0; hl < 4; hl++)
        qnr[hl] = (lane < CNODE) ? g_qn[(b * HH + g * 4 + hl) * CNODE + lane] : 0.0f;

    u64 aw[4][4];
#pragma unroll
    for (int hl = 0; hl < 4; hl++)
#pragma unroll
        for (int j = 0; j < 4; j++) aw[hl][j] = 0ull;
    float anf[4] = {0.f, 0.f, 0.f, 0.f};
    float m = -INFINITY, l = 0.0f;

    {
        const float* src = enc + row0 * DD;
#pragma unroll
        for (int i = 0; i < 5; i++) { int off = (tid + i * 256) * 4; cp_async16(&encS[0][off], src + off); }
        if (tid < TR * CNODE / 4) cp_async16(&nfS[0][tid * 4], nf + row0 * CNODE + tid * 4);
        CP_COMMIT;
    }

    for (int t = 0; t < NTILES; t++) {
        int buf = t & 1;
        if (t + 1 < NTILES) {
            const float* src = enc + (row0 + (size_t)(t + 1) * TR) * DD;
#pragma unroll
            for (int i = 0; i < 5; i++) { int off = (tid + i * 256) * 4; cp_async16(&encS[buf ^ 1][off], src + off); }
            if (tid < TR * CNODE / 4)
                cp_async16(&nfS[buf ^ 1][tid * 4], nf + (row0 + (size_t)(t + 1) * TR) * CNODE + tid * 4);
            CP_COMMIT;
            CP_WAIT1;
        } else {
            CP_WAIT0;
        }
        __syncthreads();

        float pk[RPW];
#pragma unroll
        for (int k = 0; k < RPW; k++) {
            int r = rl + 4 * k;
            const ulonglong2* e2 = (const ulonglong2*)(&encS[buf][r * DD + lane * 8]);
            ulonglong2 eA = e2[0], eB = e2[1];
            float nfv = (lane < CNODE) ? nfS[buf][r * CNODE + lane] : 0.0f;
            float sacc[4];
#pragma unroll
            for (int hl = 0; hl < 4; hl++) {
                u64 acc2 = mul2(eA.x, qp[hl][0]);
                acc2 = fma2(eA.y, qp[hl][1], acc2);
                acc2 = fma2(eB.x, qp[hl][2], acc2);
                acc2 = fma2(eB.y, qp[hl][3], acc2);
                sacc[hl] = hsum2(acc2) + nfv * qnr[hl];
            }
            float v01 = (lane & 1) ? sacc[1] : sacc[0];
            float o01 = (lane & 1) ? sacc[0] : sacc[1];
            v01 += __shfl_xor_sync(FULLM, o01, 1);
            float v23 = (lane & 1) ? sacc[3] : sacc[2];
            float o23 = (lane & 1) ? sacc[2] : sacc[3];
            v23 += __shfl_xor_sync(FULLM, o23, 1);
            float vv = (lane & 2) ? v23 : v01;
            float oo = (lane & 2) ? v01 : v23;
            vv += __shfl_xor_sync(FULLM, oo, 2);
            vv += __shfl_xor_sync(FULLM, vv, 4);
            vv += __shfl_xor_sync(FULLM, vv, 8);
            vv += __shfl_xor_sync(FULLM, vv, 16);
            pk[k] = vv;
        }

        float tmax = pk[0];
#pragma unroll
        for (int k = 1; k < RPW; k++) tmax = fmaxf(tmax, pk[k]);
        float mn = fmaxf(m, tmax);
        float c = __expf(m - mn);
        m = mn;
        l *= c;
        {
            float cc0 = __shfl_sync(FULLM, c, 0);
            float cc1 = __shfl_sync(FULLM, c, 1);
            float cc2 = __shfl_sync(FULLM, c, 2);
            float cc3 = __shfl_sync(FULLM, c, 3);
            u64 cp0 = pk2(cc0, cc0), cp1 = pk2(cc1, cc1);
            u64 cp2 = pk2(cc2, cc2), cp3 = pk2(cc3, cc3);
#pragma unroll
            for (int j = 0; j < 4; j++) {
                aw[0][j] = mul2(aw[0][j], cp0);
                aw[1][j] = mul2(aw[1][j], cp1);
                aw[2][j] = mul2(aw[2][j], cp2);
                aw[3][j] = mul2(aw[3][j], cp3);
            }
            anf[0] *= cc0; anf[1] *= cc1; anf[2] *= cc2; anf[3] *= cc3;
        }

#pragma unroll
        for (int k = 0; k < RPW; k++) {
            int r = rl + 4 * k;
            float wv = __expf(pk[k] - m);
            l += wv;
            float w0 = __shfl_sync(FULLM, wv, 0);
            float w1 = __shfl_sync(FULLM, wv, 1);
            float w2 = __shfl_sync(FULLM, wv, 2);
            float w3 = __shfl_sync(FULLM, wv, 3);
            const ulonglong2* e2 = (const ulonglong2*)(&encS[buf][r * DD + lane * 8]);
            ulonglong2 eA = e2[0], eB = e2[1];
            float nfv = (lane < CNODE) ? nfS[buf][r * CNODE + lane] : 0.0f;
            u64 wp0 = pk2(w0, w0), wp1 = pk2(w1, w1), wp2 = pk2(w2, w2), wp3 = pk2(w3, w3);
            aw[0][0] = fma2(eA.x, wp0, aw[0][0]); aw[0][1] = fma2(eA.y, wp0, aw[0][1]);
            aw[0][2] = fma2(eB.x, wp0, aw[0][2]); aw[0][3] = fma2(eB.y, wp0, aw[0][3]);
            aw[1][0] = fma2(eA.x, wp1, aw[1][0]); aw[1][1] = fma2(eA.y, wp1, aw[1][1]);
            aw[1][2] = fma2(eB.x, wp1, aw[1][2]); aw[1][3] = fma2(eB.y, wp1, aw[1][3]);
            aw[2][0] = fma2(eA.x, wp2, aw[2][0]); aw[2][1] = fma2(eA.y, wp2, aw[2][1]);
            aw[2][2] = fma2(eB.x, wp2, aw[2][2]); aw[2][3] = fma2(eB.y, wp2, aw[2][3]);
            aw[3][0] = fma2(eA.x, wp3, aw[3][0]); aw[3][1] = fma2(eA.y, wp3, aw[3][1]);
            aw[3][2] = fma2(eB.x, wp3, aw[3][2]); aw[3][3] = fma2(eB.y, wp3, aw[3][3]);
            anf[0] += w0 * nfv; anf[1] += w1 * nfv; anf[2] += w2 * nfv; anf[3] += w3 * nfv;
        }
        __syncthreads();
    }

    // ---- block combine -> split partials ----
    u64* cAW = (u64*)encS;
    if (lane < 4) { cM[w][lane] = m; cL[w][lane] = l; }
#pragma unroll
    for (int hl = 0; hl < 4; hl++) {
#pragma unroll
        for (int j = 0; j < 4; j++) cAW[(w * 4 + hl) * (DD / 2) + lane * 4 + j] = aw[hl][j];
    }
    if (lane < CNODE) {
#pragma unroll
        for (int hl = 0; hl < 4; hl++) cANF[w][hl][lane] = anf[hl];
    }
    __syncthreads();

    {
        int h = w, g2 = h >> 2, hl2 = h & 3;
        float M = -INFINITY;
#pragma unroll
        for (int rw = 0; rw < 4; rw++) M = fmaxf(M, cM[g2 * 4 + rw][hl2]);
        float es[4], L = 0.0f;
#pragma unroll
        for (int rw = 0; rw < 4; rw++) {
            es[rw] = __expf(cM[g2 * 4 + rw][hl2] - M);
            L += cL[g2 * 4 + rw][hl2] * es[rw];
        }
        int pidx = (b * SPLIT + s) * HH + h;
        u64* dst = (u64*)g_paw + (size_t)pidx * (DD / 2) + lane * 4;
        u64 ep[4];
#pragma unroll
        for (int rw = 0; rw < 4; rw++) ep[rw] = pk2(es[rw], es[rw]);
#pragma unroll
        for (int j = 0; j < 4; j++) {
            u64 acc = 0ull;
#pragma unroll
            for (int rw = 0; rw < 4; rw++)
                acc = fma2(cAW[((g2 * 4 + rw) * 4 + hl2) * (DD / 2) + lane * 4 + j], ep[rw], acc);
            dst[j] = acc;
        }
        if (lane == 0) { g_pm[pidx] = M; g_pl[pidx] = L; }
        if (lane < CNODE) {
            float acc = 0.0f;
#pragma unroll
            for (int rw = 0; rw < 4; rw++) acc += es[rw] * cANF[g2 * 4 + rw][hl2][lane];
            g_panf[pidx * CNODE + lane] = acc;
        }
    }
}

// ---------------- K4a: combine split partials (bandwidth-shaped) ----------------
// grid (BS, HH), block 256. thread = (split-group q = t>>6, float4-dim d4 = t&63)
__global__ __launch_bounds__(256) void k4a_combine() {
    __shared__ float esS[SPLIT];
    __shared__ __align__(16) float4 sred[4][64];
    int b = blockIdx.x, h = blockIdx.y, t = threadIdx.x;

    if (t < 32) {
        float pmv = (t < SPLIT) ? g_pm[(b * SPLIT + t) * HH + h] : -INFINITY;
        float plv = (t < SPLIT) ? g_pl[(b * SPLIT + t) * HH + h] : 0.0f;
        float M = pmv;
#pragma unroll
        for (int o = 16; o > 0; o >>= 1) M = fmaxf(M, __shfl_xor_sync(FULLM, M, o));
        float e = (t < SPLIT) ? __expf(pmv - M) : 0.0f;
        float Lp = plv * e;
#pragma unroll
        for (int o = 16; o > 0; o >>= 1) Lp += __shfl_xor_sync(FULLM, Lp, o);
        float invL = 1.0f / Lp;
        if (t < SPLIT) esS[t] = e * invL;
    }
    __syncthreads();

    int q = t >> 6, d4 = t & 63;
    float4 acc = make_float4(0.f, 0.f, 0.f, 0.f);
#pragma unroll
    for (int j = 0; j < 5; j++) {
        int s = q + 4 * j;          // covers 0..19
        float es = esS[s];
        float4 v = ((const float4*)(g_paw + (size_t)((b * SPLIT + s) * HH + h) * DD))[d4];
        acc.x += es * v.x; acc.y += es * v.y; acc.z += es * v.z; acc.w += es * v.w;
    }
    sred[q][d4] = acc;
    __syncthreads();

    if (t < 64) {
        float4 a = sred[0][t], b2 = sred[1][t], c = sred[2][t], d = sred[3][t];
        float4 r;
        r.x = a.x + b2.x + c.x + d.x;
        r.y = a.y + b2.y + c.y + d.y;
        r.z = a.z + b2.z + c.z + d.z;
        r.w = a.w + b2.w + c.w + d.w;
        ((float4*)(g_aw + (size_t)(b * HH + h) * DD))[t] = r;
    } else if (t >= 64 && t < 64 + CNODE) {
        int c = t - 64;
        float acc2 = 0.0f;
#pragma unroll
        for (int s = 0; s < SPLIT; s++)
            acc2 += esS[s] * g_panf[((b * SPLIT + s) * HH + h) * CNODE + c];
        g_anfc[(b * HH + h) * CNODE + c] = acc2;
    }
}

// ---------------- K4b: glimpse + g2/gn (warp-GEMV, coalesced) ----------------
// grid BS, block 256
__global__ __launch_bounds__(256) void k4b_glimpse(const float* __restrict__ Wv,
                                                   const float* __restrict__ Wout,
                                                   const float* __restrict__ Wk2,
                                                   const float* __restrict__ Wn) {
    __shared__ __align__(16) float hs[DD];
    __shared__ __align__(16) float gl[DD];
    int b = blockIdx.x, t = threadIdx.x;
    int w = t >> 5, lane = t & 31;

    // stage 1: hs[w*32+o] = aw[head w]·Wv_row(o) + anf·Wn_v_row(o)
    {
        float awr[8];
        const float4* ap = (const float4*)(g_aw + ((size_t)(b * HH + w)) * DD + lane * 8);
        float4 a0 = ap[0], a1 = ap[1];
        awr[0]=a0.x; awr[1]=a0.y; awr[2]=a0.z; awr[3]=a0.w;
        awr[4]=a1.x; awr[5]=a1.y; awr[6]=a1.z; awr[7]=a1.w;
        float anfr = (lane < CNODE) ? g_anfc[(b * HH + w) * CNODE + lane] : 0.0f;
#pragma unroll 4
        for (int o = 0; o < 32; o++) {
            int row = w * HDIM + o;
            const float4* wv4 = (const float4*)(Wv + (size_t)row * DD) + lane * 2;
            float4 v0 = wv4[0], v1 = wv4[1];
            float acc = awr[0]*v0.x + awr[1]*v0.y + awr[2]*v0.z + awr[3]*v0.w
                      + awr[4]*v1.x + awr[5]*v1.y + awr[6]*v1.z + awr[7]*v1.w;
            if (lane < CNODE) acc += anfr * Wn[(DD + row) * CNODE + lane];
#pragma unroll
            for (int o2 = 16; o2 > 0; o2 >>= 1) acc += __shfl_xor_sync(FULLM, acc, o2);
            if (lane == 0) hs[row] = acc;
        }
    }
    __syncthreads();

    // stage 2: gl = hs @ Wout^T
    {
        float hr[8];
        const float4* hp = (const float4*)hs + lane * 2;
        float4 h0 = hp[0], h1 = hp[1];
        hr[0]=h0.x; hr[1]=h0.y; hr[2]=h0.z; hr[3]=h0.w;
        hr[4]=h1.x; hr[5]=h1.y; hr[6]=h1.z; hr[7]=h1.w;
#pragma unroll 4
        for (int o = 0; o < 32; o++) {
            int row = w * 32 + o;
            const float4* wo4 = (const float4*)(Wout + (size_t)row * DD) + lane * 2;
            float4 v0 = wo4[0], v1 = wo4[1];
            float acc = hr[0]*v0.x + hr[1]*v0.y + hr[2]*v0.z + hr[3]*v0.w
                      + hr[4]*v1.x + hr[5]*v1.y + hr[6]*v1.z + hr[7]*v1.w;
#pragma unroll
            for (int o2 = 16; o2 > 0; o2 >>= 1) acc += __shfl_xor_sync(FULLM, acc, o2);
            if (lane == 0) gl[row] = acc;
        }
    }
    __syncthreads();

    // stage 3: g2[t] = gl · Wk2_col(t), gn small
    float a2 = 0.0f;
#pragma unroll 8
    for (int d = 0; d < DD; d++) a2 += gl[d] * Wk2[d * DD + t];
    g_g2[b * DD + t] = a2 * INV_SQRT_D;
    if (t < CNODE) {
        float a3 = 0.0f;
#pragma unroll 8
        for (int d = 0; d < DD; d++) a3 += gl[d] * Wn[(2 * DD + d) * CNODE + t];
        g_gn[b * CNODE + t] = a3 * INV_SQRT_D;
    }
}

// ---------------- K5a: split logits, 4 rows in flight per warp, packed dot ----------------
// grid (BS, SPLITL), block 256
__global__ __launch_bounds__(256) void k5a_logits(const float* __restrict__ enc,
                                                  const float* __restrict__ nf,
                                                  const void* __restrict__ maskp) {
    __shared__ __align__(16) float g2s[DD];
    __shared__ float gns[CNODE];
    __shared__ float tls[RSL];
    __shared__ float red[256];
    int b = blockIdx.x, s = blockIdx.y;
    int tid = threadIdx.x, wid = tid >> 5, lane = tid & 31;

    g2s[tid] = g_g2[b * DD + tid];
    if (tid < CNODE) gns[tid] = g_gn[b * CNODE + tid];
    int flags = g_flags;
    __syncthreads();

    const ulonglong2* cpa = (const ulonglong2*)(g2s + lane * 4);
    const ulonglong2* cpb = (const ulonglong2*)(g2s + 128 + lane * 4);
    ulonglong2 cA = cpa[0], cB = cpb[0];
    float gnl = (lane < CNODE) ? gns[lane] : 0.0f;

    int n0 = s * RSL;
    size_t rowb = (size_t)b * NN;
    for (int base = 0; base < 13; base += 4) {
        float pv[4] = {0.f, 0.f, 0.f, 0.f};
        bool val[4];
#pragma unroll
        for (int j = 0; j < 4; j++) {
            int i = base + j;
            int rr = wid + 8 * i;
            val[j] = (i < 13) && (rr < RSL);
            if (val[j]) {
                const ulonglong2* ea2 = (const ulonglong2*)(enc + (rowb + n0 + rr) * DD + lane * 4);
                const ulonglong2* eb2 = (const ulonglong2*)(enc + (rowb + n0 + rr) * DD + 128 + lane * 4);
                ulonglong2 ea = ea2[0], eb = eb2[0];
                u64 a2 = mul2(ea.x, cA.x); a2 = fma2(ea.y, cA.y, a2);
                a2 = fma2(eb.x, cB.x, a2); a2 = fma2(eb.y, cB.y, a2);
                pv[j] = hsum2(a2);
                if (lane < CNODE) pv[j] += nf[(rowb + n0 + rr) * CNODE + lane] * gnl;
            }
        }
#pragma unroll
        for (int o = 16; o > 0; o >>= 1) {
            pv[0] += __shfl_xor_sync(FULLM, pv[0], o);
            pv[1] += __shfl_xor_sync(FULLM, pv[1], o);
            pv[2] += __shfl_xor_sync(FULLM, pv[2], o);
            pv[3] += __shfl_xor_sync(FULLM, pv[3], o);
        }
        if (lane == 0) {
#pragma unroll
            for (int j = 0; j < 4; j++) {
                if (val[j]) {
                    int rr = wid + 8 * (base + j);
                    bool msk = read_mask(maskp, flags, rowb + n0 + rr);
                    float v = msk ? -INFINITY : TANH_CLIP * tanhf(pv[j]);
                    g_tl[rowb + n0 + rr] = v;
                    tls[rr] = v;
                }
            }
        }
    }
    __syncthreads();

    float mx = -INFINITY;
    for (int r = tid; r < RSL; r += 256) mx = fmaxf(mx, tls[r]);
    red[tid] = mx;
    __syncthreads();
    for (int st = 128; st > 0; st >>= 1) {
        if (tid < st) red[tid] = fmaxf(red[tid], red[tid + st]);
        __syncthreads();
    }
    mx = red[0];
    __syncthreads();

    float sm = 0.0f;
    if (mx > -INFINITY) {
        for (int r = tid; r < RSL; r += 256) sm += __expf(tls[r] - mx);
    }
    red[tid] = sm;
    __syncthreads();
    for (int st = 128; st > 0; st >>= 1) {
        if (tid < st) red[tid] += red[tid + st];
        __syncthreads();
    }
    if (tid == 0) {
        g_pmax[b * SPLITL + s] = mx;
        g_psum[b * SPLITL + s] = (mx > -INFINITY) ? red[0] : 0.0f;
    }
}

// ---------------- K5c: fused combine + normalize ----------------
// grid (BS, SPLITL), block 128
__global__ __launch_bounds__(128) void k5c_norm(float* __restrict__ out) {
    __shared__ float sM, sInv;
    int b = blockIdx.x, s = blockIdx.y, t = threadIdx.x;
    if (t < 32) {
        float mx = (t < SPLITL) ? g_pmax[b * SPLITL + t] : -INFINITY;
#pragma unroll
        for (int o = 16; o > 0; o >>= 1) mx = fmaxf(mx, __shfl_xor_sync(FULLM, mx, o));
        float sm = 0.0f;
        if (t < SPLITL) {
            float pm = g_pmax[b * SPLITL + t];
            sm = (pm > -INFINITY) ? g_psum[b * SPLITL + t] * __expf(pm - mx) : 0.0f;
        }
#pragma unroll
        for (int o = 16; o > 0; o >>= 1) sm += __shfl_xor_sync(FULLM, sm, o);
        if (t == 0) { sM = mx; sInv = 1.0f / sm; }
    }
    __syncthreads();
    float M = sM, inv = sInv;
    int n0 = s * RSL;
    for (int r = t; r < RSL; r += 128) {
        size_t i = (size_t)b * NN + n0 + r;
        out[i] = __expf(g_tl[i] - M) * inv;
    }
}

// ---------------- launch ----------------
extern "C" void kernel_launch(void* const* d_in, const int* in_sizes, int n_in,
                              void* d_out, int out_size) {
    const float* shelf = (const float*)d_in[0];
    const float* enc   = (const float*)d_in[1];
    const float* ctx   = (const float*)d_in[2];
    const float* nf    = (const float*)d_in[3];
    const float* Wk    = (const float*)d_in[4];
    const float* Wv    = (const float*)d_in[5];
    const float* Wk2   = (const float*)d_in[6];
    const float* Wq    = (const float*)d_in[7];
    const float* Wout  = (const float*)d_in[8];
    const float* Wc    = (const float*)d_in[9];
    const float* Wg    = (const float*)d_in[10];
    const float* Wn    = (const float*)d_in[11];
    const int*   cur   = (const int*)d_in[12];
    const void*  maskp = (const void*)d_in[13];
    float* out = (float*)d_out;

    { dim3 g(BS, SPLIT1); k1_sum<<<g, 256>>>(enc, maskp); }
    k2_setup<<<BS, 256>>>(shelf, ctx, Wk, Wq, Wc, Wg, Wn, cur);
    { dim3 g(BS, SPLIT);  k3_attn<<<g, 256>>>(enc, nf); }
    { dim3 g(BS, HH);     k4a_combine<<<g, 256>>>(); }
    k4b_glimpse<<<BS, 256>>>(Wv, Wout, Wk2, Wn);
    { dim3 g(BS, SPLITL); k5a_logits<<<g, 256>>>(enc, nf, maskp); }
    { dim3 g(BS, SPLITL); k5c_norm<<<g, 128>>>(out); }
}

// round 10
// speedup vs baseline: 3.2881x; 1.0191x over previous
#include <cuda_runtime.h>
#include <cuda_bf16.h>
#include <math.h>
#include <stdint.h>

// Problem constants
#define BS 128
#define NN 2000
#define DD 256
#define HH 8
#define HDIM 32
#define CCTX 64
#define CNODE 8
#define TANH_CLIP 10.0f

#define SPLIT 20          // n-splits for k3
#define RS (NN / SPLIT)   // 100 rows per k3 block
#define TR 20             // tile rows in k3
#define NTILES (RS / TR)  // 5
#define RPW (TR / 4)      // 5 rows per warp per tile

#define SPLIT1 25          // n-splits for k1
#define RPB1 (NN / SPLIT1) // 80

#define SPLITL 25         // n-splits for k5
#define RSL (NN / SPLITL) // 80 rows per k5a block (= 8 warps * 10 rows exactly)

#define INV_SQRT_HD 0.17677669529663687f   // 1/sqrt(32)
#define INV_SQRT_D  0.0625f                // 1/sqrt(256)

typedef unsigned long long u64;

// ---------------- scratch (16B aligned) ----------------
__device__ __align__(16) float g_sump[BS * SPLIT1 * DD];
__device__ __align__(16) float g_qk[BS * HH * DD];
__device__ __align__(16) float g_qn[BS * HH * CNODE];
__device__ __align__(16) float g_pm[BS * SPLIT * HH];
__device__ __align__(16) float g_pl[BS * SPLIT * HH];
__device__ __align__(16) float g_paw[BS * SPLIT * HH * DD];
__device__ __align__(16) float g_panf[BS * SPLIT * HH * CNODE];
__device__ __align__(16) float g_aw[BS * HH * DD];
__device__ __align__(16) float g_anfc[BS * HH * CNODE];
__device__ __align__(16) float g_g2[BS * DD];
__device__ __align__(16) float g_gn[BS * CNODE];
__device__ __align__(16) float g_tl[BS * NN];
__device__ __align__(16) float g_pmax[BS * SPLITL];
__device__ __align__(16) float g_psum[BS * SPLITL];
__device__ int g_flags;   // zero-initialized at load; atomicOr idempotent across replays

// ---------------- helpers ----------------
__device__ __forceinline__ void cp_async16(void* sdst, const void* gsrc) {
    unsigned s = (unsigned)__cvta_generic_to_shared(sdst);
    asm volatile("cp.async.cg.shared.global [%0], [%1], 16;\n" :: "r"(s), "l"(gsrc) : "memory");
}
#define CP_COMMIT asm volatile("cp.async.commit_group;\n" ::: "memory")
#define CP_WAIT1  asm volatile("cp.async.wait_group 1;\n" ::: "memory")
#define CP_WAIT0  asm volatile("cp.async.wait_group 0;\n" ::: "memory")
#define FULLM 0xffffffffu

// packed fp32x2 (Blackwell FFMA2 — PTX-only path)
__device__ __forceinline__ u64 fma2(u64 a, u64 b, u64 c) {
    u64 d; asm("fma.rn.f32x2 %0, %1, %2, %3;" : "=l"(d) : "l"(a), "l"(b), "l"(c)); return d;
}
__device__ __forceinline__ u64 mul2(u64 a, u64 b) {
    u64 d; asm("mul.rn.f32x2 %0, %1, %2;" : "=l"(d) : "l"(a), "l"(b)); return d;
}
__device__ __forceinline__ u64 pk2(float lo, float hi) {
    u64 r; asm("mov.b64 %0, {%1, %2};" : "=l"(r) : "f"(lo), "f"(hi)); return r;
}
__device__ __forceinline__ float hsum2(u64 v) {
    float lo, hi; asm("mov.b64 {%0, %1}, %2;" : "=f"(lo), "=f"(hi) : "l"(v)); return lo + hi;
}

__device__ __forceinline__ bool read_mask(const void* mp, int flags, size_t i) {
    if (flags == 0) return false;
    if (flags & 2) {
        if (flags & 1) return ((const unsigned char*)mp)[i] != 0;  // bool
        return ((const float*)mp)[i] != 0.0f;                      // float32
    }
    return ((const int*)mp)[i] != 0;                               // int32
}

// ---------------- K1: per-split partial sums of enc + mask scan ----------------
// grid (BS, SPLIT1), block 256
__global__ __launch_bounds__(256) void k1_sum(const float* __restrict__ enc,
                                              const void* __restrict__ maskp) {
    __shared__ __align__(16) float4 sred[256];
    int b = blockIdx.x, s = blockIdx.y;
    int tid = threadIdx.x;
    int c4 = tid & 63;
    int rg = tid >> 6;

    const float4* base = (const float4*)(enc + ((size_t)b * NN + (size_t)s * RPB1) * DD) + c4;
    float4 acc = make_float4(0.f, 0.f, 0.f, 0.f);
#pragma unroll 5
    for (int r = rg; r < RPB1; r += 4) {
        float4 v = base[(size_t)r * 64];
        acc.x += v.x; acc.y += v.y; acc.z += v.z; acc.w += v.w;
    }
    sred[tid] = acc;
    __syncthreads();
    if (tid < 64) {
        float4 a = sred[tid], b1 = sred[tid + 64], c = sred[tid + 128], d = sred[tid + 192];
        float* dst = &g_sump[(b * SPLIT1 + s) * DD + c4 * 4];
        dst[0] = a.x + b1.x + c.x + d.x;
        dst[1] = a.y + b1.y + c.y + d.y;
        dst[2] = a.z + b1.z + c.z + d.z;
        dst[3] = a.w + b1.w + c.w + d.w;
    }

    size_t idx = (size_t)(b * SPLIT1 + s) * 256 + tid;
    bool nz0 = false, nz1 = false;
    if (idx < (size_t)BS * NN) {
        unsigned char v = ((const unsigned char*)maskp)[idx];
        if (v) { if ((idx & 3) == 0) nz0 = true; else nz1 = true; }
    }
    unsigned b0 = __ballot_sync(FULLM, nz0);
    unsigned b1 = __ballot_sync(FULLM, nz1);
    if ((tid & 31) == 0) {
        int f = (b0 ? 1 : 0) | (b1 ? 2 : 0);
        if (f) atomicOr(&g_flags, f);
    }
}

// ---------------- K2: per-batch setup (coalesced warp-GEMV) ----------------
// grid BS, block 256
__global__ __launch_bounds__(256) void k2_setup(const float* __restrict__ shelf,
                                                const float* __restrict__ ctx,
                                                const float* __restrict__ Wk,
                                                const float* __restrict__ Wq,
                                                const float* __restrict__ Wc,
                                                const float* __restrict__ Wg,
                                                const float* __restrict__ Wn,
                                                const int* __restrict__ cur_node) {
    __shared__ __align__(16) float Xs[2 * DD];
    __shared__ __align__(16) float Qs[DD];
    __shared__ __align__(16) float ms[DD];
    int b = blockIdx.x, t = threadIdx.x;
    int w = t >> 5, lane = t & 31;

    int cn = cur_node[b];
    Xs[t] = shelf[((size_t)b * NN + cn) * DD + t];
    float a = 0.0f;
#pragma unroll 8
    for (int c = 0; c < CCTX; c++) a += ctx[b * CCTX + c] * Wc[t * CCTX + c];
    Xs[DD + t] = a;
    float smv = 0.0f;
#pragma unroll
    for (int s = 0; s < SPLIT1; s++) smv += g_sump[(b * SPLIT1 + s) * DD + t];
    ms[t] = smv * (1.0f / NN);
    __syncthreads();

    {
        float msr[8];
        const float4* msp = (const float4*)ms + lane * 2;
        { float4 v0 = msp[0], v1 = msp[1];
          msr[0]=v0.x; msr[1]=v0.y; msr[2]=v0.z; msr[3]=v0.w;
          msr[4]=v1.x; msr[5]=v1.y; msr[6]=v1.z; msr[7]=v1.w; }
        float xr[16];
        const float4* xp = (const float4*)Xs + lane * 4;
#pragma unroll
        for (int j = 0; j < 4; j++) {
            float4 v = xp[j];
            xr[j*4+0]=v.x; xr[j*4+1]=v.y; xr[j*4+2]=v.z; xr[j*4+3]=v.w;
        }
#pragma unroll 4
        for (int o = 0; o < 32; o++) {
            int tt = w * 32 + o;
            const float4* wg4 = (const float4*)(Wg + (size_t)tt * DD) + lane * 2;
            const float4* wq4 = (const float4*)(Wq + (size_t)tt * 2 * DD) + lane * 4;
            float acc = 0.0f;
            float4 g0 = wg4[0], g1 = wg4[1];
            acc += msr[0]*g0.x + msr[1]*g0.y + msr[2]*g0.z + msr[3]*g0.w;
            acc += msr[4]*g1.x + msr[5]*g1.y + msr[6]*g1.z + msr[7]*g1.w;
#pragma unroll
            for (int j = 0; j < 4; j++) {
                float4 q4 = wq4[j];
                acc += xr[j*4+0]*q4.x + xr[j*4+1]*q4.y + xr[j*4+2]*q4.z + xr[j*4+3]*q4.w;
            }
#pragma unroll
            for (int o2 = 16; o2 > 0; o2 >>= 1) acc += __shfl_xor_sync(FULLM, acc, o2);
            if (lane == 0) Qs[tt] = acc;
        }
    }
    __syncthreads();

#pragma unroll
    for (int h = 0; h < HH; h++) {
        float a2 = 0.0f;
#pragma unroll 8
        for (int e = 0; e < HDIM; e++) a2 += Qs[h * HDIM + e] * Wk[(h * HDIM + e) * DD + t];
        g_qk[(b * HH + h) * DD + t] = a2 * INV_SQRT_HD;
    }
    if (t < HH * CNODE) {
        int h = t >> 3, c = t & 7;
        float a3 = 0.0f;
#pragma unroll 8
        for (int e = 0; e < HDIM; e++) a3 += Qs[h * HDIM + e] * Wn[(h * HDIM + e) * CNODE + c];
        g_qn[(b * HH + h) * CNODE + c] = a3 * INV_SQRT_HD;
    }
}

// ---------------- K3: split flash glimpse, deferred per-tile rescale ----------------
// grid (BS, SPLIT), block 256
// m starts at 0 (exact: m is only an offset; compat ~ N(0,1) so exp(p-m) cannot overflow).
// Each row is accumulated immediately with the stale m; ONE uniform correction per tile
// (applied to l/aw/anf) retroactively fixes everything, including this tile's rows.
__global__ __launch_bounds__(256, 2) void k3_attn(const float* __restrict__ enc,
                                                  const float* __restrict__ nf) {
    __shared__ __align__(16) float encS[2][TR * DD];   // 40 KB, aliased for combine
    __shared__ __align__(16) float nfS[2][TR * CNODE];
    __shared__ float cM[8][4], cL[8][4];
    __shared__ float cANF[8][4][CNODE];

    int b = blockIdx.x, s = blockIdx.y;
    int tid = threadIdx.x, w = tid >> 5, lane = tid & 31;
    int g = w >> 2, rl = w & 3;
    size_t row0 = (size_t)b * NN + (size_t)s * RS;

    u64 qp[4][4];
#pragma unroll
    for (int hl = 0; hl < 4; hl++) {
        const ulonglong2* qq = (const ulonglong2*)(g_qk + ((size_t)(b * HH + g * 4 + hl)) * DD + lane * 8);
        ulonglong2 qa = qq[0], qb = qq[1];
        qp[hl][0] = qa.x; qp[hl][1] = qa.y; qp[hl][2] = qb.x; qp[hl][3] = qb.y;
    }
    float qnr[4];
#pragma unroll
    for (int hl = 0; hl < 4; hl++)
        qnr[hl] = (lane < CNODE) ? g_qn[(b * HH + g * 4 + hl) * CNODE + lane] : 0.0f;

    u64 aw[4][4];
#pragma unroll
    for (int hl = 0; hl < 4; hl++)
#pragma unroll
        for (int j = 0; j < 4; j++) aw[hl][j] = 0ull;
    float anf[4] = {0.f, 0.f, 0.f, 0.f};
    float m = 0.0f, l = 0.0f;   // offset starts at 0 (no -inf handling needed)

    {
        const float* src = enc + row0 * DD;
#pragma unroll
        for (int i = 0; i < 5; i++) { int off = (tid + i * 256) * 4; cp_async16(&encS[0][off], src + off); }
        if (tid < TR * CNODE / 4) cp_async16(&nfS[0][tid * 4], nf + row0 * CNODE + tid * 4);
        CP_COMMIT;
    }

    for (int t = 0; t < NTILES; t++) {
        int buf = t & 1;
        if (t + 1 < NTILES) {
            const float* src = enc + (row0 + (size_t)(t + 1) * TR) * DD;
#pragma unroll
            for (int i = 0; i < 5; i++) { int off = (tid + i * 256) * 4; cp_async16(&encS[buf ^ 1][off], src + off); }
            if (tid < TR * CNODE / 4)
                cp_async16(&nfS[buf ^ 1][tid * 4], nf + (row0 + (size_t)(t + 1) * TR) * CNODE + tid * 4);
            CP_COMMIT;
            CP_WAIT1;
        } else {
            CP_WAIT0;
        }
        __syncthreads();

        float tmax = -INFINITY;
#pragma unroll
        for (int k = 0; k < RPW; k++) {
            int r = rl + 4 * k;
            const ulonglong2* e2 = (const ulonglong2*)(&encS[buf][r * DD + lane * 8]);
            ulonglong2 eA = e2[0], eB = e2[1];
            float nfv = (lane < CNODE) ? nfS[buf][r * CNODE + lane] : 0.0f;

            float sacc[4];
#pragma unroll
            for (int hl = 0; hl < 4; hl++) {
                u64 acc2 = mul2(eA.x, qp[hl][0]);
                acc2 = fma2(eA.y, qp[hl][1], acc2);
                acc2 = fma2(eB.x, qp[hl][2], acc2);
                acc2 = fma2(eB.y, qp[hl][3], acc2);
                sacc[hl] = hsum2(acc2) + nfv * qnr[hl];
            }
            float v01 = (lane & 1) ? sacc[1] : sacc[0];
            float o01 = (lane & 1) ? sacc[0] : sacc[1];
            v01 += __shfl_xor_sync(FULLM, o01, 1);
            float v23 = (lane & 1) ? sacc[3] : sacc[2];
            float o23 = (lane & 1) ? sacc[2] : sacc[3];
            v23 += __shfl_xor_sync(FULLM, o23, 1);
            float vv = (lane & 2) ? v23 : v01;
            float oo = (lane & 2) ? v01 : v23;
            vv += __shfl_xor_sync(FULLM, oo, 2);
            vv += __shfl_xor_sync(FULLM, vv, 4);
            vv += __shfl_xor_sync(FULLM, vv, 8);
            vv += __shfl_xor_sync(FULLM, vv, 16);
            float p = vv;           // p for head (lane&3), row r

            tmax = fmaxf(tmax, p);
            float wv = __expf(p - m);   // stale m: corrected at tile end
            l += wv;
            float w0 = __shfl_sync(FULLM, wv, 0);
            float w1 = __shfl_sync(FULLM, wv, 1);
            float w2 = __shfl_sync(FULLM, wv, 2);
            float w3 = __shfl_sync(FULLM, wv, 3);
            u64 wp0 = pk2(w0, w0), wp1 = pk2(w1, w1), wp2 = pk2(w2, w2), wp3 = pk2(w3, w3);
            aw[0][0] = fma2(eA.x, wp0, aw[0][0]); aw[0][1] = fma2(eA.y, wp0, aw[0][1]);
            aw[0][2] = fma2(eB.x, wp0, aw[0][2]); aw[0][3] = fma2(eB.y, wp0, aw[0][3]);
            aw[1][0] = fma2(eA.x, wp1, aw[1][0]); aw[1][1] = fma2(eA.y, wp1, aw[1][1]);
            aw[1][2] = fma2(eB.x, wp1, aw[1][2]); aw[1][3] = fma2(eB.y, wp1, aw[1][3]);
            aw[2][0] = fma2(eA.x, wp2, aw[2][0]); aw[2][1] = fma2(eA.y, wp2, aw[2][1]);
            aw[2][2] = fma2(eB.x, wp2, aw[2][2]); aw[2][3] = fma2(eB.y, wp2, aw[2][3]);
            aw[3][0] = fma2(eA.x, wp3, aw[3][0]); aw[3][1] = fma2(eA.y, wp3, aw[3][1]);
            aw[3][2] = fma2(eB.x, wp3, aw[3][2]); aw[3][3] = fma2(eB.y, wp3, aw[3][3]);
            anf[0] += w0 * nfv; anf[1] += w1 * nfv; anf[2] += w2 * nfv; anf[3] += w3 * nfv;
        }

        // ---- tile-end uniform correction ----
        {
            float mn = fmaxf(m, tmax);
            float c = __expf(m - mn);    // <= 1
            m = mn;
            l *= c;
            float cc0 = __shfl_sync(FULLM, c, 0);
            float cc1 = __shfl_sync(FULLM, c, 1);
            float cc2 = __shfl_sync(FULLM, c, 2);
            float cc3 = __shfl_sync(FULLM, c, 3);
            u64 cp0 = pk2(cc0, cc0), cp1 = pk2(cc1, cc1);
            u64 cp2 = pk2(cc2, cc2), cp3 = pk2(cc3, cc3);
#pragma unroll
            for (int j = 0; j < 4; j++) {
                aw[0][j] = mul2(aw[0][j], cp0);
                aw[1][j] = mul2(aw[1][j], cp1);
                aw[2][j] = mul2(aw[2][j], cp2);
                aw[3][j] = mul2(aw[3][j], cp3);
            }
            anf[0] *= cc0; anf[1] *= cc1; anf[2] *= cc2; anf[3] *= cc3;
        }
        __syncthreads();
    }

    // ---- block combine -> split partials ----
    u64* cAW = (u64*)encS;
    if (lane < 4) { cM[w][lane] = m; cL[w][lane] = l; }
#pragma unroll
    for (int hl = 0; hl < 4; hl++) {
#pragma unroll
        for (int j = 0; j < 4; j++) cAW[(w * 4 + hl) * (DD / 2) + lane * 4 + j] = aw[hl][j];
    }
    if (lane < CNODE) {
#pragma unroll
        for (int hl = 0; hl < 4; hl++) cANF[w][hl][lane] = anf[hl];
    }
    __syncthreads();

    {
        int h = w, g2 = h >> 2, hl2 = h & 3;
        float M = -INFINITY;
#pragma unroll
        for (int rw = 0; rw < 4; rw++) M = fmaxf(M, cM[g2 * 4 + rw][hl2]);
        float es[4], L = 0.0f;
#pragma unroll
        for (int rw = 0; rw < 4; rw++) {
            es[rw] = __expf(cM[g2 * 4 + rw][hl2] - M);
            L += cL[g2 * 4 + rw][hl2] * es[rw];
        }
        int pidx = (b * SPLIT + s) * HH + h;
        u64* dst = (u64*)g_paw + (size_t)pidx * (DD / 2) + lane * 4;
        u64 ep[4];
#pragma unroll
        for (int rw = 0; rw < 4; rw++) ep[rw] = pk2(es[rw], es[rw]);
#pragma unroll
        for (int j = 0; j < 4; j++) {
            u64 acc = 0ull;
#pragma unroll
            for (int rw = 0; rw < 4; rw++)
                acc = fma2(cAW[((g2 * 4 + rw) * 4 + hl2) * (DD / 2) + lane * 4 + j], ep[rw], acc);
            dst[j] = acc;
        }
        if (lane == 0) { g_pm[pidx] = M; g_pl[pidx] = L; }
        if (lane < CNODE) {
            float acc = 0.0f;
#pragma unroll
            for (int rw = 0; rw < 4; rw++) acc += es[rw] * cANF[g2 * 4 + rw][hl2][lane];
            g_panf[pidx * CNODE + lane] = acc;
        }
    }
}

// ---------------- K4a: combine split partials (bandwidth-shaped) ----------------
// grid (BS, HH), block 256
__global__ __launch_bounds__(256) void k4a_combine() {
    __shared__ float esS[SPLIT];
    __shared__ __align__(16) float4 sred[4][64];
    int b = blockIdx.x, h = blockIdx.y, t = threadIdx.x;

    if (t < 32) {
        float pmv = (t < SPLIT) ? g_pm[(b * SPLIT + t) * HH + h] : -INFINITY;
        float plv = (t < SPLIT) ? g_pl[(b * SPLIT + t) * HH + h] : 0.0f;
        float M = pmv;
#pragma unroll
        for (int o = 16; o > 0; o >>= 1) M = fmaxf(M, __shfl_xor_sync(FULLM, M, o));
        float e = (t < SPLIT) ? __expf(pmv - M) : 0.0f;
        float Lp = plv * e;
#pragma unroll
        for (int o = 16; o > 0; o >>= 1) Lp += __shfl_xor_sync(FULLM, Lp, o);
        float invL = 1.0f / Lp;
        if (t < SPLIT) esS[t] = e * invL;
    }
    __syncthreads();

    int q = t >> 6, d4 = t & 63;
    float4 acc = make_float4(0.f, 0.f, 0.f, 0.f);
#pragma unroll
    for (int j = 0; j < 5; j++) {
        int s = q + 4 * j;
        float es = esS[s];
        float4 v = ((const float4*)(g_paw + (size_t)((b * SPLIT + s) * HH + h) * DD))[d4];
        acc.x += es * v.x; acc.y += es * v.y; acc.z += es * v.z; acc.w += es * v.w;
    }
    sred[q][d4] = acc;
    __syncthreads();

    if (t < 64) {
        float4 a = sred[0][t], b2 = sred[1][t], c = sred[2][t], d = sred[3][t];
        float4 r;
        r.x = a.x + b2.x + c.x + d.x;
        r.y = a.y + b2.y + c.y + d.y;
        r.z = a.z + b2.z + c.z + d.z;
        r.w = a.w + b2.w + c.w + d.w;
        ((float4*)(g_aw + (size_t)(b * HH + h) * DD))[t] = r;
    } else if (t >= 64 && t < 64 + CNODE) {
        int c = t - 64;
        float acc2 = 0.0f;
#pragma unroll
        for (int s = 0; s < SPLIT; s++)
            acc2 += esS[s] * g_panf[((b * SPLIT + s) * HH + h) * CNODE + c];
        g_anfc[(b * HH + h) * CNODE + c] = acc2;
    }
}

// ---------------- K4b: glimpse + g2/gn (warp-GEMV, coalesced) ----------------
// grid BS, block 256
__global__ __launch_bounds__(256) void k4b_glimpse(const float* __restrict__ Wv,
                                                   const float* __restrict__ Wout,
                                                   const float* __restrict__ Wk2,
                                                   const float* __restrict__ Wn) {
    __shared__ __align__(16) float hs[DD];
    __shared__ __align__(16) float gl[DD];
    int b = blockIdx.x, t = threadIdx.x;
    int w = t >> 5, lane = t & 31;

    {
        float awr[8];
        const float4* ap = (const float4*)(g_aw + ((size_t)(b * HH + w)) * DD + lane * 8);
        float4 a0 = ap[0], a1 = ap[1];
        awr[0]=a0.x; awr[1]=a0.y; awr[2]=a0.z; awr[3]=a0.w;
        awr[4]=a1.x; awr[5]=a1.y; awr[6]=a1.z; awr[7]=a1.w;
        float anfr = (lane < CNODE) ? g_anfc[(b * HH + w) * CNODE + lane] : 0.0f;
#pragma unroll 4
        for (int o = 0; o < 32; o++) {
            int row = w * HDIM + o;
            const float4* wv4 = (const float4*)(Wv + (size_t)row * DD) + lane * 2;
            float4 v0 = wv4[0], v1 = wv4[1];
            float acc = awr[0]*v0.x + awr[1]*v0.y + awr[2]*v0.z + awr[3]*v0.w
                      + awr[4]*v1.x + awr[5]*v1.y + awr[6]*v1.z + awr[7]*v1.w;
            if (lane < CNODE) acc += anfr * Wn[(DD + row) * CNODE + lane];
#pragma unroll
            for (int o2 = 16; o2 > 0; o2 >>= 1) acc += __shfl_xor_sync(FULLM, acc, o2);
            if (lane == 0) hs[row] = acc;
        }
    }
    __syncthreads();

    {
        float hr[8];
        const float4* hp = (const float4*)hs + lane * 2;
        float4 h0 = hp[0], h1 = hp[1];
        hr[0]=h0.x; hr[1]=h0.y; hr[2]=h0.z; hr[3]=h0.w;
        hr[4]=h1.x; hr[5]=h1.y; hr[6]=h1.z; hr[7]=h1.w;
#pragma unroll 4
        for (int o = 0; o < 32; o++) {
            int row = w * 32 + o;
            const float4* wo4 = (const float4*)(Wout + (size_t)row * DD) + lane * 2;
            float4 v0 = wo4[0], v1 = wo4[1];
            float acc = hr[0]*v0.x + hr[1]*v0.y + hr[2]*v0.z + hr[3]*v0.w
                      + hr[4]*v1.x + hr[5]*v1.y + hr[6]*v1.z + hr[7]*v1.w;
#pragma unroll
            for (int o2 = 16; o2 > 0; o2 >>= 1) acc += __shfl_xor_sync(FULLM, acc, o2);
            if (lane == 0) gl[row] = acc;
        }
    }
    __syncthreads();

    float a2 = 0.0f;
#pragma unroll 8
    for (int d = 0; d < DD; d++) a2 += gl[d] * Wk2[d * DD + t];
    g_g2[b * DD + t] = a2 * INV_SQRT_D;
    if (t < CNODE) {
        float a3 = 0.0f;
#pragma unroll 8
        for (int d = 0; d < DD; d++) a3 += gl[d] * Wn[(2 * DD + d) * CNODE + t];
        g_gn[b * CNODE + t] = a3 * INV_SQRT_D;
    }
}

// ---------------- K5a: split logits, 5 rows in flight per warp, packed dot ----------------
// grid (BS, SPLITL), block 256; RSL=80 = 8 warps * 10 rows exactly
__global__ __launch_bounds__(256) void k5a_logits(const float* __restrict__ enc,
                                                  const float* __restrict__ nf,
                                                  const void* __restrict__ maskp) {
    __shared__ __align__(16) float g2s[DD];
    __shared__ float gns[CNODE];
    __shared__ float tls[RSL];
    __shared__ float red[256];
    int b = blockIdx.x, s = blockIdx.y;
    int tid = threadIdx.x, wid = tid >> 5, lane = tid & 31;

    g2s[tid] = g_g2[b * DD + tid];
    if (tid < CNODE) gns[tid] = g_gn[b * CNODE + tid];
    int flags = g_flags;
    __syncthreads();

    const ulonglong2* cpa = (const ulonglong2*)(g2s + lane * 4);
    const ulonglong2* cpb = (const ulonglong2*)(g2s + 128 + lane * 4);
    ulonglong2 cA = cpa[0], cB = cpb[0];
    float gnl = (lane < CNODE) ? gns[lane] : 0.0f;

    int n0 = s * RSL;
    size_t rowb = (size_t)b * NN;
    // rows rr = wid + 8*i, i = 0..9 (all valid); 5 in flight
#pragma unroll
    for (int base = 0; base < 10; base += 5) {
        float pv[5];
#pragma unroll
        for (int j = 0; j < 5; j++) {
            int rr = wid + 8 * (base + j);
            const ulonglong2* ea2 = (const ulonglong2*)(enc + (rowb + n0 + rr) * DD + lane * 4);
            const ulonglong2* eb2 = (const ulonglong2*)(enc + (rowb + n0 + rr) * DD + 128 + lane * 4);
            ulonglong2 ea = ea2[0], eb = eb2[0];
            u64 a2 = mul2(ea.x, cA.x); a2 = fma2(ea.y, cA.y, a2);
            a2 = fma2(eb.x, cB.x, a2); a2 = fma2(eb.y, cB.y, a2);
            pv[j] = hsum2(a2);
            if (lane < CNODE) pv[j] += nf[(rowb + n0 + rr) * CNODE + lane] * gnl;
        }
#pragma unroll
        for (int o = 16; o > 0; o >>= 1) {
#pragma unroll
            for (int j = 0; j < 5; j++) pv[j] += __shfl_xor_sync(FULLM, pv[j], o);
        }
        if (lane == 0) {
#pragma unroll
            for (int j = 0; j < 5; j++) {
                int rr = wid + 8 * (base + j);
                bool msk = read_mask(maskp, flags, rowb + n0 + rr);
                float v = msk ? -INFINITY : TANH_CLIP * tanhf(pv[j]);
                g_tl[rowb + n0 + rr] = v;
                tls[rr] = v;
            }
        }
    }
    __syncthreads();

    float mx = -INFINITY;
    for (int r = tid; r < RSL; r += 256) mx = fmaxf(mx, tls[r]);
    red[tid] = mx;
    __syncthreads();
    for (int st = 128; st > 0; st >>= 1) {
        if (tid < st) red[tid] = fmaxf(red[tid], red[tid + st]);
        __syncthreads();
    }
    mx = red[0];
    __syncthreads();

    float sm = 0.0f;
    if (mx > -INFINITY) {
        for (int r = tid; r < RSL; r += 256) sm += __expf(tls[r] - mx);
    }
    red[tid] = sm;
    __syncthreads();
    for (int st = 128; st > 0; st >>= 1) {
        if (tid < st) red[tid] += red[tid + st];
        __syncthreads();
    }
    if (tid == 0) {
        g_pmax[b * SPLITL + s] = mx;
        g_psum[b * SPLITL + s] = (mx > -INFINITY) ? red[0] : 0.0f;
    }
}

// ---------------- K5c: fused combine + normalize ----------------
// grid (BS, SPLITL), block 128
__global__ __launch_bounds__(128) void k5c_norm(float* __restrict__ out) {
    __shared__ float sM, sInv;
    int b = blockIdx.x, s = blockIdx.y, t = threadIdx.x;
    if (t < 32) {
        float mx = (t < SPLITL) ? g_pmax[b * SPLITL + t] : -INFINITY;
#pragma unroll
        for (int o = 16; o > 0; o >>= 1) mx = fmaxf(mx, __shfl_xor_sync(FULLM, mx, o));
        float sm = 0.0f;
        if (t < SPLITL) {
            float pm = g_pmax[b * SPLITL + t];
            sm = (pm > -INFINITY) ? g_psum[b * SPLITL + t] * __expf(pm - mx) : 0.0f;
        }
#pragma unroll
        for (int o = 16; o > 0; o >>= 1) sm += __shfl_xor_sync(FULLM, sm, o);
        if (t == 0) { sM = mx; sInv = 1.0f / sm; }
    }
    __syncthreads();
    float M = sM, inv = sInv;
    int n0 = s * RSL;
    for (int r = t; r < RSL; r += 128) {
        size_t i = (size_t)b * NN + n0 + r;
        out[i] = __expf(g_tl[i] - M) * inv;
    }
}

// ---------------- launch ----------------
extern "C" void kernel_launch(void* const* d_in, const int* in_sizes, int n_in,
                              void* d_out, int out_size) {
    const float* shelf = (const float*)d_in[0];
    const float* enc   = (const float*)d_in[1];
    const float* ctx   = (const float*)d_in[2];
    const float* nf    = (const float*)d_in[3];
    const float* Wk    = (const float*)d_in[4];
    const float* Wv    = (const float*)d_in[5];
    const float* Wk2   = (const float*)d_in[6];
    const float* Wq    = (const float*)d_in[7];
    const float* Wout  = (const float*)d_in[8];
    const float* Wc    = (const float*)d_in[9];
    const float* Wg    = (const float*)d_in[10];
    const float* Wn    = (const float*)d_in[11];
    const int*   cur   = (const int*)d_in[12];
    const void*  maskp = (const void*)d_in[13];
    float* out = (float*)d_out;

    { dim3 g(BS, SPLIT1); k1_sum<<<g, 256>>>(enc, maskp); }
    k2_setup<<<BS, 256>>>(shelf, ctx, Wk, Wq, Wc, Wg, Wn, cur);
    { dim3 g(BS, SPLIT);  k3_attn<<<g, 256>>>(enc, nf); }
    { dim3 g(BS, HH);     k4a_combine<<<g, 256>>>(); }
    k4b_glimpse<<<BS, 256>>>(Wv, Wout, Wk2, Wn);
    { dim3 g(BS, SPLITL); k5a_logits<<<g, 256>>>(enc, nf, maskp); }
    { dim3 g(BS, SPLITL); k5c_norm<<<g, 128>>>(out); }
}